// round 3
// baseline (speedup 1.0000x reference)
#include <cuda_runtime.h>
#include <cuda_bf16.h>

#define NNODES 100000
#define EMAX   1600000
#define DIM    128

// Scratch (__device__ globals: allocation-free rule)
__device__ float g_h[(size_t)NNODES * DIM];    // GEMM output per layer
__device__ float g_agg[(size_t)NNODES * DIM];  // aggregation output / next input
__device__ float g_dinv[NNODES];               // rsqrt(deg)
__device__ int   g_deg[NNODES];                // in-degree (excl self-loop)
__device__ int   g_cnt[NNODES];                // fill counters
__device__ int   g_rowptr[NNODES + 1];         // CSR row pointers (by dst)
__device__ int   g_bsum[256];                  // scan block sums
__device__ int   g_csr_src[EMAX];              // CSR src node per edge
__device__ float g_csr_coef[EMAX];             // per-edge norm coefficient

// ---------------- CSR build ----------------
__global__ void zero2_kernel(int* __restrict__ a, int* __restrict__ b, int n) {
    int i = blockIdx.x * blockDim.x + threadIdx.x;
    if (i < n) { a[i] = 0; b[i] = 0; }
}

__global__ void deg_acc_kernel(const int* __restrict__ dst, int* __restrict__ deg, int E) {
    int e = blockIdx.x * blockDim.x + threadIdx.x;
    if (e < E) atomicAdd(&deg[dst[e]], 1);
}

__global__ void dinv_kernel(const int* __restrict__ deg, float* __restrict__ dinv, int n) {
    int i = blockIdx.x * blockDim.x + threadIdx.x;
    if (i < n) dinv[i] = rsqrtf((float)(deg[i] + 1));  // +1 self-loop
}

// exclusive scan, chunk = 1024 elems / block of 256 threads (4 elems each)
__global__ void scan1_kernel(const int* __restrict__ in, int* __restrict__ out,
                             int* __restrict__ bsum, int n) {
    __shared__ int sh[256];
    int t  = threadIdx.x;
    int i0 = blockIdx.x * 1024 + t * 4;
    int v[4];
#pragma unroll
    for (int k = 0; k < 4; k++) v[k] = (i0 + k < n) ? in[i0 + k] : 0;
    int s = v[0] + v[1] + v[2] + v[3];
    sh[t] = s;
    __syncthreads();
#pragma unroll
    for (int off = 1; off < 256; off <<= 1) {
        int x = (t >= off) ? sh[t - off] : 0;
        __syncthreads();
        sh[t] += x;
        __syncthreads();
    }
    int excl = sh[t] - s;  // exclusive prefix of this thread within chunk
    int run = excl;
#pragma unroll
    for (int k = 0; k < 4; k++) {
        if (i0 + k < n) out[i0 + k] = run;
        run += v[k];
    }
    if (t == 255) bsum[blockIdx.x] = sh[255];
}

__global__ void scan2_kernel(int* __restrict__ bsum, int nch, int* __restrict__ rowptr,
                             int n, int E) {
    if (blockIdx.x == 0 && threadIdx.x == 0) {
        int run = 0;
        for (int i = 0; i < nch; i++) { int t = bsum[i]; bsum[i] = run; run += t; }
        rowptr[n] = E;
    }
}

__global__ void scan3_kernel(int* __restrict__ rowptr, const int* __restrict__ bsum, int n) {
    int i = blockIdx.x * blockDim.x + threadIdx.x;
    if (i < n) rowptr[i] += bsum[i >> 10];
}

__global__ void fill_kernel(const int* __restrict__ src, const int* __restrict__ dst,
                            const int* __restrict__ rowptr, int* __restrict__ cnt,
                            const float* __restrict__ dinv,
                            int* __restrict__ csr_src, float* __restrict__ csr_coef, int E) {
    int e = blockIdx.x * blockDim.x + threadIdx.x;
    if (e >= E) return;
    int s = src[e], d = dst[e];
    int pos = rowptr[d] + atomicAdd(&cnt[d], 1);
    csr_src[pos]  = s;
    csr_coef[pos] = dinv[s] * dinv[d];
}

// ---------------- SGEMM: C[M,128] = A[M,128] @ B[128,128] ----------------
__global__ __launch_bounds__(256, 2)
void sgemm_128(const float* __restrict__ A, const float* __restrict__ B,
               float* __restrict__ C, int M) {
    __shared__ float As[8][128];
    __shared__ float Bs[8][128];

    const int tid  = threadIdx.x;
    const int row0 = blockIdx.x * 128;

    const int a_row = tid >> 1;
    const int a_col = (tid & 1) * 4;
    const int b_row = tid >> 5;
    const int b_col = (tid & 31) * 4;
    const int ty = tid >> 4;
    const int tx = tid & 15;

    float acc[8][8];
#pragma unroll
    for (int i = 0; i < 8; i++)
#pragma unroll
        for (int j = 0; j < 8; j++) acc[i][j] = 0.0f;

    const int  ga_row = row0 + a_row;
    const bool a_ok   = ga_row < M;

    for (int k0 = 0; k0 < 128; k0 += 8) {
        float4 av = a_ok ? *(const float4*)(A + (size_t)ga_row * DIM + k0 + a_col)
                         : make_float4(0.f, 0.f, 0.f, 0.f);
        As[a_col + 0][a_row] = av.x;
        As[a_col + 1][a_row] = av.y;
        As[a_col + 2][a_row] = av.z;
        As[a_col + 3][a_row] = av.w;

        *(float4*)(&Bs[b_row][b_col]) =
            *(const float4*)(B + (size_t)(k0 + b_row) * DIM + b_col);

        __syncthreads();

#pragma unroll
        for (int k = 0; k < 8; k++) {
            float a[8], b[8];
            *(float4*)(a)     = *(const float4*)(&As[k][ty * 8]);
            *(float4*)(a + 4) = *(const float4*)(&As[k][ty * 8 + 4]);
            *(float4*)(b)     = *(const float4*)(&Bs[k][tx * 8]);
            *(float4*)(b + 4) = *(const float4*)(&Bs[k][tx * 8 + 4]);
#pragma unroll
            for (int i = 0; i < 8; i++)
#pragma unroll
                for (int j = 0; j < 8; j++)
                    acc[i][j] += a[i] * b[j];
        }
        __syncthreads();
    }

#pragma unroll
    for (int i = 0; i < 8; i++) {
        int r = row0 + ty * 8 + i;
        if (r < M) {
            *(float4*)(C + (size_t)r * DIM + tx * 8) =
                make_float4(acc[i][0], acc[i][1], acc[i][2], acc[i][3]);
            *(float4*)(C + (size_t)r * DIM + tx * 8 + 4) =
                make_float4(acc[i][4], acc[i][5], acc[i][6], acc[i][7]);
        }
    }
}

// ---------------- fused gather: out[d] = relu?( b + dinv[d]^2*h[d] + sum_e c_e*h[src_e] ) ----------------
// One warp per node; each lane owns 4 features.
template <bool RELU>
__global__ __launch_bounds__(256)
void gather_kernel(const float* __restrict__ h, const float* __restrict__ bias,
                   const int* __restrict__ rowptr, const int* __restrict__ csr_src,
                   const float* __restrict__ csr_coef, const float* __restrict__ dinv,
                   float* __restrict__ out, int n) {
    int warp = (blockIdx.x * blockDim.x + threadIdx.x) >> 5;
    int lane = threadIdx.x & 31;
    if (warp >= n) return;
    const int d = warp;
    const int c4 = lane * 4;

    float di = __ldg(&dinv[d]);
    float s  = di * di;
    float4 self = *(const float4*)(h + (size_t)d * DIM + c4);
    float4 bb   = *(const float4*)(bias + c4);
    float4 acc;
    acc.x = fmaf(self.x, s, bb.x);
    acc.y = fmaf(self.y, s, bb.y);
    acc.z = fmaf(self.z, s, bb.z);
    acc.w = fmaf(self.w, s, bb.w);

    int j   = __ldg(&rowptr[d]);
    int end = __ldg(&rowptr[d + 1]);

    for (; j + 1 < end; j += 2) {
        int   s0 = __ldg(&csr_src[j]);
        int   s1 = __ldg(&csr_src[j + 1]);
        float c0 = __ldg(&csr_coef[j]);
        float c1 = __ldg(&csr_coef[j + 1]);
        float4 v0 = *(const float4*)(h + (size_t)s0 * DIM + c4);
        float4 v1 = *(const float4*)(h + (size_t)s1 * DIM + c4);
        acc.x = fmaf(v0.x, c0, acc.x);
        acc.y = fmaf(v0.y, c0, acc.y);
        acc.z = fmaf(v0.z, c0, acc.z);
        acc.w = fmaf(v0.w, c0, acc.w);
        acc.x = fmaf(v1.x, c1, acc.x);
        acc.y = fmaf(v1.y, c1, acc.y);
        acc.z = fmaf(v1.z, c1, acc.z);
        acc.w = fmaf(v1.w, c1, acc.w);
    }
    if (j < end) {
        int   s0 = __ldg(&csr_src[j]);
        float c0 = __ldg(&csr_coef[j]);
        float4 v0 = *(const float4*)(h + (size_t)s0 * DIM + c4);
        acc.x = fmaf(v0.x, c0, acc.x);
        acc.y = fmaf(v0.y, c0, acc.y);
        acc.z = fmaf(v0.z, c0, acc.z);
        acc.w = fmaf(v0.w, c0, acc.w);
    }

    if (RELU) {
        acc.x = fmaxf(acc.x, 0.f);
        acc.y = fmaxf(acc.y, 0.f);
        acc.z = fmaxf(acc.z, 0.f);
        acc.w = fmaxf(acc.w, 0.f);
    }
    *(float4*)(out + (size_t)d * DIM + c4) = acc;
}

extern "C" void kernel_launch(void* const* d_in, const int* in_sizes, int n_in,
                              void* d_out, int out_size) {
    const float* x  = (const float*)d_in[0];
    const int*   ei = (const int*)d_in[1];
    const float* W1 = (const float*)d_in[2];
    const float* b1 = (const float*)d_in[3];
    const float* W2 = (const float*)d_in[4];
    const float* b2 = (const float*)d_in[5];
    const float* W3 = (const float*)d_in[6];
    const float* b3 = (const float*)d_in[7];
    float*       out = (float*)d_out;

    const int N = in_sizes[0] / DIM;
    const int E = in_sizes[1] / 2;
    const int* src = ei;
    const int* dst = ei + E;

    float *h, *agg, *dinv, *csr_coef;
    int *deg, *cnt, *rowptr, *bsum, *csr_src;
    cudaGetSymbolAddress((void**)&h,        g_h);
    cudaGetSymbolAddress((void**)&agg,      g_agg);
    cudaGetSymbolAddress((void**)&dinv,     g_dinv);
    cudaGetSymbolAddress((void**)&deg,      g_deg);
    cudaGetSymbolAddress((void**)&cnt,      g_cnt);
    cudaGetSymbolAddress((void**)&rowptr,   g_rowptr);
    cudaGetSymbolAddress((void**)&bsum,     g_bsum);
    cudaGetSymbolAddress((void**)&csr_src,  g_csr_src);
    cudaGetSymbolAddress((void**)&csr_coef, g_csr_coef);

    const int TB = 256;
    const int n_blk  = (N + TB - 1) / TB;
    const int e_blk  = (E + TB - 1) / TB;
    const int gemm_g = (N + 127) / 128;
    const int nch    = (N + 1023) / 1024;
    const int gat_blk = (int)(((long)N * 32 + TB - 1) / TB);

    // ---- CSR build (by destination) ----
    zero2_kernel<<<n_blk, TB>>>(deg, cnt, N);
    deg_acc_kernel<<<e_blk, TB>>>(dst, deg, E);
    dinv_kernel<<<n_blk, TB>>>(deg, dinv, N);
    scan1_kernel<<<nch, 256>>>(deg, rowptr, bsum, N);
    scan2_kernel<<<1, 32>>>(bsum, nch, rowptr, N, E);
    scan3_kernel<<<n_blk, TB>>>(rowptr, bsum, N);
    fill_kernel<<<e_blk, TB>>>(src, dst, rowptr, cnt, dinv, csr_src, csr_coef, E);

    // ---- layer 1 ----
    sgemm_128<<<gemm_g, 256>>>(x, W1, h, N);
    gather_kernel<true><<<gat_blk, TB>>>(h, b1, rowptr, csr_src, csr_coef, dinv, agg, N);
    // ---- layer 2 ----
    sgemm_128<<<gemm_g, 256>>>(agg, W2, h, N);
    gather_kernel<true><<<gat_blk, TB>>>(h, b2, rowptr, csr_src, csr_coef, dinv, agg, N);
    // ---- layer 3 -> d_out ----
    sgemm_128<<<gemm_g, 256>>>(agg, W3, h, N);
    gather_kernel<false><<<gat_blk, TB>>>(h, b3, rowptr, csr_src, csr_coef, dinv, out, N);
}

// round 5
// speedup vs baseline: 1.2212x; 1.2212x over previous
#include <cuda_runtime.h>
#include <cuda_bf16.h>
#include <cstdint>

#define NNODES 100000
#define EMAX   1600000
#define DIM    128

// Scratch (__device__ globals: allocation-free rule)
__device__ float g_h[(size_t)NNODES * DIM];
__device__ float g_agg[(size_t)NNODES * DIM];
__device__ float g_dinv[NNODES];
__device__ int   g_deg[NNODES];
__device__ int   g_cnt[NNODES];
__device__ int   g_rowptr[NNODES + 1];
__device__ int   g_bsum[256];
__device__ int   g_csr_src[EMAX];
__device__ float g_csr_coef[EMAX];
__device__ __nv_bfloat16 g_whi[3 * DIM * DIM];  // W^T hi: [layer][n][k]
__device__ __nv_bfloat16 g_wlo[3 * DIM * DIM];  // W^T lo

// ================= helpers =================
__device__ __forceinline__ uint32_t smem_u32(const void* p) {
    uint32_t a;
    asm("{ .reg .u64 t; cvta.to.shared.u64 t, %1; cvt.u32.u64 %0, t; }" : "=r"(a) : "l"(p));
    return a;
}
__device__ __forceinline__ void ldm_x4(uint32_t* r, uint32_t addr) {
    asm volatile("ldmatrix.sync.aligned.m8n8.x4.shared.b16 {%0,%1,%2,%3}, [%4];"
                 : "=r"(r[0]), "=r"(r[1]), "=r"(r[2]), "=r"(r[3]) : "r"(addr));
}
__device__ __forceinline__ void mma_bf16(float* c, const uint32_t* a, const uint32_t* b) {
    asm volatile(
        "mma.sync.aligned.m16n8k16.row.col.f32.bf16.bf16.f32 "
        "{%0,%1,%2,%3}, {%4,%5,%6,%7}, {%8,%9}, {%0,%1,%2,%3};"
        : "+f"(c[0]), "+f"(c[1]), "+f"(c[2]), "+f"(c[3])
        : "r"(a[0]), "r"(a[1]), "r"(a[2]), "r"(a[3]), "r"(b[0]), "r"(b[1]));
}

// ================= CSR build =================
__global__ void zero2_kernel(int* __restrict__ a, int* __restrict__ b, int n) {
    int i = blockIdx.x * blockDim.x + threadIdx.x;
    if (i < n) { a[i] = 0; b[i] = 0; }
}
__global__ void deg_acc_kernel(const int* __restrict__ dst, int* __restrict__ deg, int E) {
    int e = blockIdx.x * blockDim.x + threadIdx.x;
    if (e < E) atomicAdd(&deg[dst[e]], 1);
}
__global__ void dinv_kernel(const int* __restrict__ deg, float* __restrict__ dinv, int n) {
    int i = blockIdx.x * blockDim.x + threadIdx.x;
    if (i < n) dinv[i] = rsqrtf((float)(deg[i] + 1));
}
__global__ void scan1_kernel(const int* __restrict__ in, int* __restrict__ out,
                             int* __restrict__ bsum, int n) {
    __shared__ int sh[256];
    int t = threadIdx.x;
    int i0 = blockIdx.x * 1024 + t * 4;
    int v[4];
#pragma unroll
    for (int k = 0; k < 4; k++) v[k] = (i0 + k < n) ? in[i0 + k] : 0;
    int s = v[0] + v[1] + v[2] + v[3];
    sh[t] = s;
    __syncthreads();
#pragma unroll
    for (int off = 1; off < 256; off <<= 1) {
        int x = (t >= off) ? sh[t - off] : 0;
        __syncthreads();
        sh[t] += x;
        __syncthreads();
    }
    int run = sh[t] - s;
#pragma unroll
    for (int k = 0; k < 4; k++) {
        if (i0 + k < n) out[i0 + k] = run;
        run += v[k];
    }
    if (t == 255) bsum[blockIdx.x] = sh[255];
}
__global__ void scan2_kernel(int* __restrict__ bsum, int nch, int* __restrict__ rowptr,
                             int n, int E) {
    if (threadIdx.x == 0) {
        int run = 0;
        for (int i = 0; i < nch; i++) { int t = bsum[i]; bsum[i] = run; run += t; }
        rowptr[n] = E;
    }
}
__global__ void scan3_kernel(int* __restrict__ rowptr, const int* __restrict__ bsum, int n) {
    int i = blockIdx.x * blockDim.x + threadIdx.x;
    if (i < n) rowptr[i] += bsum[i >> 10];
}
__global__ void fill_kernel(const int* __restrict__ src, const int* __restrict__ dst,
                            const int* __restrict__ rowptr, int* __restrict__ cnt,
                            const float* __restrict__ dinv,
                            int* __restrict__ csr_src, float* __restrict__ csr_coef, int E) {
    int e = blockIdx.x * blockDim.x + threadIdx.x;
    if (e >= E) return;
    int s = src[e], d = dst[e];
    int pos = rowptr[d] + atomicAdd(&cnt[d], 1);
    csr_src[pos]  = s;
    csr_coef[pos] = dinv[s] * dinv[d];
}

// ================= W prep: Wt_hi/lo[n][k] = split(W[k][n]) =================
__global__ void wprep_kernel(const float* __restrict__ W,
                             __nv_bfloat16* __restrict__ bhi,
                             __nv_bfloat16* __restrict__ blo) {
    int i = blockIdx.x * blockDim.x + threadIdx.x;  // [n][k]
    if (i >= DIM * DIM) return;
    int n = i >> 7, k = i & 127;
    float w = W[k * DIM + n];
    __nv_bfloat16 hi = __float2bfloat16(w);
    __nv_bfloat16 lo = __float2bfloat16(w - __bfloat162float(hi));
    bhi[i] = hi;
    blo[i] = lo;
}

// ================= HMMA GEMM: C[M,128] = A[M,128] @ W =================
// 256 threads (8 warps), CTA tile 128x128, warp tile 32 rows x 64 cols.
// bf16 hi/lo split: acc = Ahi*Whi + Ahi*Wlo + Alo*Whi.
#define LDA 136           // bf16 elems per smem row (pad 8: conflict-free ldmatrix)
#define SM_AHI 0
#define SM_ALO 34816
#define SM_WHI 69632
#define SM_WLO 104448
#define SM_TOT 139264
#define LDS_STAGE 132     // floats per row for epilogue staging

__global__ __launch_bounds__(256, 1)
void mma_gemm(const float* __restrict__ A,
              const __nv_bfloat16* __restrict__ Whi,   // [n][k]
              const __nv_bfloat16* __restrict__ Wlo,
              float* __restrict__ C, int M) {
    extern __shared__ char smem[];
    const uint32_t sb = smem_u32(smem);
    const int tid  = threadIdx.x;
    const int wid  = tid >> 5;
    const int lane = tid & 31;
    const int row0 = blockIdx.x * 128;

    // ---- load A (fp32 -> bf16 hi/lo) and W (bf16) into padded smem ----
    for (int i = tid; i < 128 * 64; i += 256) {
        int row = i >> 6, cp = i & 63, col = cp * 2;
        float2 v = make_float2(0.f, 0.f);
        if (row0 + row < M) v = *(const float2*)(A + (size_t)(row0 + row) * DIM + col);
        __nv_bfloat16 hx = __float2bfloat16(v.x);
        __nv_bfloat16 hy = __float2bfloat16(v.y);
        __nv_bfloat16 lx = __float2bfloat16(v.x - __bfloat162float(hx));
        __nv_bfloat16 ly = __float2bfloat16(v.y - __bfloat162float(hy));
        __nv_bfloat162 hp = __nv_bfloat162(hx, hy);
        __nv_bfloat162 lp = __nv_bfloat162(lx, ly);
        uint32_t off = (uint32_t)(row * LDA + col) * 2;
        *(uint32_t*)(smem + SM_AHI + off) = *(uint32_t*)&hp;
        *(uint32_t*)(smem + SM_ALO + off) = *(uint32_t*)&lp;

        // W: i -> [n][k] pair
        uint32_t wh = *(const uint32_t*)(Whi + (size_t)row * DIM + col);
        uint32_t wl = *(const uint32_t*)(Wlo + (size_t)row * DIM + col);
        *(uint32_t*)(smem + SM_WHI + off) = wh;
        *(uint32_t*)(smem + SM_WLO + off) = wl;
    }
    __syncthreads();

    const int wr = (wid >> 1) * 32;   // warp row base: 0/32/64/96
    const int wc = (wid & 1) * 64;    // warp col base: 0/64

    float acc[2][8][4];
#pragma unroll
    for (int rt = 0; rt < 2; rt++)
#pragma unroll
        for (int j = 0; j < 8; j++)
#pragma unroll
            for (int q = 0; q < 4; q++) acc[rt][j][q] = 0.f;

    const int m  = lane >> 3;   // matrix id within ldmatrix.x4
    const int rr = lane & 7;

#pragma unroll
    for (int ks = 0; ks < 8; ks++) {
        const int k0 = ks * 16;

        // A fragments (row-major): matrices [r0-7,k0-7][r8-15,k0-7][r0-7,k8-15][r8-15,k8-15]
        uint32_t ah[2][4], al[2][4];
#pragma unroll
        for (int rt = 0; rt < 2; rt++) {
            int arow = wr + rt * 16 + ((m & 1) ? 8 : 0) + rr;
            int acol = k0 + ((m >> 1) ? 8 : 0);
            uint32_t off = (uint32_t)(arow * LDA + acol) * 2;
            ldm_x4(ah[rt], sb + SM_AHI + off);
            ldm_x4(al[rt], sb + SM_ALO + off);
        }

        // B fragments from Wt[n][k] (row-major n x k => col-major k x n, no trans)
        // matrices: [n0-7,k0-7][n0-7,k8-15][n8-15,k0-7][n8-15,k8-15]
        uint32_t bh[8][2], bl[8][2];
#pragma unroll
        for (int jp = 0; jp < 4; jp++) {
            int nrow = wc + jp * 16 + ((m >> 1) ? 8 : 0) + rr;
            int kcol = k0 + ((m & 1) ? 8 : 0);
            uint32_t off = (uint32_t)(nrow * LDA + kcol) * 2;
            uint32_t r[4];
            ldm_x4(r, sb + SM_WHI + off);
            bh[jp * 2][0] = r[0]; bh[jp * 2][1] = r[1];
            bh[jp * 2 + 1][0] = r[2]; bh[jp * 2 + 1][1] = r[3];
            ldm_x4(r, sb + SM_WLO + off);
            bl[jp * 2][0] = r[0]; bl[jp * 2][1] = r[1];
            bl[jp * 2 + 1][0] = r[2]; bl[jp * 2 + 1][1] = r[3];
        }

#pragma unroll
        for (int rt = 0; rt < 2; rt++)
#pragma unroll
            for (int j = 0; j < 8; j++) {
                mma_bf16(acc[rt][j], ah[rt], bh[j]);
                mma_bf16(acc[rt][j], ah[rt], bl[j]);
                mma_bf16(acc[rt][j], al[rt], bh[j]);
            }
    }

    // ---- epilogue: fragments -> staging smem (reuses A region) -> coalesced global ----
    __syncthreads();
    float* stage = (float*)smem;
    const int g  = lane >> 2;
    const int cq = (lane & 3) * 2;
#pragma unroll
    for (int rt = 0; rt < 2; rt++)
#pragma unroll
        for (int j = 0; j < 8; j++) {
            int row = wr + rt * 16 + g;
            int col = wc + j * 8 + cq;
            stage[row * LDS_STAGE + col]           = acc[rt][j][0];
            stage[row * LDS_STAGE + col + 1]       = acc[rt][j][1];
            stage[(row + 8) * LDS_STAGE + col]     = acc[rt][j][2];
            stage[(row + 8) * LDS_STAGE + col + 1] = acc[rt][j][3];
        }
    __syncthreads();

    for (int i = tid; i < 128 * 32; i += 256) {
        int r = i >> 5, cp = i & 31;
        if (row0 + r < M) {
            float4 v = *(float4*)(stage + r * LDS_STAGE + cp * 4);
            *(float4*)(C + (size_t)(row0 + r) * DIM + cp * 4) = v;
        }
    }
}

// ================= fused gather =================
template <bool RELU>
__global__ __launch_bounds__(256)
void gather_kernel(const float* __restrict__ h, const float* __restrict__ bias,
                   const int* __restrict__ rowptr, const int* __restrict__ csr_src,
                   const float* __restrict__ csr_coef, const float* __restrict__ dinv,
                   float* __restrict__ out, int n) {
    int warp = (blockIdx.x * blockDim.x + threadIdx.x) >> 5;
    int lane = threadIdx.x & 31;
    if (warp >= n) return;
    const int d = warp;
    const int c4 = lane * 4;

    float di = __ldg(&dinv[d]);
    float s  = di * di;
    float4 self = *(const float4*)(h + (size_t)d * DIM + c4);
    float4 bb   = *(const float4*)(bias + c4);
    float4 acc;
    acc.x = fmaf(self.x, s, bb.x);
    acc.y = fmaf(self.y, s, bb.y);
    acc.z = fmaf(self.z, s, bb.z);
    acc.w = fmaf(self.w, s, bb.w);

    int j   = __ldg(&rowptr[d]);
    int end = __ldg(&rowptr[d + 1]);

    for (; j + 1 < end; j += 2) {
        int   s0 = __ldg(&csr_src[j]);
        int   s1 = __ldg(&csr_src[j + 1]);
        float c0 = __ldg(&csr_coef[j]);
        float c1 = __ldg(&csr_coef[j + 1]);
        float4 v0 = *(const float4*)(h + (size_t)s0 * DIM + c4);
        float4 v1 = *(const float4*)(h + (size_t)s1 * DIM + c4);
        acc.x = fmaf(v0.x, c0, acc.x);
        acc.y = fmaf(v0.y, c0, acc.y);
        acc.z = fmaf(v0.z, c0, acc.z);
        acc.w = fmaf(v0.w, c0, acc.w);
        acc.x = fmaf(v1.x, c1, acc.x);
        acc.y = fmaf(v1.y, c1, acc.y);
        acc.z = fmaf(v1.z, c1, acc.z);
        acc.w = fmaf(v1.w, c1, acc.w);
    }
    if (j < end) {
        int   s0 = __ldg(&csr_src[j]);
        float c0 = __ldg(&csr_coef[j]);
        float4 v0 = *(const float4*)(h + (size_t)s0 * DIM + c4);
        acc.x = fmaf(v0.x, c0, acc.x);
        acc.y = fmaf(v0.y, c0, acc.y);
        acc.z = fmaf(v0.z, c0, acc.z);
        acc.w = fmaf(v0.w, c0, acc.w);
    }

    if (RELU) {
        acc.x = fmaxf(acc.x, 0.f);
        acc.y = fmaxf(acc.y, 0.f);
        acc.z = fmaxf(acc.z, 0.f);
        acc.w = fmaxf(acc.w, 0.f);
    }
    *(float4*)(out + (size_t)d * DIM + c4) = acc;
}

extern "C" void kernel_launch(void* const* d_in, const int* in_sizes, int n_in,
                              void* d_out, int out_size) {
    const float* x  = (const float*)d_in[0];
    const int*   ei = (const int*)d_in[1];
    const float* W1 = (const float*)d_in[2];
    const float* b1 = (const float*)d_in[3];
    const float* W2 = (const float*)d_in[4];
    const float* b2 = (const float*)d_in[5];
    const float* W3 = (const float*)d_in[6];
    const float* b3 = (const float*)d_in[7];
    float*       out = (float*)d_out;

    const int N = in_sizes[0] / DIM;
    const int E = in_sizes[1] / 2;
    const int* src = ei;
    const int* dst = ei + E;

    float *h, *agg, *dinv, *csr_coef;
    int *deg, *cnt, *rowptr, *bsum, *csr_src;
    __nv_bfloat16 *whi, *wlo;
    cudaGetSymbolAddress((void**)&h,        g_h);
    cudaGetSymbolAddress((void**)&agg,      g_agg);
    cudaGetSymbolAddress((void**)&dinv,     g_dinv);
    cudaGetSymbolAddress((void**)&deg,      g_deg);
    cudaGetSymbolAddress((void**)&cnt,      g_cnt);
    cudaGetSymbolAddress((void**)&rowptr,   g_rowptr);
    cudaGetSymbolAddress((void**)&bsum,     g_bsum);
    cudaGetSymbolAddress((void**)&csr_src,  g_csr_src);
    cudaGetSymbolAddress((void**)&csr_coef, g_csr_coef);
    cudaGetSymbolAddress((void**)&whi,      g_whi);
    cudaGetSymbolAddress((void**)&wlo,      g_wlo);

    cudaFuncSetAttribute(mma_gemm, cudaFuncAttributeMaxDynamicSharedMemorySize, SM_TOT);

    const int TB = 256;
    const int n_blk  = (N + TB - 1) / TB;
    const int e_blk  = (E + TB - 1) / TB;
    const int gemm_g = (N + 127) / 128;
    const int nch    = (N + 1023) / 1024;
    const int gat_blk = (int)(((long)N * 32 + TB - 1) / TB);

    // ---- CSR build + weight split prep ----
    zero2_kernel<<<n_blk, TB>>>(deg, cnt, N);
    deg_acc_kernel<<<e_blk, TB>>>(dst, deg, E);
    dinv_kernel<<<n_blk, TB>>>(deg, dinv, N);
    scan1_kernel<<<nch, 256>>>(deg, rowptr, bsum, N);
    scan2_kernel<<<1, 32>>>(bsum, nch, rowptr, N, E);
    scan3_kernel<<<n_blk, TB>>>(rowptr, bsum, N);
    fill_kernel<<<e_blk, TB>>>(src, dst, rowptr, cnt, dinv, csr_src, csr_coef, E);
    wprep_kernel<<<64, 256>>>(W1, whi,                 wlo);
    wprep_kernel<<<64, 256>>>(W2, whi + DIM * DIM,     wlo + DIM * DIM);
    wprep_kernel<<<64, 256>>>(W3, whi + 2 * DIM * DIM, wlo + 2 * DIM * DIM);

    // ---- layer 1 ----
    mma_gemm<<<gemm_g, 256, SM_TOT>>>(x, whi, wlo, h, N);
    gather_kernel<true><<<gat_blk, TB>>>(h, b1, rowptr, csr_src, csr_coef, dinv, agg, N);
    // ---- layer 2 ----
    mma_gemm<<<gemm_g, 256, SM_TOT>>>(agg, whi + DIM * DIM, wlo + DIM * DIM, h, N);
    gather_kernel<true><<<gat_blk, TB>>>(h, b2, rowptr, csr_src, csr_coef, dinv, agg, N);
    // ---- layer 3 -> d_out ----
    mma_gemm<<<gemm_g, 256, SM_TOT>>>(agg, whi + 2 * DIM * DIM, wlo + 2 * DIM * DIM, h, N);
    gather_kernel<false><<<gat_blk, TB>>>(h, b3, rowptr, csr_src, csr_coef, dinv, out, N);
}

// round 6
// speedup vs baseline: 1.2296x; 1.0069x over previous
#include <cuda_runtime.h>
#include <cuda_bf16.h>
#include <cstdint>

#define NNODES 100000
#define EMAX   1600000
#define DIM    128

// Scratch (__device__ globals: allocation-free rule)
__device__ float g_h[(size_t)NNODES * DIM];
__device__ float g_agg[(size_t)NNODES * DIM];
__device__ float g_dinv[NNODES];
__device__ int   g_deg[NNODES];
__device__ int   g_cnt[NNODES];
__device__ int   g_rowptr[NNODES + 1];
__device__ int   g_bsum[256];
__device__ int   g_csr_src[EMAX];
__device__ float g_csr_coef[EMAX];
__device__ __nv_bfloat16 g_whi[3 * DIM * DIM];  // W^T hi: [layer][n][k]
__device__ __nv_bfloat16 g_wlo[3 * DIM * DIM];  // W^T lo

// ================= helpers =================
__device__ __forceinline__ uint32_t smem_u32(const void* p) {
    uint32_t a;
    asm("{ .reg .u64 t; cvta.to.shared.u64 t, %1; cvt.u32.u64 %0, t; }" : "=r"(a) : "l"(p));
    return a;
}
__device__ __forceinline__ void ldm_x4(uint32_t* r, uint32_t addr) {
    asm volatile("ldmatrix.sync.aligned.m8n8.x4.shared.b16 {%0,%1,%2,%3}, [%4];"
                 : "=r"(r[0]), "=r"(r[1]), "=r"(r[2]), "=r"(r[3]) : "r"(addr));
}
__device__ __forceinline__ void mma_bf16(float* c, const uint32_t* a, const uint32_t* b) {
    asm volatile(
        "mma.sync.aligned.m16n8k16.row.col.f32.bf16.bf16.f32 "
        "{%0,%1,%2,%3}, {%4,%5,%6,%7}, {%8,%9}, {%0,%1,%2,%3};"
        : "+f"(c[0]), "+f"(c[1]), "+f"(c[2]), "+f"(c[3])
        : "r"(a[0]), "r"(a[1]), "r"(a[2]), "r"(a[3]), "r"(b[0]), "r"(b[1]));
}

// ================= CSR build =================
__global__ void zero2_kernel(int* __restrict__ a, int* __restrict__ b, int n) {
    int i = blockIdx.x * blockDim.x + threadIdx.x;
    if (i < n) { a[i] = 0; b[i] = 0; }
}
__global__ void deg_acc_kernel(const int* __restrict__ dst, int* __restrict__ deg, int E) {
    int e = blockIdx.x * blockDim.x + threadIdx.x;
    if (e < E) atomicAdd(&deg[dst[e]], 1);
}
__global__ void dinv_kernel(const int* __restrict__ deg, float* __restrict__ dinv, int n) {
    int i = blockIdx.x * blockDim.x + threadIdx.x;
    if (i < n) dinv[i] = rsqrtf((float)(deg[i] + 1));
}
__global__ void scan1_kernel(const int* __restrict__ in, int* __restrict__ out,
                             int* __restrict__ bsum, int n) {
    __shared__ int sh[256];
    int t = threadIdx.x;
    int i0 = blockIdx.x * 1024 + t * 4;
    int v[4];
#pragma unroll
    for (int k = 0; k < 4; k++) v[k] = (i0 + k < n) ? in[i0 + k] : 0;
    int s = v[0] + v[1] + v[2] + v[3];
    sh[t] = s;
    __syncthreads();
#pragma unroll
    for (int off = 1; off < 256; off <<= 1) {
        int x = (t >= off) ? sh[t - off] : 0;
        __syncthreads();
        sh[t] += x;
        __syncthreads();
    }
    int run = sh[t] - s;
#pragma unroll
    for (int k = 0; k < 4; k++) {
        if (i0 + k < n) out[i0 + k] = run;
        run += v[k];
    }
    if (t == 255) bsum[blockIdx.x] = sh[255];
}
__global__ void scan2_kernel(int* __restrict__ bsum, int nch, int* __restrict__ rowptr,
                             int n, int E) {
    if (threadIdx.x == 0) {
        int run = 0;
        for (int i = 0; i < nch; i++) { int t = bsum[i]; bsum[i] = run; run += t; }
        rowptr[n] = E;
    }
}
__global__ void scan3_kernel(int* __restrict__ rowptr, const int* __restrict__ bsum, int n) {
    int i = blockIdx.x * blockDim.x + threadIdx.x;
    if (i < n) rowptr[i] += bsum[i >> 10];
}
__global__ void fill_kernel(const int* __restrict__ src, const int* __restrict__ dst,
                            const int* __restrict__ rowptr, int* __restrict__ cnt,
                            const float* __restrict__ dinv,
                            int* __restrict__ csr_src, float* __restrict__ csr_coef, int E) {
    int e = blockIdx.x * blockDim.x + threadIdx.x;
    if (e >= E) return;
    int s = src[e], d = dst[e];
    int pos = rowptr[d] + atomicAdd(&cnt[d], 1);
    csr_src[pos]  = s;
    csr_coef[pos] = dinv[s] * dinv[d];
}

// ================= W prep (all 3 layers): Wt_hi/lo[l][n][k] = split(Wl[k][n]) =================
__global__ void wprep_all_kernel(const float* __restrict__ W1, const float* __restrict__ W2,
                                 const float* __restrict__ W3,
                                 __nv_bfloat16* __restrict__ bhi,
                                 __nv_bfloat16* __restrict__ blo) {
    int i = blockIdx.x * blockDim.x + threadIdx.x;  // [l][n][k]
    if (i >= 3 * DIM * DIM) return;
    int l = i / (DIM * DIM);
    int r = i - l * DIM * DIM;
    int n = r >> 7, k = r & 127;
    const float* W = (l == 0) ? W1 : (l == 1) ? W2 : W3;
    float w = W[k * DIM + n];
    __nv_bfloat16 hi = __float2bfloat16(w);
    __nv_bfloat16 lo = __float2bfloat16(w - __bfloat162float(hi));
    bhi[i] = hi;
    blo[i] = lo;
}

// ================= HMMA GEMM: C[M,128] = A[M,128] @ W =================
// 256 threads (8 warps), CTA tile 256x128, warp tile 64x64.
// bf16 hi/lo split: acc = Ahi*Whi + Ahi*Wlo + Alo*Whi.
#define TILE_M 256
#define LDA 136           // bf16 elems per smem row (pad 8: conflict-free ldmatrix)
#define SM_AHI 0
#define SM_ALO (SM_AHI + TILE_M * LDA * 2)          // 69632
#define SM_WHI (SM_ALO + TILE_M * LDA * 2)          // 139264
#define SM_WLO (SM_WHI + DIM * LDA * 2)             // 174080
#define SM_TOT (SM_WLO + DIM * LDA * 2)             // 208896
#define LDS_STAGE 132     // floats per row for epilogue staging

__global__ __launch_bounds__(256, 1)
void mma_gemm(const float* __restrict__ A,
              const __nv_bfloat16* __restrict__ Whi,   // [n][k]
              const __nv_bfloat16* __restrict__ Wlo,
              float* __restrict__ C, int M) {
    extern __shared__ char smem[];
    const uint32_t sb = smem_u32(smem);
    const int tid  = threadIdx.x;
    const int wid  = tid >> 5;
    const int lane = tid & 31;
    const int row0 = blockIdx.x * TILE_M;

    // ---- load A (fp32 -> bf16 hi/lo) into padded smem ----
    for (int i = tid; i < TILE_M * 64; i += 256) {
        int row = i >> 6, cp = i & 63, col = cp * 2;
        float2 v = make_float2(0.f, 0.f);
        if (row0 + row < M) v = *(const float2*)(A + (size_t)(row0 + row) * DIM + col);
        __nv_bfloat16 hx = __float2bfloat16(v.x);
        __nv_bfloat16 hy = __float2bfloat16(v.y);
        __nv_bfloat16 lx = __float2bfloat16(v.x - __bfloat162float(hx));
        __nv_bfloat16 ly = __float2bfloat16(v.y - __bfloat162float(hy));
        __nv_bfloat162 hp = __nv_bfloat162(hx, hy);
        __nv_bfloat162 lp = __nv_bfloat162(lx, ly);
        uint32_t off = (uint32_t)(row * LDA + col) * 2;
        *(uint32_t*)(smem + SM_AHI + off) = *(uint32_t*)&hp;
        *(uint32_t*)(smem + SM_ALO + off) = *(uint32_t*)&lp;
    }
    // ---- load W hi/lo (bf16 [n][k]) ----
    for (int i = tid; i < DIM * 64; i += 256) {
        int n = i >> 6, cp = i & 63, col = cp * 2;
        uint32_t off = (uint32_t)(n * LDA + col) * 2;
        *(uint32_t*)(smem + SM_WHI + off) = *(const uint32_t*)(Whi + (size_t)n * DIM + col);
        *(uint32_t*)(smem + SM_WLO + off) = *(const uint32_t*)(Wlo + (size_t)n * DIM + col);
    }
    __syncthreads();

    const int wr = (wid >> 1) * 64;   // warp row base: 0/64/128/192
    const int wc = (wid & 1) * 64;    // warp col base: 0/64

    float acc[4][8][4];
#pragma unroll
    for (int rt = 0; rt < 4; rt++)
#pragma unroll
        for (int j = 0; j < 8; j++)
#pragma unroll
            for (int q = 0; q < 4; q++) acc[rt][j][q] = 0.f;

    const int m  = lane >> 3;   // matrix id within ldmatrix.x4
    const int rr = lane & 7;

#pragma unroll
    for (int ks = 0; ks < 8; ks++) {
        const int k0 = ks * 16;

        // B fragments from Wt[n][k] (row-major n x k => col-major k x n, no trans)
        uint32_t bh[8][2], bl[8][2];
#pragma unroll
        for (int jp = 0; jp < 4; jp++) {
            int nrow = wc + jp * 16 + ((m >> 1) ? 8 : 0) + rr;
            int kcol = k0 + ((m & 1) ? 8 : 0);
            uint32_t off = (uint32_t)(nrow * LDA + kcol) * 2;
            uint32_t r[4];
            ldm_x4(r, sb + SM_WHI + off);
            bh[jp * 2][0] = r[0]; bh[jp * 2][1] = r[1];
            bh[jp * 2 + 1][0] = r[2]; bh[jp * 2 + 1][1] = r[3];
            ldm_x4(r, sb + SM_WLO + off);
            bl[jp * 2][0] = r[0]; bl[jp * 2][1] = r[1];
            bl[jp * 2 + 1][0] = r[2]; bl[jp * 2 + 1][1] = r[3];
        }

        // A fragments (row-major), 4 row-tiles of 16
#pragma unroll
        for (int rt = 0; rt < 4; rt++) {
            int arow = wr + rt * 16 + ((m & 1) ? 8 : 0) + rr;
            int acol = k0 + ((m >> 1) ? 8 : 0);
            uint32_t off = (uint32_t)(arow * LDA + acol) * 2;
            uint32_t ah[4], al[4];
            ldm_x4(ah, sb + SM_AHI + off);
            ldm_x4(al, sb + SM_ALO + off);
#pragma unroll
            for (int j = 0; j < 8; j++) {
                mma_bf16(acc[rt][j], ah, bh[j]);
                mma_bf16(acc[rt][j], ah, bl[j]);
                mma_bf16(acc[rt][j], al, bh[j]);
            }
        }
    }

    // ---- epilogue: fragments -> staging smem (reuses A region) -> coalesced global ----
    __syncthreads();
    float* stage = (float*)smem;
    const int g  = lane >> 2;
    const int cq = (lane & 3) * 2;
#pragma unroll
    for (int rt = 0; rt < 4; rt++)
#pragma unroll
        for (int j = 0; j < 8; j++) {
            int row = wr + rt * 16 + g;
            int col = wc + j * 8 + cq;
            stage[row * LDS_STAGE + col]           = acc[rt][j][0];
            stage[row * LDS_STAGE + col + 1]       = acc[rt][j][1];
            stage[(row + 8) * LDS_STAGE + col]     = acc[rt][j][2];
            stage[(row + 8) * LDS_STAGE + col + 1] = acc[rt][j][3];
        }
    __syncthreads();

    for (int i = tid; i < TILE_M * 32; i += 256) {
        int r = i >> 5, cp = i & 31;
        if (row0 + r < M) {
            float4 v = *(float4*)(stage + r * LDS_STAGE + cp * 4);
            *(float4*)(C + (size_t)(row0 + r) * DIM + cp * 4) = v;
        }
    }
}

// ================= fused gather =================
template <bool RELU>
__global__ __launch_bounds__(256)
void gather_kernel(const float* __restrict__ h, const float* __restrict__ bias,
                   const int* __restrict__ rowptr, const int* __restrict__ csr_src,
                   const float* __restrict__ csr_coef, const float* __restrict__ dinv,
                   float* __restrict__ out, int n) {
    int warp = (blockIdx.x * blockDim.x + threadIdx.x) >> 5;
    int lane = threadIdx.x & 31;
    if (warp >= n) return;
    const int d = warp;
    const int c4 = lane * 4;

    float di = __ldg(&dinv[d]);
    float s  = di * di;
    float4 self = *(const float4*)(h + (size_t)d * DIM + c4);
    float4 bb   = *(const float4*)(bias + c4);
    float4 acc;
    acc.x = fmaf(self.x, s, bb.x);
    acc.y = fmaf(self.y, s, bb.y);
    acc.z = fmaf(self.z, s, bb.z);
    acc.w = fmaf(self.w, s, bb.w);

    int j   = __ldg(&rowptr[d]);
    int end = __ldg(&rowptr[d + 1]);

    for (; j + 1 < end; j += 2) {
        int   s0 = __ldg(&csr_src[j]);
        int   s1 = __ldg(&csr_src[j + 1]);
        float c0 = __ldg(&csr_coef[j]);
        float c1 = __ldg(&csr_coef[j + 1]);
        float4 v0 = *(const float4*)(h + (size_t)s0 * DIM + c4);
        float4 v1 = *(const float4*)(h + (size_t)s1 * DIM + c4);
        acc.x = fmaf(v0.x, c0, acc.x);
        acc.y = fmaf(v0.y, c0, acc.y);
        acc.z = fmaf(v0.z, c0, acc.z);
        acc.w = fmaf(v0.w, c0, acc.w);
        acc.x = fmaf(v1.x, c1, acc.x);
        acc.y = fmaf(v1.y, c1, acc.y);
        acc.z = fmaf(v1.z, c1, acc.z);
        acc.w = fmaf(v1.w, c1, acc.w);
    }
    if (j < end) {
        int   s0 = __ldg(&csr_src[j]);
        float c0 = __ldg(&csr_coef[j]);
        float4 v0 = *(const float4*)(h + (size_t)s0 * DIM + c4);
        acc.x = fmaf(v0.x, c0, acc.x);
        acc.y = fmaf(v0.y, c0, acc.y);
        acc.z = fmaf(v0.z, c0, acc.z);
        acc.w = fmaf(v0.w, c0, acc.w);
    }

    if (RELU) {
        acc.x = fmaxf(acc.x, 0.f);
        acc.y = fmaxf(acc.y, 0.f);
        acc.z = fmaxf(acc.z, 0.f);
        acc.w = fmaxf(acc.w, 0.f);
    }
    *(float4*)(out + (size_t)d * DIM + c4) = acc;
}

extern "C" void kernel_launch(void* const* d_in, const int* in_sizes, int n_in,
                              void* d_out, int out_size) {
    const float* x  = (const float*)d_in[0];
    const int*   ei = (const int*)d_in[1];
    const float* W1 = (const float*)d_in[2];
    const float* b1 = (const float*)d_in[3];
    const float* W2 = (const float*)d_in[4];
    const float* b2 = (const float*)d_in[5];
    const float* W3 = (const float*)d_in[6];
    const float* b3 = (const float*)d_in[7];
    float*       out = (float*)d_out;

    const int N = in_sizes[0] / DIM;
    const int E = in_sizes[1] / 2;
    const int* src = ei;
    const int* dst = ei + E;

    float *h, *agg, *dinv, *csr_coef;
    int *deg, *cnt, *rowptr, *bsum, *csr_src;
    __nv_bfloat16 *whi, *wlo;
    cudaGetSymbolAddress((void**)&h,        g_h);
    cudaGetSymbolAddress((void**)&agg,      g_agg);
    cudaGetSymbolAddress((void**)&dinv,     g_dinv);
    cudaGetSymbolAddress((void**)&deg,      g_deg);
    cudaGetSymbolAddress((void**)&cnt,      g_cnt);
    cudaGetSymbolAddress((void**)&rowptr,   g_rowptr);
    cudaGetSymbolAddress((void**)&bsum,     g_bsum);
    cudaGetSymbolAddress((void**)&csr_src,  g_csr_src);
    cudaGetSymbolAddress((void**)&csr_coef, g_csr_coef);
    cudaGetSymbolAddress((void**)&whi,      g_whi);
    cudaGetSymbolAddress((void**)&wlo,      g_wlo);

    cudaFuncSetAttribute(mma_gemm, cudaFuncAttributeMaxDynamicSharedMemorySize, SM_TOT);

    const int TB = 256;
    const int n_blk  = (N + TB - 1) / TB;
    const int e_blk  = (E + TB - 1) / TB;
    const int gemm_g = (N + TILE_M - 1) / TILE_M;
    const int nch    = (N + 1023) / 1024;
    const int gat_blk = (int)(((long)N * 32 + TB - 1) / TB);

    // Launch order chosen so mma_gemm is the 4th launch (ncu profile slot).
    wprep_all_kernel<<<192, 256>>>(W1, W2, W3, whi, wlo);                     // 1
    zero2_kernel<<<n_blk, TB>>>(deg, cnt, N);                                 // 2
    deg_acc_kernel<<<e_blk, TB>>>(dst, deg, E);                               // 3
    mma_gemm<<<gemm_g, 256, SM_TOT>>>(x, whi, wlo, h, N);                     // 4 (profiled)
    dinv_kernel<<<n_blk, TB>>>(deg, dinv, N);                                 // 5
    scan1_kernel<<<nch, 256>>>(deg, rowptr, bsum, N);                         // 6
    scan2_kernel<<<1, 32>>>(bsum, nch, rowptr, N, E);                         // 7
    scan3_kernel<<<n_blk, TB>>>(rowptr, bsum, N);                             // 8
    fill_kernel<<<e_blk, TB>>>(src, dst, rowptr, cnt, dinv, csr_src, csr_coef, E);  // 9

    // ---- layer 1 aggregation ----
    gather_kernel<true><<<gat_blk, TB>>>(h, b1, rowptr, csr_src, csr_coef, dinv, agg, N);
    // ---- layer 2 ----
    mma_gemm<<<gemm_g, 256, SM_TOT>>>(agg, whi + DIM * DIM, wlo + DIM * DIM, h, N);
    gather_kernel<true><<<gat_blk, TB>>>(h, b2, rowptr, csr_src, csr_coef, dinv, agg, N);
    // ---- layer 3 -> d_out ----
    mma_gemm<<<gemm_g, 256, SM_TOT>>>(agg, whi + 2 * DIM * DIM, wlo + 2 * DIM * DIM, h, N);
    gather_kernel<false><<<gat_blk, TB>>>(h, b3, rowptr, csr_src, csr_coef, dinv, out, N);
}

// round 7
// speedup vs baseline: 1.3040x; 1.0605x over previous
#include <cuda_runtime.h>
#include <cuda_bf16.h>
#include <cstdint>

#define NNODES 100000
#define EMAX   1600000
#define DIM    128

// Scratch (__device__ globals: allocation-free rule)
__device__ float g_h[(size_t)NNODES * DIM];
__device__ float g_agg[(size_t)NNODES * DIM];
__device__ float g_dinv[NNODES];
__device__ int   g_deg[NNODES];
__device__ int   g_cnt[NNODES];
__device__ int   g_rowptr[NNODES + 1];
__device__ int   g_bsum[256];
__device__ int   g_csr_src[EMAX];
__device__ float g_csr_coef[EMAX];
__device__ __nv_bfloat16 g_whi[3 * DIM * DIM];  // W^T hi: [layer][n][k]
__device__ __nv_bfloat16 g_wlo[3 * DIM * DIM];  // W^T lo

// ================= helpers =================
__device__ __forceinline__ uint32_t smem_u32(const void* p) {
    uint32_t a;
    asm("{ .reg .u64 t; cvta.to.shared.u64 t, %1; cvt.u32.u64 %0, t; }" : "=r"(a) : "l"(p));
    return a;
}
__device__ __forceinline__ void ldm_x4(uint32_t* r, uint32_t addr) {
    asm volatile("ldmatrix.sync.aligned.m8n8.x4.shared.b16 {%0,%1,%2,%3}, [%4];"
                 : "=r"(r[0]), "=r"(r[1]), "=r"(r[2]), "=r"(r[3]) : "r"(addr));
}
__device__ __forceinline__ void mma_bf16(float* c, const uint32_t* a, const uint32_t* b) {
    asm volatile(
        "mma.sync.aligned.m16n8k16.row.col.f32.bf16.bf16.f32 "
        "{%0,%1,%2,%3}, {%4,%5,%6,%7}, {%8,%9}, {%0,%1,%2,%3};"
        : "+f"(c[0]), "+f"(c[1]), "+f"(c[2]), "+f"(c[3])
        : "r"(a[0]), "r"(a[1]), "r"(a[2]), "r"(a[3]), "r"(b[0]), "r"(b[1]));
}

// ================= CSR build =================
__global__ void zero2_kernel(int* __restrict__ a, int* __restrict__ b, int n) {
    int i = blockIdx.x * blockDim.x + threadIdx.x;
    if (i < n) { a[i] = 0; b[i] = 0; }
}
__global__ void deg_acc_kernel(const int* __restrict__ dst, int* __restrict__ deg, int E) {
    int e = blockIdx.x * blockDim.x + threadIdx.x;
    if (e < E) atomicAdd(&deg[dst[e]], 1);
}
__global__ void dinv_kernel(const int* __restrict__ deg, float* __restrict__ dinv, int n) {
    int i = blockIdx.x * blockDim.x + threadIdx.x;
    if (i < n) dinv[i] = rsqrtf((float)(deg[i] + 1));
}
__global__ void scan1_kernel(const int* __restrict__ in, int* __restrict__ out,
                             int* __restrict__ bsum, int n) {
    __shared__ int sh[256];
    int t = threadIdx.x;
    int i0 = blockIdx.x * 1024 + t * 4;
    int v[4];
#pragma unroll
    for (int k = 0; k < 4; k++) v[k] = (i0 + k < n) ? in[i0 + k] : 0;
    int s = v[0] + v[1] + v[2] + v[3];
    sh[t] = s;
    __syncthreads();
#pragma unroll
    for (int off = 1; off < 256; off <<= 1) {
        int x = (t >= off) ? sh[t - off] : 0;
        __syncthreads();
        sh[t] += x;
        __syncthreads();
    }
    int run = sh[t] - s;
#pragma unroll
    for (int k = 0; k < 4; k++) {
        if (i0 + k < n) out[i0 + k] = run;
        run += v[k];
    }
    if (t == 255) bsum[blockIdx.x] = sh[255];
}
__global__ void scan2_kernel(int* __restrict__ bsum, int nch, int* __restrict__ rowptr,
                             int n, int E) {
    if (threadIdx.x == 0) {
        int run = 0;
        for (int i = 0; i < nch; i++) { int t = bsum[i]; bsum[i] = run; run += t; }
        rowptr[n] = E;
    }
}
__global__ void scan3_kernel(int* __restrict__ rowptr, const int* __restrict__ bsum, int n) {
    int i = blockIdx.x * blockDim.x + threadIdx.x;
    if (i < n) rowptr[i] += bsum[i >> 10];
}
__global__ void fill_kernel(const int* __restrict__ src, const int* __restrict__ dst,
                            const int* __restrict__ rowptr, int* __restrict__ cnt,
                            const float* __restrict__ dinv,
                            int* __restrict__ csr_src, float* __restrict__ csr_coef, int E) {
    int e = blockIdx.x * blockDim.x + threadIdx.x;
    if (e >= E) return;
    int s = src[e], d = dst[e];
    int pos = rowptr[d] + atomicAdd(&cnt[d], 1);
    csr_src[pos]  = s;
    csr_coef[pos] = dinv[s] * dinv[d];
}

// ================= W prep (all 3 layers) =================
__global__ void wprep_all_kernel(const float* __restrict__ W1, const float* __restrict__ W2,
                                 const float* __restrict__ W3,
                                 __nv_bfloat16* __restrict__ bhi,
                                 __nv_bfloat16* __restrict__ blo) {
    int i = blockIdx.x * blockDim.x + threadIdx.x;  // [l][n][k]
    if (i >= 3 * DIM * DIM) return;
    int l = i / (DIM * DIM);
    int r = i - l * DIM * DIM;
    int n = r >> 7, k = r & 127;
    const float* W = (l == 0) ? W1 : (l == 1) ? W2 : W3;
    float w = W[k * DIM + n];
    __nv_bfloat16 hi = __float2bfloat16(w);
    __nv_bfloat16 lo = __float2bfloat16(w - __bfloat162float(hi));
    bhi[i] = hi;
    blo[i] = lo;
}

// ================= HMMA GEMM: C[M,128] = A[M,128] @ W =================
// 512 threads (16 warps), CTA tile 256x128, warp tile 32x64 (8x2 warp grid).
// bf16 hi/lo split: acc = Ahi*Whi + Ahi*Wlo + Alo*Whi.
#define TILE_M 256
#define NTHR   512
#define LDA 136           // bf16 elems per smem row (pad 8: conflict-free ldmatrix)
#define SM_AHI 0
#define SM_ALO (SM_AHI + TILE_M * LDA * 2)          // 69632
#define SM_WHI (SM_ALO + TILE_M * LDA * 2)          // 139264
#define SM_WLO (SM_WHI + DIM * LDA * 2)             // 174080
#define SM_TOT (SM_WLO + DIM * LDA * 2)             // 208896
#define LDS_STAGE 132     // floats per row for epilogue staging

__global__ __launch_bounds__(NTHR, 1)
void mma_gemm(const float* __restrict__ A,
              const __nv_bfloat16* __restrict__ Whi,   // [n][k]
              const __nv_bfloat16* __restrict__ Wlo,
              float* __restrict__ C, int M) {
    extern __shared__ char smem[];
    const uint32_t sb = smem_u32(smem);
    const int tid  = threadIdx.x;
    const int wid  = tid >> 5;
    const int lane = tid & 31;
    const int row0 = blockIdx.x * TILE_M;

    // ---- load A (fp32 -> bf16 hi/lo) into padded smem ----
    for (int i = tid; i < TILE_M * 64; i += NTHR) {
        int row = i >> 6, cp = i & 63, col = cp * 2;
        float2 v = make_float2(0.f, 0.f);
        if (row0 + row < M) v = *(const float2*)(A + (size_t)(row0 + row) * DIM + col);
        __nv_bfloat16 hx = __float2bfloat16(v.x);
        __nv_bfloat16 hy = __float2bfloat16(v.y);
        __nv_bfloat16 lx = __float2bfloat16(v.x - __bfloat162float(hx));
        __nv_bfloat16 ly = __float2bfloat16(v.y - __bfloat162float(hy));
        __nv_bfloat162 hp = __nv_bfloat162(hx, hy);
        __nv_bfloat162 lp = __nv_bfloat162(lx, ly);
        uint32_t off = (uint32_t)(row * LDA + col) * 2;
        *(uint32_t*)(smem + SM_AHI + off) = *(uint32_t*)&hp;
        *(uint32_t*)(smem + SM_ALO + off) = *(uint32_t*)&lp;
    }
    // ---- load W hi/lo (bf16 [n][k]) ----
    for (int i = tid; i < DIM * 64; i += NTHR) {
        int n = i >> 6, cp = i & 63, col = cp * 2;
        uint32_t off = (uint32_t)(n * LDA + col) * 2;
        *(uint32_t*)(smem + SM_WHI + off) = *(const uint32_t*)(Whi + (size_t)n * DIM + col);
        *(uint32_t*)(smem + SM_WLO + off) = *(const uint32_t*)(Wlo + (size_t)n * DIM + col);
    }
    __syncthreads();

    const int wr = (wid >> 1) * 32;   // warp row base: 0..224
    const int wc = (wid & 1) * 64;    // warp col base: 0/64

    float acc[2][8][4];
#pragma unroll
    for (int rt = 0; rt < 2; rt++)
#pragma unroll
        for (int j = 0; j < 8; j++)
#pragma unroll
            for (int q = 0; q < 4; q++) acc[rt][j][q] = 0.f;

    const int m  = lane >> 3;   // matrix id within ldmatrix.x4
    const int rr = lane & 7;

#pragma unroll
    for (int ks = 0; ks < 8; ks++) {
        const int k0 = ks * 16;

        // A fragments: 2 row-tiles of 16
        uint32_t ah[2][4], al[2][4];
#pragma unroll
        for (int rt = 0; rt < 2; rt++) {
            int arow = wr + rt * 16 + ((m & 1) ? 8 : 0) + rr;
            int acol = k0 + ((m >> 1) ? 8 : 0);
            uint32_t off = (uint32_t)(arow * LDA + acol) * 2;
            ldm_x4(ah[rt], sb + SM_AHI + off);
            ldm_x4(al[rt], sb + SM_ALO + off);
        }

        // B fragments in two halves of 32 cols to bound register use
#pragma unroll
        for (int jh = 0; jh < 2; jh++) {
            uint32_t bh[4][2], bl[4][2];
#pragma unroll
            for (int jp = 0; jp < 2; jp++) {
                int nrow = wc + jh * 32 + jp * 16 + ((m >> 1) ? 8 : 0) + rr;
                int kcol = k0 + ((m & 1) ? 8 : 0);
                uint32_t off = (uint32_t)(nrow * LDA + kcol) * 2;
                uint32_t r[4];
                ldm_x4(r, sb + SM_WHI + off);
                bh[jp * 2][0] = r[0]; bh[jp * 2][1] = r[1];
                bh[jp * 2 + 1][0] = r[2]; bh[jp * 2 + 1][1] = r[3];
                ldm_x4(r, sb + SM_WLO + off);
                bl[jp * 2][0] = r[0]; bl[jp * 2][1] = r[1];
                bl[jp * 2 + 1][0] = r[2]; bl[jp * 2 + 1][1] = r[3];
            }
#pragma unroll
            for (int rt = 0; rt < 2; rt++)
#pragma unroll
                for (int j4 = 0; j4 < 4; j4++) {
                    float* a4 = acc[rt][jh * 4 + j4];
                    mma_bf16(a4, ah[rt], bh[j4]);
                    mma_bf16(a4, ah[rt], bl[j4]);
                    mma_bf16(a4, al[rt], bh[j4]);
                }
        }
    }

    // ---- epilogue: fragments -> staging smem -> coalesced global ----
    __syncthreads();
    float* stage = (float*)smem;
    const int g  = lane >> 2;
    const int cq = (lane & 3) * 2;
#pragma unroll
    for (int rt = 0; rt < 2; rt++)
#pragma unroll
        for (int j = 0; j < 8; j++) {
            int row = wr + rt * 16 + g;
            int col = wc + j * 8 + cq;
            stage[row * LDS_STAGE + col]           = acc[rt][j][0];
            stage[row * LDS_STAGE + col + 1]       = acc[rt][j][1];
            stage[(row + 8) * LDS_STAGE + col]     = acc[rt][j][2];
            stage[(row + 8) * LDS_STAGE + col + 1] = acc[rt][j][3];
        }
    __syncthreads();

    for (int i = tid; i < TILE_M * 32; i += NTHR) {
        int r = i >> 5, cp = i & 31;
        if (row0 + r < M) {
            float4 v = *(float4*)(stage + r * LDS_STAGE + cp * 4);
            *(float4*)(C + (size_t)(row0 + r) * DIM + cp * 4) = v;
        }
    }
}

// ================= fused gather =================
template <bool RELU>
__global__ __launch_bounds__(256)
void gather_kernel(const float* __restrict__ h, const float* __restrict__ bias,
                   const int* __restrict__ rowptr, const int* __restrict__ csr_src,
                   const float* __restrict__ csr_coef, const float* __restrict__ dinv,
                   float* __restrict__ out, int n) {
    int warp = (blockIdx.x * blockDim.x + threadIdx.x) >> 5;
    int lane = threadIdx.x & 31;
    if (warp >= n) return;
    const int d = warp;
    const int c4 = lane * 4;

    float di = __ldg(&dinv[d]);
    float s  = di * di;
    float4 self = *(const float4*)(h + (size_t)d * DIM + c4);
    float4 bb   = *(const float4*)(bias + c4);
    float4 acc;
    acc.x = fmaf(self.x, s, bb.x);
    acc.y = fmaf(self.y, s, bb.y);
    acc.z = fmaf(self.z, s, bb.z);
    acc.w = fmaf(self.w, s, bb.w);

    int j   = __ldg(&rowptr[d]);
    int end = __ldg(&rowptr[d + 1]);

    for (; j + 1 < end; j += 2) {
        int   s0 = __ldg(&csr_src[j]);
        int   s1 = __ldg(&csr_src[j + 1]);
        float c0 = __ldg(&csr_coef[j]);
        float c1 = __ldg(&csr_coef[j + 1]);
        float4 v0 = *(const float4*)(h + (size_t)s0 * DIM + c4);
        float4 v1 = *(const float4*)(h + (size_t)s1 * DIM + c4);
        acc.x = fmaf(v0.x, c0, acc.x);
        acc.y = fmaf(v0.y, c0, acc.y);
        acc.z = fmaf(v0.z, c0, acc.z);
        acc.w = fmaf(v0.w, c0, acc.w);
        acc.x = fmaf(v1.x, c1, acc.x);
        acc.y = fmaf(v1.y, c1, acc.y);
        acc.z = fmaf(v1.z, c1, acc.z);
        acc.w = fmaf(v1.w, c1, acc.w);
    }
    if (j < end) {
        int   s0 = __ldg(&csr_src[j]);
        float c0 = __ldg(&csr_coef[j]);
        float4 v0 = *(const float4*)(h + (size_t)s0 * DIM + c4);
        acc.x = fmaf(v0.x, c0, acc.x);
        acc.y = fmaf(v0.y, c0, acc.y);
        acc.z = fmaf(v0.z, c0, acc.z);
        acc.w = fmaf(v0.w, c0, acc.w);
    }

    if (RELU) {
        acc.x = fmaxf(acc.x, 0.f);
        acc.y = fmaxf(acc.y, 0.f);
        acc.z = fmaxf(acc.z, 0.f);
        acc.w = fmaxf(acc.w, 0.f);
    }
    *(float4*)(out + (size_t)d * DIM + c4) = acc;
}

extern "C" void kernel_launch(void* const* d_in, const int* in_sizes, int n_in,
                              void* d_out, int out_size) {
    const float* x  = (const float*)d_in[0];
    const int*   ei = (const int*)d_in[1];
    const float* W1 = (const float*)d_in[2];
    const float* b1 = (const float*)d_in[3];
    const float* W2 = (const float*)d_in[4];
    const float* b2 = (const float*)d_in[5];
    const float* W3 = (const float*)d_in[6];
    const float* b3 = (const float*)d_in[7];
    float*       out = (float*)d_out;

    const int N = in_sizes[0] / DIM;
    const int E = in_sizes[1] / 2;
    const int* src = ei;
    const int* dst = ei + E;

    float *h, *agg, *dinv, *csr_coef;
    int *deg, *cnt, *rowptr, *bsum, *csr_src;
    __nv_bfloat16 *whi, *wlo;
    cudaGetSymbolAddress((void**)&h,        g_h);
    cudaGetSymbolAddress((void**)&agg,      g_agg);
    cudaGetSymbolAddress((void**)&dinv,     g_dinv);
    cudaGetSymbolAddress((void**)&deg,      g_deg);
    cudaGetSymbolAddress((void**)&cnt,      g_cnt);
    cudaGetSymbolAddress((void**)&rowptr,   g_rowptr);
    cudaGetSymbolAddress((void**)&bsum,     g_bsum);
    cudaGetSymbolAddress((void**)&csr_src,  g_csr_src);
    cudaGetSymbolAddress((void**)&csr_coef, g_csr_coef);
    cudaGetSymbolAddress((void**)&whi,      g_whi);
    cudaGetSymbolAddress((void**)&wlo,      g_wlo);

    cudaFuncSetAttribute(mma_gemm, cudaFuncAttributeMaxDynamicSharedMemorySize, SM_TOT);

    const int TB = 256;
    const int n_blk  = (N + TB - 1) / TB;
    const int e_blk  = (E + TB - 1) / TB;
    const int gemm_g = (N + TILE_M - 1) / TILE_M;
    const int nch    = (N + 1023) / 1024;
    const int gat_blk = (int)(((long)N * 32 + TB - 1) / TB);

    // Launch order chosen so mma_gemm is the 4th launch (ncu profile slot).
    wprep_all_kernel<<<192, 256>>>(W1, W2, W3, whi, wlo);                     // 1
    zero2_kernel<<<n_blk, TB>>>(deg, cnt, N);                                 // 2
    deg_acc_kernel<<<e_blk, TB>>>(dst, deg, E);                               // 3
    mma_gemm<<<gemm_g, NTHR, SM_TOT>>>(x, whi, wlo, h, N);                    // 4 (profiled)
    dinv_kernel<<<n_blk, TB>>>(deg, dinv, N);                                 // 5
    scan1_kernel<<<nch, 256>>>(deg, rowptr, bsum, N);                         // 6
    scan2_kernel<<<1, 32>>>(bsum, nch, rowptr, N, E);                         // 7
    scan3_kernel<<<n_blk, TB>>>(rowptr, bsum, N);                             // 8
    fill_kernel<<<e_blk, TB>>>(src, dst, rowptr, cnt, dinv, csr_src, csr_coef, E);  // 9

    // ---- layer 1 aggregation ----
    gather_kernel<true><<<gat_blk, TB>>>(h, b1, rowptr, csr_src, csr_coef, dinv, agg, N);
    // ---- layer 2 ----
    mma_gemm<<<gemm_g, NTHR, SM_TOT>>>(agg, whi + DIM * DIM, wlo + DIM * DIM, h, N);
    gather_kernel<true><<<gat_blk, TB>>>(h, b2, rowptr, csr_src, csr_coef, dinv, agg, N);
    // ---- layer 3 -> d_out ----
    mma_gemm<<<gemm_g, NTHR, SM_TOT>>>(agg, whi + 2 * DIM * DIM, wlo + 2 * DIM * DIM, h, N);
    gather_kernel<false><<<gat_blk, TB>>>(h, b3, rowptr, csr_src, csr_coef, dinv, out, N);
}

// round 8
// speedup vs baseline: 1.3705x; 1.0510x over previous
#include <cuda_runtime.h>
#include <cuda_bf16.h>
#include <cstdint>

#define NNODES 100000
#define EMAX   1600000
#define DIM    128

// Scratch (__device__ globals: allocation-free rule)
__device__ float g_h[(size_t)NNODES * DIM];
__device__ float g_agg[(size_t)NNODES * DIM];
__device__ float g_dinv[NNODES];
__device__ int   g_deg[NNODES];
__device__ int   g_cnt[NNODES];
__device__ int   g_rowptr[NNODES + 1];
__device__ int   g_bsum[256];
__device__ int   g_csr_src[EMAX];
__device__ float g_csr_coef[EMAX];
__device__ __nv_bfloat16 g_whi[3 * DIM * DIM];  // W^T hi: [layer][n][k]
__device__ __nv_bfloat16 g_wlo[3 * DIM * DIM];  // W^T lo

// ================= helpers =================
__device__ __forceinline__ uint32_t smem_u32(const void* p) {
    uint32_t a;
    asm("{ .reg .u64 t; cvta.to.shared.u64 t, %1; cvt.u32.u64 %0, t; }" : "=r"(a) : "l"(p));
    return a;
}
__device__ __forceinline__ void ldm_x4(uint32_t* r, uint32_t addr) {
    asm volatile("ldmatrix.sync.aligned.m8n8.x4.shared.b16 {%0,%1,%2,%3}, [%4];"
                 : "=r"(r[0]), "=r"(r[1]), "=r"(r[2]), "=r"(r[3]) : "r"(addr));
}
__device__ __forceinline__ void mma_bf16(float* c, const uint32_t* a, const uint32_t* b) {
    asm volatile(
        "mma.sync.aligned.m16n8k16.row.col.f32.bf16.bf16.f32 "
        "{%0,%1,%2,%3}, {%4,%5,%6,%7}, {%8,%9}, {%0,%1,%2,%3};"
        : "+f"(c[0]), "+f"(c[1]), "+f"(c[2]), "+f"(c[3])
        : "r"(a[0]), "r"(a[1]), "r"(a[2]), "r"(a[3]), "r"(b[0]), "r"(b[1]));
}

// ================= CSR build =================
__global__ void zero2_kernel(int* __restrict__ a, int* __restrict__ b, int n) {
    int i = blockIdx.x * blockDim.x + threadIdx.x;
    if (i < n) { a[i] = 0; b[i] = 0; }
}
__global__ void deg_acc_kernel(const int* __restrict__ dst, int* __restrict__ deg, int E) {
    int e = blockIdx.x * blockDim.x + threadIdx.x;
    if (e < E) atomicAdd(&deg[dst[e]], 1);
}
__global__ void dinv_kernel(const int* __restrict__ deg, float* __restrict__ dinv, int n) {
    int i = blockIdx.x * blockDim.x + threadIdx.x;
    if (i < n) dinv[i] = rsqrtf((float)(deg[i] + 1));
}
__global__ void scan1_kernel(const int* __restrict__ in, int* __restrict__ out,
                             int* __restrict__ bsum, int n) {
    __shared__ int sh[256];
    int t = threadIdx.x;
    int i0 = blockIdx.x * 1024 + t * 4;
    int v[4];
#pragma unroll
    for (int k = 0; k < 4; k++) v[k] = (i0 + k < n) ? in[i0 + k] : 0;
    int s = v[0] + v[1] + v[2] + v[3];
    sh[t] = s;
    __syncthreads();
#pragma unroll
    for (int off = 1; off < 256; off <<= 1) {
        int x = (t >= off) ? sh[t - off] : 0;
        __syncthreads();
        sh[t] += x;
        __syncthreads();
    }
    int run = sh[t] - s;
#pragma unroll
    for (int k = 0; k < 4; k++) {
        if (i0 + k < n) out[i0 + k] = run;
        run += v[k];
    }
    if (t == 255) bsum[blockIdx.x] = sh[255];
}
__global__ void scan2_kernel(int* __restrict__ bsum, int nch, int* __restrict__ rowptr,
                             int n, int E) {
    if (threadIdx.x == 0) {
        int run = 0;
        for (int i = 0; i < nch; i++) { int t = bsum[i]; bsum[i] = run; run += t; }
        rowptr[n] = E;
    }
}
__global__ void scan3_kernel(int* __restrict__ rowptr, const int* __restrict__ bsum, int n) {
    int i = blockIdx.x * blockDim.x + threadIdx.x;
    if (i < n) rowptr[i] += bsum[i >> 10];
}
__global__ void fill_kernel(const int* __restrict__ src, const int* __restrict__ dst,
                            const int* __restrict__ rowptr, int* __restrict__ cnt,
                            const float* __restrict__ dinv,
                            int* __restrict__ csr_src, float* __restrict__ csr_coef, int E) {
    int e = blockIdx.x * blockDim.x + threadIdx.x;
    if (e >= E) return;
    int s = src[e], d = dst[e];
    int pos = rowptr[d] + atomicAdd(&cnt[d], 1);
    csr_src[pos]  = s;
    csr_coef[pos] = dinv[s] * dinv[d];
}

// ================= W prep (all 3 layers) =================
__global__ void wprep_all_kernel(const float* __restrict__ W1, const float* __restrict__ W2,
                                 const float* __restrict__ W3,
                                 __nv_bfloat16* __restrict__ bhi,
                                 __nv_bfloat16* __restrict__ blo) {
    int i = blockIdx.x * blockDim.x + threadIdx.x;  // [l][n][k]
    if (i >= 3 * DIM * DIM) return;
    int l = i / (DIM * DIM);
    int r = i - l * DIM * DIM;
    int n = r >> 7, k = r & 127;
    const float* W = (l == 0) ? W1 : (l == 1) ? W2 : W3;
    float w = W[k * DIM + n];
    __nv_bfloat16 hi = __float2bfloat16(w);
    __nv_bfloat16 lo = __float2bfloat16(w - __bfloat162float(hi));
    bhi[i] = hi;
    blo[i] = lo;
}

// ================= HMMA GEMM: C[M,128] = A[M,128] @ W =================
// 512 threads (16 warps), CTA tile 256x128, warp tile 32x64 (8x2 warp grid).
// bf16 hi/lo split: acc = Ahi*Whi + Ahi*Wlo + Alo*Whi, term-major MMA order.
#define TILE_M 256
#define NTHR   512
#define LDA 136           // bf16 elems per smem row (pad 8: conflict-free ldmatrix)
#define SM_AHI 0
#define SM_ALO (SM_AHI + TILE_M * LDA * 2)          // 69632
#define SM_WHI (SM_ALO + TILE_M * LDA * 2)          // 139264
#define SM_WLO (SM_WHI + DIM * LDA * 2)             // 174080
#define SM_TOT (SM_WLO + DIM * LDA * 2)             // 208896
#define LDS_STAGE 132     // floats per row for epilogue staging

__global__ __launch_bounds__(NTHR, 1)
void mma_gemm(const float* __restrict__ A,
              const __nv_bfloat16* __restrict__ Whi,   // [n][k]
              const __nv_bfloat16* __restrict__ Wlo,
              float* __restrict__ C, int M) {
    extern __shared__ char smem[];
    const uint32_t sb = smem_u32(smem);
    const int tid  = threadIdx.x;
    const int wid  = tid >> 5;
    const int lane = tid & 31;
    const int row0 = blockIdx.x * TILE_M;

    // ---- load A (fp32 -> bf16 hi/lo) into padded smem ----
    for (int i = tid; i < TILE_M * 64; i += NTHR) {
        int row = i >> 6, cp = i & 63, col = cp * 2;
        float2 v = make_float2(0.f, 0.f);
        if (row0 + row < M) v = *(const float2*)(A + (size_t)(row0 + row) * DIM + col);
        __nv_bfloat16 hx = __float2bfloat16(v.x);
        __nv_bfloat16 hy = __float2bfloat16(v.y);
        __nv_bfloat16 lx = __float2bfloat16(v.x - __bfloat162float(hx));
        __nv_bfloat16 ly = __float2bfloat16(v.y - __bfloat162float(hy));
        __nv_bfloat162 hp = __nv_bfloat162(hx, hy);
        __nv_bfloat162 lp = __nv_bfloat162(lx, ly);
        uint32_t off = (uint32_t)(row * LDA + col) * 2;
        *(uint32_t*)(smem + SM_AHI + off) = *(uint32_t*)&hp;
        *(uint32_t*)(smem + SM_ALO + off) = *(uint32_t*)&lp;
    }
    // ---- load W hi/lo (bf16 [n][k]) ----
    for (int i = tid; i < DIM * 64; i += NTHR) {
        int n = i >> 6, cp = i & 63, col = cp * 2;
        uint32_t off = (uint32_t)(n * LDA + col) * 2;
        *(uint32_t*)(smem + SM_WHI + off) = *(const uint32_t*)(Whi + (size_t)n * DIM + col);
        *(uint32_t*)(smem + SM_WLO + off) = *(const uint32_t*)(Wlo + (size_t)n * DIM + col);
    }
    __syncthreads();

    const int wr = (wid >> 1) * 32;   // warp row base: 0..224
    const int wc = (wid & 1) * 64;    // warp col base: 0/64

    float acc[2][8][4];
#pragma unroll
    for (int rt = 0; rt < 2; rt++)
#pragma unroll
        for (int j = 0; j < 8; j++)
#pragma unroll
            for (int q = 0; q < 4; q++) acc[rt][j][q] = 0.f;

    const int m  = lane >> 3;   // matrix id within ldmatrix.x4
    const int rr = lane & 7;

#pragma unroll
    for (int ks = 0; ks < 8; ks++) {
        const int k0 = ks * 16;

        // A fragments: 2 row-tiles of 16
        uint32_t ah[2][4], al[2][4];
#pragma unroll
        for (int rt = 0; rt < 2; rt++) {
            int arow = wr + rt * 16 + ((m & 1) ? 8 : 0) + rr;
            int acol = k0 + ((m >> 1) ? 8 : 0);
            uint32_t off = (uint32_t)(arow * LDA + acol) * 2;
            ldm_x4(ah[rt], sb + SM_AHI + off);
            ldm_x4(al[rt], sb + SM_ALO + off);
        }

        // B fragments in two halves of 32 cols; term-major MMA issue within a half
#pragma unroll
        for (int jh = 0; jh < 2; jh++) {
            uint32_t bh[4][2], bl[4][2];
#pragma unroll
            for (int jp = 0; jp < 2; jp++) {
                int nrow = wc + jh * 32 + jp * 16 + ((m >> 1) ? 8 : 0) + rr;
                int kcol = k0 + ((m & 1) ? 8 : 0);
                uint32_t off = (uint32_t)(nrow * LDA + kcol) * 2;
                uint32_t r[4];
                ldm_x4(r, sb + SM_WHI + off);
                bh[jp * 2][0] = r[0]; bh[jp * 2][1] = r[1];
                bh[jp * 2 + 1][0] = r[2]; bh[jp * 2 + 1][1] = r[3];
                ldm_x4(r, sb + SM_WLO + off);
                bl[jp * 2][0] = r[0]; bl[jp * 2][1] = r[1];
                bl[jp * 2 + 1][0] = r[2]; bl[jp * 2 + 1][1] = r[3];
            }
            // term 1: ah * bh  (8 independent accumulators)
#pragma unroll
            for (int rt = 0; rt < 2; rt++)
#pragma unroll
                for (int j4 = 0; j4 < 4; j4++)
                    mma_bf16(acc[rt][jh * 4 + j4], ah[rt], bh[j4]);
            // term 2: ah * bl
#pragma unroll
            for (int rt = 0; rt < 2; rt++)
#pragma unroll
                for (int j4 = 0; j4 < 4; j4++)
                    mma_bf16(acc[rt][jh * 4 + j4], ah[rt], bl[j4]);
            // term 3: al * bh
#pragma unroll
            for (int rt = 0; rt < 2; rt++)
#pragma unroll
                for (int j4 = 0; j4 < 4; j4++)
                    mma_bf16(acc[rt][jh * 4 + j4], al[rt], bh[j4]);
        }
    }

    // ---- epilogue: fragments -> staging smem -> coalesced global ----
    __syncthreads();
    float* stage = (float*)smem;
    const int g  = lane >> 2;
    const int cq = (lane & 3) * 2;
#pragma unroll
    for (int rt = 0; rt < 2; rt++)
#pragma unroll
        for (int j = 0; j < 8; j++) {
            int row = wr + rt * 16 + g;
            int col = wc + j * 8 + cq;
            stage[row * LDS_STAGE + col]           = acc[rt][j][0];
            stage[row * LDS_STAGE + col + 1]       = acc[rt][j][1];
            stage[(row + 8) * LDS_STAGE + col]     = acc[rt][j][2];
            stage[(row + 8) * LDS_STAGE + col + 1] = acc[rt][j][3];
        }
    __syncthreads();

    for (int i = tid; i < TILE_M * 32; i += NTHR) {
        int r = i >> 5, cp = i & 31;
        if (row0 + r < M) {
            float4 v = *(float4*)(stage + r * LDS_STAGE + cp * 4);
            *(float4*)(C + (size_t)(row0 + r) * DIM + cp * 4) = v;
        }
    }
}

// ================= fused gather (4x unrolled neighbor loop) =================
template <bool RELU>
__global__ __launch_bounds__(256)
void gather_kernel(const float* __restrict__ h, const float* __restrict__ bias,
                   const int* __restrict__ rowptr, const int* __restrict__ csr_src,
                   const float* __restrict__ csr_coef, const float* __restrict__ dinv,
                   float* __restrict__ out, int n) {
    int warp = (blockIdx.x * blockDim.x + threadIdx.x) >> 5;
    int lane = threadIdx.x & 31;
    if (warp >= n) return;
    const int d = warp;
    const int c4 = lane * 4;

    float di = __ldg(&dinv[d]);
    float s  = di * di;
    float4 self = *(const float4*)(h + (size_t)d * DIM + c4);
    float4 bb   = *(const float4*)(bias + c4);
    float4 acc;
    acc.x = fmaf(self.x, s, bb.x);
    acc.y = fmaf(self.y, s, bb.y);
    acc.z = fmaf(self.z, s, bb.z);
    acc.w = fmaf(self.w, s, bb.w);

    int j   = __ldg(&rowptr[d]);
    int end = __ldg(&rowptr[d + 1]);

    for (; j + 3 < end; j += 4) {
        int   s0 = __ldg(&csr_src[j]);
        int   s1 = __ldg(&csr_src[j + 1]);
        int   s2 = __ldg(&csr_src[j + 2]);
        int   s3 = __ldg(&csr_src[j + 3]);
        float c0 = __ldg(&csr_coef[j]);
        float c1 = __ldg(&csr_coef[j + 1]);
        float c2 = __ldg(&csr_coef[j + 2]);
        float c3 = __ldg(&csr_coef[j + 3]);
        float4 v0 = *(const float4*)(h + (size_t)s0 * DIM + c4);
        float4 v1 = *(const float4*)(h + (size_t)s1 * DIM + c4);
        float4 v2 = *(const float4*)(h + (size_t)s2 * DIM + c4);
        float4 v3 = *(const float4*)(h + (size_t)s3 * DIM + c4);
        acc.x = fmaf(v0.x, c0, acc.x);
        acc.y = fmaf(v0.y, c0, acc.y);
        acc.z = fmaf(v0.z, c0, acc.z);
        acc.w = fmaf(v0.w, c0, acc.w);
        acc.x = fmaf(v1.x, c1, acc.x);
        acc.y = fmaf(v1.y, c1, acc.y);
        acc.z = fmaf(v1.z, c1, acc.z);
        acc.w = fmaf(v1.w, c1, acc.w);
        acc.x = fmaf(v2.x, c2, acc.x);
        acc.y = fmaf(v2.y, c2, acc.y);
        acc.z = fmaf(v2.z, c2, acc.z);
        acc.w = fmaf(v2.w, c2, acc.w);
        acc.x = fmaf(v3.x, c3, acc.x);
        acc.y = fmaf(v3.y, c3, acc.y);
        acc.z = fmaf(v3.z, c3, acc.z);
        acc.w = fmaf(v3.w, c3, acc.w);
    }
    for (; j < end; j++) {
        int   s0 = __ldg(&csr_src[j]);
        float c0 = __ldg(&csr_coef[j]);
        float4 v0 = *(const float4*)(h + (size_t)s0 * DIM + c4);
        acc.x = fmaf(v0.x, c0, acc.x);
        acc.y = fmaf(v0.y, c0, acc.y);
        acc.z = fmaf(v0.z, c0, acc.z);
        acc.w = fmaf(v0.w, c0, acc.w);
    }

    if (RELU) {
        acc.x = fmaxf(acc.x, 0.f);
        acc.y = fmaxf(acc.y, 0.f);
        acc.z = fmaxf(acc.z, 0.f);
        acc.w = fmaxf(acc.w, 0.f);
    }
    *(float4*)(out + (size_t)d * DIM + c4) = acc;
}

extern "C" void kernel_launch(void* const* d_in, const int* in_sizes, int n_in,
                              void* d_out, int out_size) {
    const float* x  = (const float*)d_in[0];
    const int*   ei = (const int*)d_in[1];
    const float* W1 = (const float*)d_in[2];
    const float* b1 = (const float*)d_in[3];
    const float* W2 = (const float*)d_in[4];
    const float* b2 = (const float*)d_in[5];
    const float* W3 = (const float*)d_in[6];
    const float* b3 = (const float*)d_in[7];
    float*       out = (float*)d_out;

    const int N = in_sizes[0] / DIM;
    const int E = in_sizes[1] / 2;
    const int* src = ei;
    const int* dst = ei + E;

    float *h, *agg, *dinv, *csr_coef;
    int *deg, *cnt, *rowptr, *bsum, *csr_src;
    __nv_bfloat16 *whi, *wlo;
    cudaGetSymbolAddress((void**)&h,        g_h);
    cudaGetSymbolAddress((void**)&agg,      g_agg);
    cudaGetSymbolAddress((void**)&dinv,     g_dinv);
    cudaGetSymbolAddress((void**)&deg,      g_deg);
    cudaGetSymbolAddress((void**)&cnt,      g_cnt);
    cudaGetSymbolAddress((void**)&rowptr,   g_rowptr);
    cudaGetSymbolAddress((void**)&bsum,     g_bsum);
    cudaGetSymbolAddress((void**)&csr_src,  g_csr_src);
    cudaGetSymbolAddress((void**)&csr_coef, g_csr_coef);
    cudaGetSymbolAddress((void**)&whi,      g_whi);
    cudaGetSymbolAddress((void**)&wlo,      g_wlo);

    cudaFuncSetAttribute(mma_gemm, cudaFuncAttributeMaxDynamicSharedMemorySize, SM_TOT);

    const int TB = 256;
    const int n_blk  = (N + TB - 1) / TB;
    const int e_blk  = (E + TB - 1) / TB;
    const int gemm_g = (N + TILE_M - 1) / TILE_M;
    const int nch    = (N + 1023) / 1024;
    const int gat_blk = (int)(((long)N * 32 + TB - 1) / TB);

    // Launch order chosen so mma_gemm is the 4th launch (ncu profile slot).
    wprep_all_kernel<<<192, 256>>>(W1, W2, W3, whi, wlo);                     // 1
    zero2_kernel<<<n_blk, TB>>>(deg, cnt, N);                                 // 2
    deg_acc_kernel<<<e_blk, TB>>>(dst, deg, E);                               // 3
    mma_gemm<<<gemm_g, NTHR, SM_TOT>>>(x, whi, wlo, h, N);                    // 4 (profiled)
    dinv_kernel<<<n_blk, TB>>>(deg, dinv, N);                                 // 5
    scan1_kernel<<<nch, 256>>>(deg, rowptr, bsum, N);                         // 6
    scan2_kernel<<<1, 32>>>(bsum, nch, rowptr, N, E);                         // 7
    scan3_kernel<<<n_blk, TB>>>(rowptr, bsum, N);                             // 8
    fill_kernel<<<e_blk, TB>>>(src, dst, rowptr, cnt, dinv, csr_src, csr_coef, E);  // 9

    // ---- layer 1 aggregation ----
    gather_kernel<true><<<gat_blk, TB>>>(h, b1, rowptr, csr_src, csr_coef, dinv, agg, N);
    // ---- layer 2 ----
    mma_gemm<<<gemm_g, NTHR, SM_TOT>>>(agg, whi + DIM * DIM, wlo + DIM * DIM, h, N);
    gather_kernel<true><<<gat_blk, TB>>>(h, b2, rowptr, csr_src, csr_coef, dinv, agg, N);
    // ---- layer 3 -> d_out ----
    mma_gemm<<<gemm_g, NTHR, SM_TOT>>>(agg, whi + 2 * DIM * DIM, wlo + 2 * DIM * DIM, h, N);
    gather_kernel<false><<<gat_blk, TB>>>(h, b3, rowptr, csr_src, csr_coef, dinv, out, N);
}

// round 9
// speedup vs baseline: 1.5356x; 1.1205x over previous
#include <cuda_runtime.h>
#include <cuda_bf16.h>
#include <cstdint>

#define NNODES 100000
#define EMAX   1600000
#define DIM    128

// Scratch (__device__ globals: allocation-free rule)
__device__ float g_h[(size_t)NNODES * DIM];
__device__ float g_agg[(size_t)NNODES * DIM];
__device__ float g_dinv[NNODES];
__device__ int   g_deg[NNODES];
__device__ int   g_cnt[NNODES];
__device__ int   g_rowptr[NNODES + 1];
__device__ int   g_bsum[256];
__device__ int   g_csr_src[EMAX];
__device__ float g_csr_coef[EMAX];
// B-fragment tables: [layer][half][ks][j][lane] -> uint2 (b0,b1 regs of mma B frag)
#define TBL_PER_LAYER (2 * 8 * 8 * 32)
__device__ uint2 g_bfrag_hi[3 * TBL_PER_LAYER];
__device__ uint2 g_bfrag_lo[3 * TBL_PER_LAYER];

// ================= helpers =================
__device__ __forceinline__ uint32_t smem_u32(const void* p) {
    uint32_t a;
    asm("{ .reg .u64 t; cvta.to.shared.u64 t, %1; cvt.u32.u64 %0, t; }" : "=r"(a) : "l"(p));
    return a;
}
__device__ __forceinline__ void ldm_x4(uint32_t* r, uint32_t addr) {
    asm volatile("ldmatrix.sync.aligned.m8n8.x4.shared.b16 {%0,%1,%2,%3}, [%4];"
                 : "=r"(r[0]), "=r"(r[1]), "=r"(r[2]), "=r"(r[3]) : "r"(addr));
}
__device__ __forceinline__ void mma_bf16(float* c, const uint32_t* a, const uint32_t* b) {
    asm volatile(
        "mma.sync.aligned.m16n8k16.row.col.f32.bf16.bf16.f32 "
        "{%0,%1,%2,%3}, {%4,%5,%6,%7}, {%8,%9}, {%0,%1,%2,%3};"
        : "+f"(c[0]), "+f"(c[1]), "+f"(c[2]), "+f"(c[3])
        : "r"(a[0]), "r"(a[1]), "r"(a[2]), "r"(a[3]), "r"(b[0]), "r"(b[1]));
}

// ================= CSR build =================
__global__ void zero2_kernel(int* __restrict__ a, int* __restrict__ b, int n) {
    int i = blockIdx.x * blockDim.x + threadIdx.x;
    if (i < n) { a[i] = 0; b[i] = 0; }
}
__global__ void deg_acc_kernel(const int* __restrict__ dst, int* __restrict__ deg, int E) {
    int e = blockIdx.x * blockDim.x + threadIdx.x;
    if (e < E) atomicAdd(&deg[dst[e]], 1);
}
__global__ void dinv_kernel(const int* __restrict__ deg, float* __restrict__ dinv, int n) {
    int i = blockIdx.x * blockDim.x + threadIdx.x;
    if (i < n) dinv[i] = rsqrtf((float)(deg[i] + 1));
}
__global__ void scan1_kernel(const int* __restrict__ in, int* __restrict__ out,
                             int* __restrict__ bsum, int n) {
    __shared__ int sh[256];
    int t = threadIdx.x;
    int i0 = blockIdx.x * 1024 + t * 4;
    int v[4];
#pragma unroll
    for (int k = 0; k < 4; k++) v[k] = (i0 + k < n) ? in[i0 + k] : 0;
    int s = v[0] + v[1] + v[2] + v[3];
    sh[t] = s;
    __syncthreads();
#pragma unroll
    for (int off = 1; off < 256; off <<= 1) {
        int x = (t >= off) ? sh[t - off] : 0;
        __syncthreads();
        sh[t] += x;
        __syncthreads();
    }
    int run = sh[t] - s;
#pragma unroll
    for (int k = 0; k < 4; k++) {
        if (i0 + k < n) out[i0 + k] = run;
        run += v[k];
    }
    if (t == 255) bsum[blockIdx.x] = sh[255];
}
__global__ void scan2_kernel(int* __restrict__ bsum, int nch, int* __restrict__ rowptr,
                             int n, int E) {
    if (threadIdx.x == 0) {
        int run = 0;
        for (int i = 0; i < nch; i++) { int t = bsum[i]; bsum[i] = run; run += t; }
        rowptr[n] = E;
    }
}
__global__ void scan3_kernel(int* __restrict__ rowptr, const int* __restrict__ bsum, int n) {
    int i = blockIdx.x * blockDim.x + threadIdx.x;
    if (i < n) rowptr[i] += bsum[i >> 10];
}
__global__ void fill_kernel(const int* __restrict__ src, const int* __restrict__ dst,
                            const int* __restrict__ rowptr, int* __restrict__ cnt,
                            const float* __restrict__ dinv,
                            int* __restrict__ csr_src, float* __restrict__ csr_coef, int E) {
    int e = blockIdx.x * blockDim.x + threadIdx.x;
    if (e >= E) return;
    int s = src[e], d = dst[e];
    int pos = rowptr[d] + atomicAdd(&cnt[d], 1);
    csr_src[pos]  = s;
    csr_coef[pos] = dinv[s] * dinv[d];
}

// ================= W prep: precompute mma B-fragment tables (hi/lo split) =================
// Entry (l,half,ks,j,lane): b0 = pack(Wt[n][k],Wt[n][k+1]), b1 = pack(Wt[n][k+8],Wt[n][k+9])
// where n = half*64 + j*8 + lane/4, k = ks*16 + (lane%4)*2, Wt[n][k] = W[k][n].
__global__ void wprep_all_kernel(const float* __restrict__ W1, const float* __restrict__ W2,
                                 const float* __restrict__ W3,
                                 uint2* __restrict__ thi, uint2* __restrict__ tlo) {
    int i = blockIdx.x * blockDim.x + threadIdx.x;
    if (i >= 3 * TBL_PER_LAYER) return;
    int lane = i & 31;
    int j    = (i >> 5) & 7;
    int ks   = (i >> 8) & 7;
    int half = (i >> 11) & 1;
    int l    = i >> 12;
    const float* W = (l == 0) ? W1 : (l == 1) ? W2 : W3;
    int n = half * 64 + j * 8 + (lane >> 2);
    int k = ks * 16 + (lane & 3) * 2;
    float w00 = W[(size_t)k * DIM + n];
    float w01 = W[(size_t)(k + 1) * DIM + n];
    float w10 = W[(size_t)(k + 8) * DIM + n];
    float w11 = W[(size_t)(k + 9) * DIM + n];
    __nv_bfloat16 h00 = __float2bfloat16(w00), h01 = __float2bfloat16(w01);
    __nv_bfloat16 h10 = __float2bfloat16(w10), h11 = __float2bfloat16(w11);
    __nv_bfloat162 b0h = __nv_bfloat162(h00, h01);
    __nv_bfloat162 b1h = __nv_bfloat162(h10, h11);
    __nv_bfloat162 b0l = __nv_bfloat162(__float2bfloat16(w00 - __bfloat162float(h00)),
                                        __float2bfloat16(w01 - __bfloat162float(h01)));
    __nv_bfloat162 b1l = __nv_bfloat162(__float2bfloat16(w10 - __bfloat162float(h10)),
                                        __float2bfloat16(w11 - __bfloat162float(h11)));
    thi[i] = make_uint2(*(uint32_t*)&b0h, *(uint32_t*)&b1h);
    tlo[i] = make_uint2(*(uint32_t*)&b0l, *(uint32_t*)&b1l);
}

// ================= HMMA GEMM: C[M,128] = A[M,128] @ W =================
// 256 threads (8 warps), CTA tile 128x128, warp tile 32x64 (4x2 warp grid).
// A in smem (hi/lo, ldmatrix); B fragments straight from global tables (L2-resident).
// 2 CTAs/SM: load/convert of one CTA overlaps MMA of the other.
#define TILE_M 128
#define NTHR   256
#define LDA 136           // bf16 elems per smem row (pad 8: conflict-free ldmatrix)
#define SM_AHI 0
#define SM_ALO (SM_AHI + TILE_M * LDA * 2)          // 34816
#define SM_TOT (SM_ALO + TILE_M * LDA * 2)          // 69632
#define LDS_STAGE 132     // floats per row for epilogue staging (128*132*4 = 67584 <= 69632)

__global__ __launch_bounds__(NTHR, 2)
void mma_gemm(const float* __restrict__ A,
              const uint2* __restrict__ Thi,   // per-layer B-frag table (hi)
              const uint2* __restrict__ Tlo,   // (lo)
              float* __restrict__ C, int M) {
    extern __shared__ char smem[];
    const uint32_t sb = smem_u32(smem);
    const int tid  = threadIdx.x;
    const int wid  = tid >> 5;
    const int lane = tid & 31;
    const int row0 = blockIdx.x * TILE_M;

    // ---- load A (fp32 -> bf16 hi/lo) into padded smem ----
    for (int i = tid; i < TILE_M * 64; i += NTHR) {
        int row = i >> 6, cp = i & 63, col = cp * 2;
        float2 v = make_float2(0.f, 0.f);
        if (row0 + row < M) v = *(const float2*)(A + (size_t)(row0 + row) * DIM + col);
        __nv_bfloat16 hx = __float2bfloat16(v.x);
        __nv_bfloat16 hy = __float2bfloat16(v.y);
        __nv_bfloat16 lx = __float2bfloat16(v.x - __bfloat162float(hx));
        __nv_bfloat16 ly = __float2bfloat16(v.y - __bfloat162float(hy));
        __nv_bfloat162 hp = __nv_bfloat162(hx, hy);
        __nv_bfloat162 lp = __nv_bfloat162(lx, ly);
        uint32_t off = (uint32_t)(row * LDA + col) * 2;
        *(uint32_t*)(smem + SM_AHI + off) = *(uint32_t*)&hp;
        *(uint32_t*)(smem + SM_ALO + off) = *(uint32_t*)&lp;
    }
    __syncthreads();

    const int wr   = (wid >> 1) * 32;   // warp row base: 0/32/64/96
    const int half = wid & 1;           // warp col half: 0 -> cols 0-63, 1 -> 64-127
    const int wc   = half * 64;

    float acc[2][8][4];
#pragma unroll
    for (int rt = 0; rt < 2; rt++)
#pragma unroll
        for (int j = 0; j < 8; j++)
#pragma unroll
            for (int q = 0; q < 4; q++) acc[rt][j][q] = 0.f;

    const int m  = lane >> 3;   // matrix id within ldmatrix.x4
    const int rr = lane & 7;

#pragma unroll
    for (int ks = 0; ks < 8; ks++) {
        const int k0 = ks * 16;

        // A fragments: 2 row-tiles of 16
        uint32_t ah[2][4], al[2][4];
#pragma unroll
        for (int rt = 0; rt < 2; rt++) {
            int arow = wr + rt * 16 + ((m & 1) ? 8 : 0) + rr;
            int acol = k0 + ((m >> 1) ? 8 : 0);
            uint32_t off = (uint32_t)(arow * LDA + acol) * 2;
            ldm_x4(ah[rt], sb + SM_AHI + off);
            ldm_x4(al[rt], sb + SM_ALO + off);
        }

        // B fragments from global tables, coalesced LDG.64 per j
        const uint2* ph = Thi + ((size_t)(half * 8 + ks) * 8) * 32 + lane;
        const uint2* pl = Tlo + ((size_t)(half * 8 + ks) * 8) * 32 + lane;
#pragma unroll
        for (int jh = 0; jh < 2; jh++) {
            uint32_t bh[4][2], bl[4][2];
#pragma unroll
            for (int j4 = 0; j4 < 4; j4++) {
                uint2 vh = __ldg(ph + (jh * 4 + j4) * 32);
                uint2 vl = __ldg(pl + (jh * 4 + j4) * 32);
                bh[j4][0] = vh.x; bh[j4][1] = vh.y;
                bl[j4][0] = vl.x; bl[j4][1] = vl.y;
            }
            // term-major: 8 independent accs per term
#pragma unroll
            for (int rt = 0; rt < 2; rt++)
#pragma unroll
                for (int j4 = 0; j4 < 4; j4++)
                    mma_bf16(acc[rt][jh * 4 + j4], ah[rt], bh[j4]);
#pragma unroll
            for (int rt = 0; rt < 2; rt++)
#pragma unroll
                for (int j4 = 0; j4 < 4; j4++)
                    mma_bf16(acc[rt][jh * 4 + j4], ah[rt], bl[j4]);
#pragma unroll
            for (int rt = 0; rt < 2; rt++)
#pragma unroll
                for (int j4 = 0; j4 < 4; j4++)
                    mma_bf16(acc[rt][jh * 4 + j4], al[rt], bh[j4]);
        }
    }

    // ---- epilogue: fragments -> staging smem (reuses A region) -> coalesced global ----
    __syncthreads();
    float* stage = (float*)smem;
    const int g  = lane >> 2;
    const int cq = (lane & 3) * 2;
#pragma unroll
    for (int rt = 0; rt < 2; rt++)
#pragma unroll
        for (int j = 0; j < 8; j++) {
            int row = wr + rt * 16 + g;
            int col = wc + j * 8 + cq;
            stage[row * LDS_STAGE + col]           = acc[rt][j][0];
            stage[row * LDS_STAGE + col + 1]       = acc[rt][j][1];
            stage[(row + 8) * LDS_STAGE + col]     = acc[rt][j][2];
            stage[(row + 8) * LDS_STAGE + col + 1] = acc[rt][j][3];
        }
    __syncthreads();

    for (int i = tid; i < TILE_M * 32; i += NTHR) {
        int r = i >> 5, cp = i & 31;
        if (row0 + r < M) {
            float4 v = *(float4*)(stage + r * LDS_STAGE + cp * 4);
            *(float4*)(C + (size_t)(row0 + r) * DIM + cp * 4) = v;
        }
    }
}

// ================= fused gather (4x unrolled neighbor loop) =================
template <bool RELU>
__global__ __launch_bounds__(256)
void gather_kernel(const float* __restrict__ h, const float* __restrict__ bias,
                   const int* __restrict__ rowptr, const int* __restrict__ csr_src,
                   const float* __restrict__ csr_coef, const float* __restrict__ dinv,
                   float* __restrict__ out, int n) {
    int warp = (blockIdx.x * blockDim.x + threadIdx.x) >> 5;
    int lane = threadIdx.x & 31;
    if (warp >= n) return;
    const int d = warp;
    const int c4 = lane * 4;

    float di = __ldg(&dinv[d]);
    float s  = di * di;
    float4 self = *(const float4*)(h + (size_t)d * DIM + c4);
    float4 bb   = *(const float4*)(bias + c4);
    float4 acc;
    acc.x = fmaf(self.x, s, bb.x);
    acc.y = fmaf(self.y, s, bb.y);
    acc.z = fmaf(self.z, s, bb.z);
    acc.w = fmaf(self.w, s, bb.w);

    int j   = __ldg(&rowptr[d]);
    int end = __ldg(&rowptr[d + 1]);

    for (; j + 3 < end; j += 4) {
        int   s0 = __ldg(&csr_src[j]);
        int   s1 = __ldg(&csr_src[j + 1]);
        int   s2 = __ldg(&csr_src[j + 2]);
        int   s3 = __ldg(&csr_src[j + 3]);
        float c0 = __ldg(&csr_coef[j]);
        float c1 = __ldg(&csr_coef[j + 1]);
        float c2 = __ldg(&csr_coef[j + 2]);
        float c3 = __ldg(&csr_coef[j + 3]);
        float4 v0 = *(const float4*)(h + (size_t)s0 * DIM + c4);
        float4 v1 = *(const float4*)(h + (size_t)s1 * DIM + c4);
        float4 v2 = *(const float4*)(h + (size_t)s2 * DIM + c4);
        float4 v3 = *(const float4*)(h + (size_t)s3 * DIM + c4);
        acc.x = fmaf(v0.x, c0, acc.x);
        acc.y = fmaf(v0.y, c0, acc.y);
        acc.z = fmaf(v0.z, c0, acc.z);
        acc.w = fmaf(v0.w, c0, acc.w);
        acc.x = fmaf(v1.x, c1, acc.x);
        acc.y = fmaf(v1.y, c1, acc.y);
        acc.z = fmaf(v1.z, c1, acc.z);
        acc.w = fmaf(v1.w, c1, acc.w);
        acc.x = fmaf(v2.x, c2, acc.x);
        acc.y = fmaf(v2.y, c2, acc.y);
        acc.z = fmaf(v2.z, c2, acc.z);
        acc.w = fmaf(v2.w, c2, acc.w);
        acc.x = fmaf(v3.x, c3, acc.x);
        acc.y = fmaf(v3.y, c3, acc.y);
        acc.z = fmaf(v3.z, c3, acc.z);
        acc.w = fmaf(v3.w, c3, acc.w);
    }
    for (; j < end; j++) {
        int   s0 = __ldg(&csr_src[j]);
        float c0 = __ldg(&csr_coef[j]);
        float4 v0 = *(const float4*)(h + (size_t)s0 * DIM + c4);
        acc.x = fmaf(v0.x, c0, acc.x);
        acc.y = fmaf(v0.y, c0, acc.y);
        acc.z = fmaf(v0.z, c0, acc.z);
        acc.w = fmaf(v0.w, c0, acc.w);
    }

    if (RELU) {
        acc.x = fmaxf(acc.x, 0.f);
        acc.y = fmaxf(acc.y, 0.f);
        acc.z = fmaxf(acc.z, 0.f);
        acc.w = fmaxf(acc.w, 0.f);
    }
    *(float4*)(out + (size_t)d * DIM + c4) = acc;
}

extern "C" void kernel_launch(void* const* d_in, const int* in_sizes, int n_in,
                              void* d_out, int out_size) {
    const float* x  = (const float*)d_in[0];
    const int*   ei = (const int*)d_in[1];
    const float* W1 = (const float*)d_in[2];
    const float* b1 = (const float*)d_in[3];
    const float* W2 = (const float*)d_in[4];
    const float* b2 = (const float*)d_in[5];
    const float* W3 = (const float*)d_in[6];
    const float* b3 = (const float*)d_in[7];
    float*       out = (float*)d_out;

    const int N = in_sizes[0] / DIM;
    const int E = in_sizes[1] / 2;
    const int* src = ei;
    const int* dst = ei + E;

    float *h, *agg, *dinv, *csr_coef;
    int *deg, *cnt, *rowptr, *bsum, *csr_src;
    uint2 *thi, *tlo;
    cudaGetSymbolAddress((void**)&h,        g_h);
    cudaGetSymbolAddress((void**)&agg,      g_agg);
    cudaGetSymbolAddress((void**)&dinv,     g_dinv);
    cudaGetSymbolAddress((void**)&deg,      g_deg);
    cudaGetSymbolAddress((void**)&cnt,      g_cnt);
    cudaGetSymbolAddress((void**)&rowptr,   g_rowptr);
    cudaGetSymbolAddress((void**)&bsum,     g_bsum);
    cudaGetSymbolAddress((void**)&csr_src,  g_csr_src);
    cudaGetSymbolAddress((void**)&csr_coef, g_csr_coef);
    cudaGetSymbolAddress((void**)&thi,      g_bfrag_hi);
    cudaGetSymbolAddress((void**)&tlo,      g_bfrag_lo);

    cudaFuncSetAttribute(mma_gemm, cudaFuncAttributeMaxDynamicSharedMemorySize, SM_TOT);

    const int TB = 256;
    const int n_blk  = (N + TB - 1) / TB;
    const int e_blk  = (E + TB - 1) / TB;
    const int gemm_g = (N + TILE_M - 1) / TILE_M;
    const int nch    = (N + 1023) / 1024;
    const int gat_blk = (int)(((long)N * 32 + TB - 1) / TB);

    // Launch order chosen so mma_gemm is the 4th launch (ncu profile slot).
    wprep_all_kernel<<<(3 * TBL_PER_LAYER + 255) / 256, 256>>>(W1, W2, W3, thi, tlo);  // 1
    zero2_kernel<<<n_blk, TB>>>(deg, cnt, N);                                 // 2
    deg_acc_kernel<<<e_blk, TB>>>(dst, deg, E);                               // 3
    mma_gemm<<<gemm_g, NTHR, SM_TOT>>>(x, thi, tlo, h, N);                    // 4 (profiled)
    dinv_kernel<<<n_blk, TB>>>(deg, dinv, N);                                 // 5
    scan1_kernel<<<nch, 256>>>(deg, rowptr, bsum, N);                         // 6
    scan2_kernel<<<1, 32>>>(bsum, nch, rowptr, N, E);                         // 7
    scan3_kernel<<<n_blk, TB>>>(rowptr, bsum, N);                             // 8
    fill_kernel<<<e_blk, TB>>>(src, dst, rowptr, cnt, dinv, csr_src, csr_coef, E);  // 9

    // ---- layer 1 aggregation ----
    gather_kernel<true><<<gat_blk, TB>>>(h, b1, rowptr, csr_src, csr_coef, dinv, agg, N);
    // ---- layer 2 ----
    mma_gemm<<<gemm_g, NTHR, SM_TOT>>>(agg, thi + TBL_PER_LAYER, tlo + TBL_PER_LAYER, h, N);
    gather_kernel<true><<<gat_blk, TB>>>(h, b2, rowptr, csr_src, csr_coef, dinv, agg, N);
    // ---- layer 3 -> d_out ----
    mma_gemm<<<gemm_g, NTHR, SM_TOT>>>(agg, thi + 2 * TBL_PER_LAYER, tlo + 2 * TBL_PER_LAYER, h, N);
    gather_kernel<false><<<gat_blk, TB>>>(h, b3, rowptr, csr_src, csr_coef, dinv, out, N);
}

// round 10
// speedup vs baseline: 1.6602x; 1.0811x over previous
#include <cuda_runtime.h>
#include <cuda_bf16.h>
#include <cstdint>

#define NNODES 100000
#define EMAX   1600000
#define DIM    128

// Scratch (__device__ globals: allocation-free rule)
__device__ float g_h[(size_t)NNODES * DIM];        // GEMM output (fp32, gather input)
__device__ __nv_bfloat16 g_ahi[(size_t)NNODES * DIM];  // activation hi plane (GEMM input)
__device__ __nv_bfloat16 g_alo[(size_t)NNODES * DIM];  // activation lo plane
__device__ float g_dinv[NNODES];
__device__ int   g_deg[NNODES];
__device__ int   g_cnt[NNODES];
__device__ int   g_rowptr[NNODES + 1];
__device__ int   g_bsum[256];
__device__ int   g_csr_src[EMAX];
// B-fragment tables: [layer][half][ks][j][lane] -> uint2 (b0,b1 regs of mma B frag)
#define TBL_PER_LAYER (2 * 8 * 8 * 32)
__device__ uint2 g_bfrag_hi[3 * TBL_PER_LAYER];
__device__ uint2 g_bfrag_lo[3 * TBL_PER_LAYER];

// ================= helpers =================
__device__ __forceinline__ uint32_t smem_u32(const void* p) {
    uint32_t a;
    asm("{ .reg .u64 t; cvta.to.shared.u64 t, %1; cvt.u32.u64 %0, t; }" : "=r"(a) : "l"(p));
    return a;
}
__device__ __forceinline__ void ldm_x4(uint32_t* r, uint32_t addr) {
    asm volatile("ldmatrix.sync.aligned.m8n8.x4.shared.b16 {%0,%1,%2,%3}, [%4];"
                 : "=r"(r[0]), "=r"(r[1]), "=r"(r[2]), "=r"(r[3]) : "r"(addr));
}
__device__ __forceinline__ void mma_bf16(float* c, const uint32_t* a, const uint32_t* b) {
    asm volatile(
        "mma.sync.aligned.m16n8k16.row.col.f32.bf16.bf16.f32 "
        "{%0,%1,%2,%3}, {%4,%5,%6,%7}, {%8,%9}, {%0,%1,%2,%3};"
        : "+f"(c[0]), "+f"(c[1]), "+f"(c[2]), "+f"(c[3])
        : "r"(a[0]), "r"(a[1]), "r"(a[2]), "r"(a[3]), "r"(b[0]), "r"(b[1]));
}
__device__ __forceinline__ void cp_async16(uint32_t saddr, const void* gptr) {
    asm volatile("cp.async.cg.shared.global [%0], [%1], 16;"
                 :: "r"(saddr), "l"(gptr) : "memory");
}
__device__ __forceinline__ void cp_async_wait_all() {
    asm volatile("cp.async.commit_group;" ::: "memory");
    asm volatile("cp.async.wait_group 0;" ::: "memory");
}

// ================= prep: zero deg/cnt + W frag tables + x -> hi/lo planes =================
__global__ void prep_kernel(const float* __restrict__ W1, const float* __restrict__ W2,
                            const float* __restrict__ W3,
                            uint2* __restrict__ thi, uint2* __restrict__ tlo,
                            const float* __restrict__ x,
                            __nv_bfloat16* __restrict__ xhi, __nv_bfloat16* __restrict__ xlo,
                            int* __restrict__ deg, int* __restrict__ cnt, int n) {
    int i = blockIdx.x * blockDim.x + threadIdx.x;
    if (i < n) { deg[i] = 0; cnt[i] = 0; }
    if (i < 3 * TBL_PER_LAYER) {
        int lane = i & 31;
        int j    = (i >> 5) & 7;
        int ks   = (i >> 8) & 7;
        int half = (i >> 11) & 1;
        int l    = i >> 12;
        const float* W = (l == 0) ? W1 : (l == 1) ? W2 : W3;
        int nn = half * 64 + j * 8 + (lane >> 2);
        int k  = ks * 16 + (lane & 3) * 2;
        float w00 = W[(size_t)k * DIM + nn];
        float w01 = W[(size_t)(k + 1) * DIM + nn];
        float w10 = W[(size_t)(k + 8) * DIM + nn];
        float w11 = W[(size_t)(k + 9) * DIM + nn];
        __nv_bfloat16 h00 = __float2bfloat16(w00), h01 = __float2bfloat16(w01);
        __nv_bfloat16 h10 = __float2bfloat16(w10), h11 = __float2bfloat16(w11);
        __nv_bfloat162 b0h = __nv_bfloat162(h00, h01);
        __nv_bfloat162 b1h = __nv_bfloat162(h10, h11);
        __nv_bfloat162 b0l = __nv_bfloat162(__float2bfloat16(w00 - __bfloat162float(h00)),
                                            __float2bfloat16(w01 - __bfloat162float(h01)));
        __nv_bfloat162 b1l = __nv_bfloat162(__float2bfloat16(w10 - __bfloat162float(h10)),
                                            __float2bfloat16(w11 - __bfloat162float(h11)));
        thi[i] = make_uint2(*(uint32_t*)&b0h, *(uint32_t*)&b1h);
        tlo[i] = make_uint2(*(uint32_t*)&b0l, *(uint32_t*)&b1l);
    }
    // x -> hi/lo planes, float2 granules
    long tot = (long)n * 64;
    for (long j = i; j < tot; j += (long)gridDim.x * blockDim.x) {
        float2 v = *(const float2*)(x + j * 2);
        __nv_bfloat16 hx = __float2bfloat16(v.x);
        __nv_bfloat16 hy = __float2bfloat16(v.y);
        __nv_bfloat162 hp = __nv_bfloat162(hx, hy);
        __nv_bfloat162 lp = __nv_bfloat162(__float2bfloat16(v.x - __bfloat162float(hx)),
                                           __float2bfloat16(v.y - __bfloat162float(hy)));
        *(uint32_t*)(xhi + j * 2) = *(uint32_t*)&hp;
        *(uint32_t*)(xlo + j * 2) = *(uint32_t*)&lp;
    }
}

// ================= CSR build =================
__global__ void deg_acc_kernel(const int* __restrict__ dst, int* __restrict__ deg, int E) {
    int e = blockIdx.x * blockDim.x + threadIdx.x;
    if (e < E) atomicAdd(&deg[dst[e]], 1);
}
__global__ void dinv_kernel(const int* __restrict__ deg, float* __restrict__ dinv, int n) {
    int i = blockIdx.x * blockDim.x + threadIdx.x;
    if (i < n) dinv[i] = rsqrtf((float)(deg[i] + 1));
}
__global__ void scan1_kernel(const int* __restrict__ in, int* __restrict__ out,
                             int* __restrict__ bsum, int n) {
    __shared__ int sh[256];
    int t = threadIdx.x;
    int i0 = blockIdx.x * 1024 + t * 4;
    int v[4];
#pragma unroll
    for (int k = 0; k < 4; k++) v[k] = (i0 + k < n) ? in[i0 + k] : 0;
    int s = v[0] + v[1] + v[2] + v[3];
    sh[t] = s;
    __syncthreads();
#pragma unroll
    for (int off = 1; off < 256; off <<= 1) {
        int x = (t >= off) ? sh[t - off] : 0;
        __syncthreads();
        sh[t] += x;
        __syncthreads();
    }
    int run = sh[t] - s;
#pragma unroll
    for (int k = 0; k < 4; k++) {
        if (i0 + k < n) out[i0 + k] = run;
        run += v[k];
    }
    if (t == 255) bsum[blockIdx.x] = sh[255];
}
__global__ void scan2_kernel(int* __restrict__ bsum, int nch, int* __restrict__ rowptr,
                             int n, int E) {
    if (threadIdx.x == 0) {
        int run = 0;
        for (int i = 0; i < nch; i++) { int t = bsum[i]; bsum[i] = run; run += t; }
        rowptr[n] = E;
    }
}
__global__ void scan3_kernel(int* __restrict__ rowptr, const int* __restrict__ bsum, int n) {
    int i = blockIdx.x * blockDim.x + threadIdx.x;
    if (i < n) rowptr[i] += bsum[i >> 10];
}
__global__ void fill_kernel(const int* __restrict__ src, const int* __restrict__ dst,
                            const int* __restrict__ rowptr, int* __restrict__ cnt,
                            int* __restrict__ csr_src, int E) {
    int e = blockIdx.x * blockDim.x + threadIdx.x;
    if (e >= E) return;
    int s = src[e], d = dst[e];
    int pos = rowptr[d] + atomicAdd(&cnt[d], 1);
    csr_src[pos] = s;
}

// ================= HMMA GEMM: C[M,128] = A[M,128] @ W =================
// A pre-split into bf16 hi/lo planes; cp.async into padded smem; B frags from global tables.
// 256 threads (8 warps), CTA tile 128x128, warp tile 32x64; 2 CTAs/SM.
#define TILE_M 128
#define NTHR   256
#define LDA 136           // bf16 elems per smem row (pad 8: conflict-free ldmatrix)
#define LDAB (LDA * 2)    // 272 bytes per smem row
#define SM_AHI 0
#define SM_ALO (SM_AHI + TILE_M * LDAB)             // 34816
#define SM_TOT (SM_ALO + TILE_M * LDAB)             // 69632
#define LDS_STAGE 132     // floats per row for epilogue staging (128*132*4 = 67584 <= 69632)

__global__ __launch_bounds__(NTHR, 2)
void mma_gemm(const __nv_bfloat16* __restrict__ Ahi,
              const __nv_bfloat16* __restrict__ Alo,
              const uint2* __restrict__ Thi,
              const uint2* __restrict__ Tlo,
              float* __restrict__ C, int M) {
    extern __shared__ char smem[];
    const uint32_t sb = smem_u32(smem);
    const int tid  = threadIdx.x;
    const int wid  = tid >> 5;
    const int lane = tid & 31;
    const int row0 = blockIdx.x * TILE_M;

    // ---- async copy A planes into padded smem (16B chunks) ----
    {
        const char* gh = (const char*)(Ahi + (size_t)row0 * DIM);
        const char* gl = (const char*)(Alo + (size_t)row0 * DIM);
        for (int i = tid; i < TILE_M * 16; i += NTHR) {
            int row = i >> 4, c = (i & 15) * 16;
            if (row0 + row < M) {
                uint32_t so = (uint32_t)(row * LDAB + c);
                cp_async16(sb + SM_AHI + so, gh + row * 256 + c);
                cp_async16(sb + SM_ALO + so, gl + row * 256 + c);
            }
        }
        cp_async_wait_all();
    }
    __syncthreads();

    const int wr   = (wid >> 1) * 32;   // warp row base: 0/32/64/96
    const int half = wid & 1;           // warp col half
    const int wc   = half * 64;

    float acc[2][8][4];
#pragma unroll
    for (int rt = 0; rt < 2; rt++)
#pragma unroll
        for (int j = 0; j < 8; j++)
#pragma unroll
            for (int q = 0; q < 4; q++) acc[rt][j][q] = 0.f;

    const int m  = lane >> 3;
    const int rr = lane & 7;

#pragma unroll
    for (int ks = 0; ks < 8; ks++) {
        const int k0 = ks * 16;

        // A fragments: 2 row-tiles of 16
        uint32_t ah[2][4], al[2][4];
#pragma unroll
        for (int rt = 0; rt < 2; rt++) {
            int arow = wr + rt * 16 + ((m & 1) ? 8 : 0) + rr;
            int acol = k0 + ((m >> 1) ? 8 : 0);
            uint32_t off = (uint32_t)(arow * LDA + acol) * 2;
            ldm_x4(ah[rt], sb + SM_AHI + off);
            ldm_x4(al[rt], sb + SM_ALO + off);
        }

        // B fragments from global tables (L1/L2-hot), coalesced LDG.64 per j
        const uint2* ph = Thi + ((size_t)(half * 8 + ks) * 8) * 32 + lane;
        const uint2* pl = Tlo + ((size_t)(half * 8 + ks) * 8) * 32 + lane;
#pragma unroll
        for (int jh = 0; jh < 2; jh++) {
            uint32_t bh[4][2], bl[4][2];
#pragma unroll
            for (int j4 = 0; j4 < 4; j4++) {
                uint2 vh = __ldg(ph + (jh * 4 + j4) * 32);
                uint2 vl = __ldg(pl + (jh * 4 + j4) * 32);
                bh[j4][0] = vh.x; bh[j4][1] = vh.y;
                bl[j4][0] = vl.x; bl[j4][1] = vl.y;
            }
#pragma unroll
            for (int rt = 0; rt < 2; rt++)
#pragma unroll
                for (int j4 = 0; j4 < 4; j4++)
                    mma_bf16(acc[rt][jh * 4 + j4], ah[rt], bh[j4]);
#pragma unroll
            for (int rt = 0; rt < 2; rt++)
#pragma unroll
                for (int j4 = 0; j4 < 4; j4++)
                    mma_bf16(acc[rt][jh * 4 + j4], ah[rt], bl[j4]);
#pragma unroll
            for (int rt = 0; rt < 2; rt++)
#pragma unroll
                for (int j4 = 0; j4 < 4; j4++)
                    mma_bf16(acc[rt][jh * 4 + j4], al[rt], bh[j4]);
        }
    }

    // ---- epilogue: fragments -> staging smem -> coalesced global ----
    __syncthreads();
    float* stage = (float*)smem;
    const int g  = lane >> 2;
    const int cq = (lane & 3) * 2;
#pragma unroll
    for (int rt = 0; rt < 2; rt++)
#pragma unroll
        for (int j = 0; j < 8; j++) {
            int row = wr + rt * 16 + g;
            int col = wc + j * 8 + cq;
            stage[row * LDS_STAGE + col]           = acc[rt][j][0];
            stage[row * LDS_STAGE + col + 1]       = acc[rt][j][1];
            stage[(row + 8) * LDS_STAGE + col]     = acc[rt][j][2];
            stage[(row + 8) * LDS_STAGE + col + 1] = acc[rt][j][3];
        }
    __syncthreads();

    for (int i = tid; i < TILE_M * 32; i += NTHR) {
        int r = i >> 5, cp = i & 31;
        if (row0 + r < M) {
            float4 v = *(float4*)(stage + r * LDS_STAGE + cp * 4);
            *(float4*)(C + (size_t)(row0 + r) * DIM + cp * 4) = v;
        }
    }
}

// ================= fused gather =================
// BF16OUT: write relu(acc) as bf16 hi/lo planes (next GEMM's input).
// else: write fp32 (final output).
template <bool RELU, bool BF16OUT>
__global__ __launch_bounds__(256)
void gather_kernel(const float* __restrict__ h, const float* __restrict__ bias,
                   const int* __restrict__ rowptr, const int* __restrict__ csr_src,
                   const float* __restrict__ dinv,
                   float* __restrict__ outf,
                   __nv_bfloat16* __restrict__ ohi, __nv_bfloat16* __restrict__ olo,
                   int n) {
    int warp = (blockIdx.x * blockDim.x + threadIdx.x) >> 5;
    int lane = threadIdx.x & 31;
    if (warp >= n) return;
    const int d = warp;
    const int c4 = lane * 4;

    float di = __ldg(&dinv[d]);
    float s  = di * di;
    float4 self = *(const float4*)(h + (size_t)d * DIM + c4);
    float4 bb   = *(const float4*)(bias + c4);
    float4 acc;
    acc.x = fmaf(self.x, s, bb.x);
    acc.y = fmaf(self.y, s, bb.y);
    acc.z = fmaf(self.z, s, bb.z);
    acc.w = fmaf(self.w, s, bb.w);

    int j   = __ldg(&rowptr[d]);
    int end = __ldg(&rowptr[d + 1]);

    for (; j + 3 < end; j += 4) {
        int   s0 = __ldg(&csr_src[j]);
        int   s1 = __ldg(&csr_src[j + 1]);
        int   s2 = __ldg(&csr_src[j + 2]);
        int   s3 = __ldg(&csr_src[j + 3]);
        float c0 = __ldg(&dinv[s0]) * di;
        float c1 = __ldg(&dinv[s1]) * di;
        float c2 = __ldg(&dinv[s2]) * di;
        float c3 = __ldg(&dinv[s3]) * di;
        float4 v0 = *(const float4*)(h + (size_t)s0 * DIM + c4);
        float4 v1 = *(const float4*)(h + (size_t)s1 * DIM + c4);
        float4 v2 = *(const float4*)(h + (size_t)s2 * DIM + c4);
        float4 v3 = *(const float4*)(h + (size_t)s3 * DIM + c4);
        acc.x = fmaf(v0.x, c0, acc.x);
        acc.y = fmaf(v0.y, c0, acc.y);
        acc.z = fmaf(v0.z, c0, acc.z);
        acc.w = fmaf(v0.w, c0, acc.w);
        acc.x = fmaf(v1.x, c1, acc.x);
        acc.y = fmaf(v1.y, c1, acc.y);
        acc.z = fmaf(v1.z, c1, acc.z);
        acc.w = fmaf(v1.w, c1, acc.w);
        acc.x = fmaf(v2.x, c2, acc.x);
        acc.y = fmaf(v2.y, c2, acc.y);
        acc.z = fmaf(v2.z, c2, acc.z);
        acc.w = fmaf(v2.w, c2, acc.w);
        acc.x = fmaf(v3.x, c3, acc.x);
        acc.y = fmaf(v3.y, c3, acc.y);
        acc.z = fmaf(v3.z, c3, acc.z);
        acc.w = fmaf(v3.w, c3, acc.w);
    }
    for (; j < end; j++) {
        int   s0 = __ldg(&csr_src[j]);
        float c0 = __ldg(&dinv[s0]) * di;
        float4 v0 = *(const float4*)(h + (size_t)s0 * DIM + c4);
        acc.x = fmaf(v0.x, c0, acc.x);
        acc.y = fmaf(v0.y, c0, acc.y);
        acc.z = fmaf(v0.z, c0, acc.z);
        acc.w = fmaf(v0.w, c0, acc.w);
    }

    if (RELU) {
        acc.x = fmaxf(acc.x, 0.f);
        acc.y = fmaxf(acc.y, 0.f);
        acc.z = fmaxf(acc.z, 0.f);
        acc.w = fmaxf(acc.w, 0.f);
    }

    if (BF16OUT) {
        __nv_bfloat16 h0 = __float2bfloat16(acc.x);
        __nv_bfloat16 h1 = __float2bfloat16(acc.y);
        __nv_bfloat16 h2 = __float2bfloat16(acc.z);
        __nv_bfloat16 h3 = __float2bfloat16(acc.w);
        __nv_bfloat162 hp0 = __nv_bfloat162(h0, h1);
        __nv_bfloat162 hp1 = __nv_bfloat162(h2, h3);
        __nv_bfloat162 lp0 = __nv_bfloat162(__float2bfloat16(acc.x - __bfloat162float(h0)),
                                            __float2bfloat16(acc.y - __bfloat162float(h1)));
        __nv_bfloat162 lp1 = __nv_bfloat162(__float2bfloat16(acc.z - __bfloat162float(h2)),
                                            __float2bfloat16(acc.w - __bfloat162float(h3)));
        *(uint2*)(ohi + (size_t)d * DIM + c4) = make_uint2(*(uint32_t*)&hp0, *(uint32_t*)&hp1);
        *(uint2*)(olo + (size_t)d * DIM + c4) = make_uint2(*(uint32_t*)&lp0, *(uint32_t*)&lp1);
    } else {
        *(float4*)(outf + (size_t)d * DIM + c4) = acc;
    }
}

extern "C" void kernel_launch(void* const* d_in, const int* in_sizes, int n_in,
                              void* d_out, int out_size) {
    const float* x  = (const float*)d_in[0];
    const int*   ei = (const int*)d_in[1];
    const float* W1 = (const float*)d_in[2];
    const float* b1 = (const float*)d_in[3];
    const float* W2 = (const float*)d_in[4];
    const float* b2 = (const float*)d_in[5];
    const float* W3 = (const float*)d_in[6];
    const float* b3 = (const float*)d_in[7];
    float*       out = (float*)d_out;

    const int N = in_sizes[0] / DIM;
    const int E = in_sizes[1] / 2;
    const int* src = ei;
    const int* dst = ei + E;

    float *h, *dinv;
    __nv_bfloat16 *ahi, *alo;
    int *deg, *cnt, *rowptr, *bsum, *csr_src;
    uint2 *thi, *tlo;
    cudaGetSymbolAddress((void**)&h,       g_h);
    cudaGetSymbolAddress((void**)&ahi,     g_ahi);
    cudaGetSymbolAddress((void**)&alo,     g_alo);
    cudaGetSymbolAddress((void**)&dinv,    g_dinv);
    cudaGetSymbolAddress((void**)&deg,     g_deg);
    cudaGetSymbolAddress((void**)&cnt,     g_cnt);
    cudaGetSymbolAddress((void**)&rowptr,  g_rowptr);
    cudaGetSymbolAddress((void**)&bsum,    g_bsum);
    cudaGetSymbolAddress((void**)&csr_src, g_csr_src);
    cudaGetSymbolAddress((void**)&thi,     g_bfrag_hi);
    cudaGetSymbolAddress((void**)&tlo,     g_bfrag_lo);

    cudaFuncSetAttribute(mma_gemm, cudaFuncAttributeMaxDynamicSharedMemorySize, SM_TOT);

    const int TB = 256;
    const int n_blk  = (N + TB - 1) / TB;
    const int e_blk  = (E + TB - 1) / TB;
    const int gemm_g = (N + TILE_M - 1) / TILE_M;
    const int nch    = (N + 1023) / 1024;
    const int gat_blk = (int)(((long)N * 32 + TB - 1) / TB);

    // 1: prep (zero deg/cnt + W frag tables + x -> planes)
    prep_kernel<<<8192, TB>>>(W1, W2, W3, thi, tlo, x, ahi, alo, deg, cnt, N);
    // 2-3: degrees
    deg_acc_kernel<<<e_blk, TB>>>(dst, deg, E);
    dinv_kernel<<<n_blk, TB>>>(deg, dinv, N);
    // 4 (profiled): layer-1 GEMM from x planes
    mma_gemm<<<gemm_g, NTHR, SM_TOT>>>(ahi, alo, thi, tlo, h, N);
    // 5-8: CSR
    scan1_kernel<<<nch, 256>>>(deg, rowptr, bsum, N);
    scan2_kernel<<<1, 32>>>(bsum, nch, rowptr, N, E);
    scan3_kernel<<<n_blk, TB>>>(rowptr, bsum, N);
    fill_kernel<<<e_blk, TB>>>(src, dst, rowptr, cnt, csr_src, E);

    // layer 1 aggregation -> planes (overwrites x planes, safe: GEMM1 done)
    gather_kernel<true, true><<<gat_blk, TB>>>(h, b1, rowptr, csr_src, dinv,
                                               nullptr, ahi, alo, N);
    // layer 2
    mma_gemm<<<gemm_g, NTHR, SM_TOT>>>(ahi, alo, thi + TBL_PER_LAYER, tlo + TBL_PER_LAYER, h, N);
    gather_kernel<true, true><<<gat_blk, TB>>>(h, b2, rowptr, csr_src, dinv,
                                               nullptr, ahi, alo, N);
    // layer 3 -> d_out (fp32)
    mma_gemm<<<gemm_g, NTHR, SM_TOT>>>(ahi, alo, thi + 2 * TBL_PER_LAYER, tlo + 2 * TBL_PER_LAYER, h, N);
    gather_kernel<false, false><<<gat_blk, TB>>>(h, b3, rowptr, csr_src, dinv,
                                                 out, nullptr, nullptr, N);
}

// round 11
// speedup vs baseline: 1.8732x; 1.1283x over previous
#include <cuda_runtime.h>
#include <cuda_bf16.h>
#include <cuda_fp16.h>
#include <cstdint>

#define NNODES 100000
#define EMAX   1600000
#define DIM    128

// Scratch (__device__ globals: allocation-free rule)
__device__ __half g_h[(size_t)NNODES * DIM];            // GEMM output (fp16, gather input)
__device__ __nv_bfloat16 g_ahi[(size_t)NNODES * DIM];   // activation hi plane (GEMM input)
__device__ __nv_bfloat16 g_alo[(size_t)NNODES * DIM];   // activation lo plane
__device__ float g_dinv[NNODES];
__device__ int   g_deg[NNODES];
__device__ int   g_cnt[NNODES];
__device__ int   g_rowptr[NNODES + 1];
__device__ int   g_bsum[256];
__device__ int   g_csr_src[EMAX];
// B-fragment tables: [layer][half][ks][j][lane] -> uint2 (b0,b1 regs of mma B frag)
#define TBL_PER_LAYER (2 * 8 * 8 * 32)
__device__ uint2 g_bfrag_hi[3 * TBL_PER_LAYER];
__device__ uint2 g_bfrag_lo[3 * TBL_PER_LAYER];

// ================= helpers =================
__device__ __forceinline__ uint32_t smem_u32(const void* p) {
    uint32_t a;
    asm("{ .reg .u64 t; cvta.to.shared.u64 t, %1; cvt.u32.u64 %0, t; }" : "=r"(a) : "l"(p));
    return a;
}
__device__ __forceinline__ void ldm_x4(uint32_t* r, uint32_t addr) {
    asm volatile("ldmatrix.sync.aligned.m8n8.x4.shared.b16 {%0,%1,%2,%3}, [%4];"
                 : "=r"(r[0]), "=r"(r[1]), "=r"(r[2]), "=r"(r[3]) : "r"(addr));
}
__device__ __forceinline__ void mma_bf16(float* c, const uint32_t* a, const uint32_t* b) {
    asm volatile(
        "mma.sync.aligned.m16n8k16.row.col.f32.bf16.bf16.f32 "
        "{%0,%1,%2,%3}, {%4,%5,%6,%7}, {%8,%9}, {%0,%1,%2,%3};"
        : "+f"(c[0]), "+f"(c[1]), "+f"(c[2]), "+f"(c[3])
        : "r"(a[0]), "r"(a[1]), "r"(a[2]), "r"(a[3]), "r"(b[0]), "r"(b[1]));
}
__device__ __forceinline__ void cp_async16(uint32_t saddr, const void* gptr) {
    asm volatile("cp.async.cg.shared.global [%0], [%1], 16;"
                 :: "r"(saddr), "l"(gptr) : "memory");
}
__device__ __forceinline__ void cp_async_wait_all() {
    asm volatile("cp.async.commit_group;" ::: "memory");
    asm volatile("cp.async.wait_group 0;" ::: "memory");
}

// ================= prep: zero deg/cnt + W frag tables + x -> hi/lo planes =================
__global__ void prep_kernel(const float* __restrict__ W1, const float* __restrict__ W2,
                            const float* __restrict__ W3,
                            uint2* __restrict__ thi, uint2* __restrict__ tlo,
                            const float* __restrict__ x,
                            __nv_bfloat16* __restrict__ xhi, __nv_bfloat16* __restrict__ xlo,
                            int* __restrict__ deg, int* __restrict__ cnt, int n) {
    int i = blockIdx.x * blockDim.x + threadIdx.x;
    if (i < n) { deg[i] = 0; cnt[i] = 0; }
    if (i < 3 * TBL_PER_LAYER) {
        int lane = i & 31;
        int j    = (i >> 5) & 7;
        int ks   = (i >> 8) & 7;
        int half = (i >> 11) & 1;
        int l    = i >> 12;
        const float* W = (l == 0) ? W1 : (l == 1) ? W2 : W3;
        int nn = half * 64 + j * 8 + (lane >> 2);
        int k  = ks * 16 + (lane & 3) * 2;
        float w00 = W[(size_t)k * DIM + nn];
        float w01 = W[(size_t)(k + 1) * DIM + nn];
        float w10 = W[(size_t)(k + 8) * DIM + nn];
        float w11 = W[(size_t)(k + 9) * DIM + nn];
        __nv_bfloat16 h00 = __float2bfloat16(w00), h01 = __float2bfloat16(w01);
        __nv_bfloat16 h10 = __float2bfloat16(w10), h11 = __float2bfloat16(w11);
        __nv_bfloat162 b0h = __nv_bfloat162(h00, h01);
        __nv_bfloat162 b1h = __nv_bfloat162(h10, h11);
        __nv_bfloat162 b0l = __nv_bfloat162(__float2bfloat16(w00 - __bfloat162float(h00)),
                                            __float2bfloat16(w01 - __bfloat162float(h01)));
        __nv_bfloat162 b1l = __nv_bfloat162(__float2bfloat16(w10 - __bfloat162float(h10)),
                                            __float2bfloat16(w11 - __bfloat162float(h11)));
        thi[i] = make_uint2(*(uint32_t*)&b0h, *(uint32_t*)&b1h);
        tlo[i] = make_uint2(*(uint32_t*)&b0l, *(uint32_t*)&b1l);
    }
    // x -> hi/lo planes, float2 granules
    long tot = (long)n * 64;
    for (long j = i; j < tot; j += (long)gridDim.x * blockDim.x) {
        float2 v = *(const float2*)(x + j * 2);
        __nv_bfloat16 hx = __float2bfloat16(v.x);
        __nv_bfloat16 hy = __float2bfloat16(v.y);
        __nv_bfloat162 hp = __nv_bfloat162(hx, hy);
        __nv_bfloat162 lp = __nv_bfloat162(__float2bfloat16(v.x - __bfloat162float(hx)),
                                           __float2bfloat16(v.y - __bfloat162float(hy)));
        *(uint32_t*)(xhi + j * 2) = *(uint32_t*)&hp;
        *(uint32_t*)(xlo + j * 2) = *(uint32_t*)&lp;
    }
}

// ================= CSR build =================
__global__ void deg_acc_kernel(const int* __restrict__ dst, int* __restrict__ deg, int E) {
    int e = blockIdx.x * blockDim.x + threadIdx.x;
    if (e < E) atomicAdd(&deg[dst[e]], 1);
}
__global__ void dinv_kernel(const int* __restrict__ deg, float* __restrict__ dinv, int n) {
    int i = blockIdx.x * blockDim.x + threadIdx.x;
    if (i < n) dinv[i] = rsqrtf((float)(deg[i] + 1));
}
__global__ void scan1_kernel(const int* __restrict__ in, int* __restrict__ out,
                             int* __restrict__ bsum, int n) {
    __shared__ int sh[256];
    int t = threadIdx.x;
    int i0 = blockIdx.x * 1024 + t * 4;
    int v[4];
#pragma unroll
    for (int k = 0; k < 4; k++) v[k] = (i0 + k < n) ? in[i0 + k] : 0;
    int s = v[0] + v[1] + v[2] + v[3];
    sh[t] = s;
    __syncthreads();
#pragma unroll
    for (int off = 1; off < 256; off <<= 1) {
        int x = (t >= off) ? sh[t - off] : 0;
        __syncthreads();
        sh[t] += x;
        __syncthreads();
    }
    int run = sh[t] - s;
#pragma unroll
    for (int k = 0; k < 4; k++) {
        if (i0 + k < n) out[i0 + k] = run;
        run += v[k];
    }
    if (t == 255) bsum[blockIdx.x] = sh[255];
}
__global__ void scan2_kernel(int* __restrict__ bsum, int nch, int* __restrict__ rowptr,
                             int n, int E) {
    if (threadIdx.x == 0) {
        int run = 0;
        for (int i = 0; i < nch; i++) { int t = bsum[i]; bsum[i] = run; run += t; }
        rowptr[n] = E;
    }
}
__global__ void scan3_kernel(int* __restrict__ rowptr, const int* __restrict__ bsum, int n) {
    int i = blockIdx.x * blockDim.x + threadIdx.x;
    if (i < n) rowptr[i] += bsum[i >> 10];
}
__global__ void fill_kernel(const int* __restrict__ src, const int* __restrict__ dst,
                            const int* __restrict__ rowptr, int* __restrict__ cnt,
                            int* __restrict__ csr_src, int E) {
    int e = blockIdx.x * blockDim.x + threadIdx.x;
    if (e >= E) return;
    int s = src[e], d = dst[e];
    int pos = rowptr[d] + atomicAdd(&cnt[d], 1);
    csr_src[pos] = s;
}

// ================= HMMA GEMM: C[M,128] = A[M,128] @ W, fp16 output =================
#define TILE_M 128
#define NTHR   256
#define LDA 136           // bf16 elems per smem row (pad 8: conflict-free ldmatrix)
#define LDAB (LDA * 2)    // 272 bytes per smem row
#define SM_AHI 0
#define SM_ALO (SM_AHI + TILE_M * LDAB)             // 34816
#define SM_TOT (SM_ALO + TILE_M * LDAB)             // 69632
#define LDS_STAGE 132     // floats per row for epilogue staging

__global__ __launch_bounds__(NTHR, 2)
void mma_gemm(const __nv_bfloat16* __restrict__ Ahi,
              const __nv_bfloat16* __restrict__ Alo,
              const uint2* __restrict__ Thi,
              const uint2* __restrict__ Tlo,
              __half* __restrict__ C, int M) {
    extern __shared__ char smem[];
    const uint32_t sb = smem_u32(smem);
    const int tid  = threadIdx.x;
    const int wid  = tid >> 5;
    const int lane = tid & 31;
    const int row0 = blockIdx.x * TILE_M;

    // ---- async copy A planes into padded smem (16B chunks) ----
    {
        const char* gh = (const char*)(Ahi + (size_t)row0 * DIM);
        const char* gl = (const char*)(Alo + (size_t)row0 * DIM);
        for (int i = tid; i < TILE_M * 16; i += NTHR) {
            int row = i >> 4, c = (i & 15) * 16;
            if (row0 + row < M) {
                uint32_t so = (uint32_t)(row * LDAB + c);
                cp_async16(sb + SM_AHI + so, gh + row * 256 + c);
                cp_async16(sb + SM_ALO + so, gl + row * 256 + c);
            }
        }
        cp_async_wait_all();
    }
    __syncthreads();

    const int wr   = (wid >> 1) * 32;
    const int half = wid & 1;
    const int wc   = half * 64;

    float acc[2][8][4];
#pragma unroll
    for (int rt = 0; rt < 2; rt++)
#pragma unroll
        for (int j = 0; j < 8; j++)
#pragma unroll
            for (int q = 0; q < 4; q++) acc[rt][j][q] = 0.f;

    const int m  = lane >> 3;
    const int rr = lane & 7;

#pragma unroll
    for (int ks = 0; ks < 8; ks++) {
        const int k0 = ks * 16;

        uint32_t ah[2][4], al[2][4];
#pragma unroll
        for (int rt = 0; rt < 2; rt++) {
            int arow = wr + rt * 16 + ((m & 1) ? 8 : 0) + rr;
            int acol = k0 + ((m >> 1) ? 8 : 0);
            uint32_t off = (uint32_t)(arow * LDA + acol) * 2;
            ldm_x4(ah[rt], sb + SM_AHI + off);
            ldm_x4(al[rt], sb + SM_ALO + off);
        }

        const uint2* ph = Thi + ((size_t)(half * 8 + ks) * 8) * 32 + lane;
        const uint2* pl = Tlo + ((size_t)(half * 8 + ks) * 8) * 32 + lane;
#pragma unroll
        for (int jh = 0; jh < 2; jh++) {
            uint32_t bh[4][2], bl[4][2];
#pragma unroll
            for (int j4 = 0; j4 < 4; j4++) {
                uint2 vh = __ldg(ph + (jh * 4 + j4) * 32);
                uint2 vl = __ldg(pl + (jh * 4 + j4) * 32);
                bh[j4][0] = vh.x; bh[j4][1] = vh.y;
                bl[j4][0] = vl.x; bl[j4][1] = vl.y;
            }
#pragma unroll
            for (int rt = 0; rt < 2; rt++)
#pragma unroll
                for (int j4 = 0; j4 < 4; j4++)
                    mma_bf16(acc[rt][jh * 4 + j4], ah[rt], bh[j4]);
#pragma unroll
            for (int rt = 0; rt < 2; rt++)
#pragma unroll
                for (int j4 = 0; j4 < 4; j4++)
                    mma_bf16(acc[rt][jh * 4 + j4], ah[rt], bl[j4]);
#pragma unroll
            for (int rt = 0; rt < 2; rt++)
#pragma unroll
                for (int j4 = 0; j4 < 4; j4++)
                    mma_bf16(acc[rt][jh * 4 + j4], al[rt], bh[j4]);
        }
    }

    // ---- epilogue: fragments -> staging smem -> coalesced fp16 global ----
    __syncthreads();
    float* stage = (float*)smem;
    const int g  = lane >> 2;
    const int cq = (lane & 3) * 2;
#pragma unroll
    for (int rt = 0; rt < 2; rt++)
#pragma unroll
        for (int j = 0; j < 8; j++) {
            int row = wr + rt * 16 + g;
            int col = wc + j * 8 + cq;
            stage[row * LDS_STAGE + col]           = acc[rt][j][0];
            stage[row * LDS_STAGE + col + 1]       = acc[rt][j][1];
            stage[(row + 8) * LDS_STAGE + col]     = acc[rt][j][2];
            stage[(row + 8) * LDS_STAGE + col + 1] = acc[rt][j][3];
        }
    __syncthreads();

    for (int i = tid; i < TILE_M * 32; i += NTHR) {
        int r = i >> 5, cp = i & 31;
        if (row0 + r < M) {
            float4 v = *(float4*)(stage + r * LDS_STAGE + cp * 4);
            __half2 h0 = __float22half2_rn(make_float2(v.x, v.y));
            __half2 h1 = __float22half2_rn(make_float2(v.z, v.w));
            *(uint2*)(C + (size_t)(row0 + r) * DIM + cp * 4) =
                make_uint2(*(uint32_t*)&h0, *(uint32_t*)&h1);
        }
    }
}

// ================= fused gather (fp16 h, fp32 accumulate) =================
__device__ __forceinline__ float4 h4_to_f4(uint2 u) {
    float2 f0 = __half22float2(*(__half2*)&u.x);
    float2 f1 = __half22float2(*(__half2*)&u.y);
    return make_float4(f0.x, f0.y, f1.x, f1.y);
}

template <bool RELU, bool BF16OUT>
__global__ __launch_bounds__(256)
void gather_kernel(const __half* __restrict__ h, const float* __restrict__ bias,
                   const int* __restrict__ rowptr, const int* __restrict__ csr_src,
                   const float* __restrict__ dinv,
                   float* __restrict__ outf,
                   __nv_bfloat16* __restrict__ ohi, __nv_bfloat16* __restrict__ olo,
                   int n) {
    int warp = (blockIdx.x * blockDim.x + threadIdx.x) >> 5;
    int lane = threadIdx.x & 31;
    if (warp >= n) return;
    const int d = warp;
    const int c4 = lane * 4;

    float di = __ldg(&dinv[d]);
    float s  = di * di;
    float4 self = h4_to_f4(*(const uint2*)(h + (size_t)d * DIM + c4));
    float4 bb   = *(const float4*)(bias + c4);
    float4 acc;
    acc.x = fmaf(self.x, s, bb.x);
    acc.y = fmaf(self.y, s, bb.y);
    acc.z = fmaf(self.z, s, bb.z);
    acc.w = fmaf(self.w, s, bb.w);

    int j   = __ldg(&rowptr[d]);
    int end = __ldg(&rowptr[d + 1]);

    for (; j + 3 < end; j += 4) {
        int   s0 = __ldg(&csr_src[j]);
        int   s1 = __ldg(&csr_src[j + 1]);
        int   s2 = __ldg(&csr_src[j + 2]);
        int   s3 = __ldg(&csr_src[j + 3]);
        float c0 = __ldg(&dinv[s0]) * di;
        float c1 = __ldg(&dinv[s1]) * di;
        float c2 = __ldg(&dinv[s2]) * di;
        float c3 = __ldg(&dinv[s3]) * di;
        uint2 u0 = *(const uint2*)(h + (size_t)s0 * DIM + c4);
        uint2 u1 = *(const uint2*)(h + (size_t)s1 * DIM + c4);
        uint2 u2 = *(const uint2*)(h + (size_t)s2 * DIM + c4);
        uint2 u3 = *(const uint2*)(h + (size_t)s3 * DIM + c4);
        float4 v0 = h4_to_f4(u0);
        float4 v1 = h4_to_f4(u1);
        float4 v2 = h4_to_f4(u2);
        float4 v3 = h4_to_f4(u3);
        acc.x = fmaf(v0.x, c0, acc.x);
        acc.y = fmaf(v0.y, c0, acc.y);
        acc.z = fmaf(v0.z, c0, acc.z);
        acc.w = fmaf(v0.w, c0, acc.w);
        acc.x = fmaf(v1.x, c1, acc.x);
        acc.y = fmaf(v1.y, c1, acc.y);
        acc.z = fmaf(v1.z, c1, acc.z);
        acc.w = fmaf(v1.w, c1, acc.w);
        acc.x = fmaf(v2.x, c2, acc.x);
        acc.y = fmaf(v2.y, c2, acc.y);
        acc.z = fmaf(v2.z, c2, acc.z);
        acc.w = fmaf(v2.w, c2, acc.w);
        acc.x = fmaf(v3.x, c3, acc.x);
        acc.y = fmaf(v3.y, c3, acc.y);
        acc.z = fmaf(v3.z, c3, acc.z);
        acc.w = fmaf(v3.w, c3, acc.w);
    }
    for (; j < end; j++) {
        int   s0 = __ldg(&csr_src[j]);
        float c0 = __ldg(&dinv[s0]) * di;
        float4 v0 = h4_to_f4(*(const uint2*)(h + (size_t)s0 * DIM + c4));
        acc.x = fmaf(v0.x, c0, acc.x);
        acc.y = fmaf(v0.y, c0, acc.y);
        acc.z = fmaf(v0.z, c0, acc.z);
        acc.w = fmaf(v0.w, c0, acc.w);
    }

    if (RELU) {
        acc.x = fmaxf(acc.x, 0.f);
        acc.y = fmaxf(acc.y, 0.f);
        acc.z = fmaxf(acc.z, 0.f);
        acc.w = fmaxf(acc.w, 0.f);
    }

    if (BF16OUT) {
        __nv_bfloat16 h0 = __float2bfloat16(acc.x);
        __nv_bfloat16 h1 = __float2bfloat16(acc.y);
        __nv_bfloat16 h2 = __float2bfloat16(acc.z);
        __nv_bfloat16 h3 = __float2bfloat16(acc.w);
        __nv_bfloat162 hp0 = __nv_bfloat162(h0, h1);
        __nv_bfloat162 hp1 = __nv_bfloat162(h2, h3);
        __nv_bfloat162 lp0 = __nv_bfloat162(__float2bfloat16(acc.x - __bfloat162float(h0)),
                                            __float2bfloat16(acc.y - __bfloat162float(h1)));
        __nv_bfloat162 lp1 = __nv_bfloat162(__float2bfloat16(acc.z - __bfloat162float(h2)),
                                            __float2bfloat16(acc.w - __bfloat162float(h3)));
        *(uint2*)(ohi + (size_t)d * DIM + c4) = make_uint2(*(uint32_t*)&hp0, *(uint32_t*)&hp1);
        *(uint2*)(olo + (size_t)d * DIM + c4) = make_uint2(*(uint32_t*)&lp0, *(uint32_t*)&lp1);
    } else {
        *(float4*)(outf + (size_t)d * DIM + c4) = acc;
    }
}

extern "C" void kernel_launch(void* const* d_in, const int* in_sizes, int n_in,
                              void* d_out, int out_size) {
    const float* x  = (const float*)d_in[0];
    const int*   ei = (const int*)d_in[1];
    const float* W1 = (const float*)d_in[2];
    const float* b1 = (const float*)d_in[3];
    const float* W2 = (const float*)d_in[4];
    const float* b2 = (const float*)d_in[5];
    const float* W3 = (const float*)d_in[6];
    const float* b3 = (const float*)d_in[7];
    float*       out = (float*)d_out;

    const int N = in_sizes[0] / DIM;
    const int E = in_sizes[1] / 2;
    const int* src = ei;
    const int* dst = ei + E;

    __half* h;
    float* dinv;
    __nv_bfloat16 *ahi, *alo;
    int *deg, *cnt, *rowptr, *bsum, *csr_src;
    uint2 *thi, *tlo;
    cudaGetSymbolAddress((void**)&h,       g_h);
    cudaGetSymbolAddress((void**)&ahi,     g_ahi);
    cudaGetSymbolAddress((void**)&alo,     g_alo);
    cudaGetSymbolAddress((void**)&dinv,    g_dinv);
    cudaGetSymbolAddress((void**)&deg,     g_deg);
    cudaGetSymbolAddress((void**)&cnt,     g_cnt);
    cudaGetSymbolAddress((void**)&rowptr,  g_rowptr);
    cudaGetSymbolAddress((void**)&bsum,    g_bsum);
    cudaGetSymbolAddress((void**)&csr_src, g_csr_src);
    cudaGetSymbolAddress((void**)&thi,     g_bfrag_hi);
    cudaGetSymbolAddress((void**)&tlo,     g_bfrag_lo);

    cudaFuncSetAttribute(mma_gemm, cudaFuncAttributeMaxDynamicSharedMemorySize, SM_TOT);

    const int TB = 256;
    const int n_blk  = (N + TB - 1) / TB;
    const int e_blk  = (E + TB - 1) / TB;
    const int gemm_g = (N + TILE_M - 1) / TILE_M;
    const int nch    = (N + 1023) / 1024;
    const int gat_blk = (int)(((long)N * 32 + TB - 1) / TB);

    // 1: prep (zero deg/cnt + W frag tables + x -> planes)
    prep_kernel<<<8192, TB>>>(W1, W2, W3, thi, tlo, x, ahi, alo, deg, cnt, N);
    // 2-3: degrees
    deg_acc_kernel<<<e_blk, TB>>>(dst, deg, E);
    dinv_kernel<<<n_blk, TB>>>(deg, dinv, N);
    // 4 (profiled): layer-1 GEMM from x planes
    mma_gemm<<<gemm_g, NTHR, SM_TOT>>>(ahi, alo, thi, tlo, h, N);
    // 5-8: CSR
    scan1_kernel<<<nch, 256>>>(deg, rowptr, bsum, N);
    scan2_kernel<<<1, 32>>>(bsum, nch, rowptr, N, E);
    scan3_kernel<<<n_blk, TB>>>(rowptr, bsum, N);
    fill_kernel<<<e_blk, TB>>>(src, dst, rowptr, cnt, csr_src, E);

    // layer 1 aggregation -> planes
    gather_kernel<true, true><<<gat_blk, TB>>>(h, b1, rowptr, csr_src, dinv,
                                               nullptr, ahi, alo, N);
    // layer 2
    mma_gemm<<<gemm_g, NTHR, SM_TOT>>>(ahi, alo, thi + TBL_PER_LAYER, tlo + TBL_PER_LAYER, h, N);
    gather_kernel<true, true><<<gat_blk, TB>>>(h, b2, rowptr, csr_src, dinv,
                                               nullptr, ahi, alo, N);
    // layer 3 -> d_out (fp32)
    mma_gemm<<<gemm_g, NTHR, SM_TOT>>>(ahi, alo, thi + 2 * TBL_PER_LAYER, tlo + 2 * TBL_PER_LAYER, h, N);
    gather_kernel<false, false><<<gat_blk, TB>>>(h, b3, rowptr, csr_src, dinv,
                                                 out, nullptr, nullptr, N);
}

// round 12
// speedup vs baseline: 2.1110x; 1.1270x over previous
#include <cuda_runtime.h>
#include <cuda_bf16.h>
#include <cuda_fp16.h>
#include <cstdint>

#define NNODES 100000
#define EMAX   1600000
#define DIM    128

// Scratch (__device__ globals: allocation-free rule)
__device__ __half g_h[(size_t)NNODES * DIM];   // GEMM output (fp16, gather input)
__device__ __half g_a[(size_t)NNODES * DIM];   // activation plane (fp16, GEMM input)
__device__ float g_dinv[NNODES];
__device__ int   g_deg[NNODES];
__device__ int   g_cnt[NNODES];
__device__ int   g_rowptr[NNODES + 1];
__device__ int   g_bsum[256];
__device__ int   g_csr_src[EMAX];
// B-fragment tables: [layer][half][ks][j][lane] -> uint2 (b0,b1 regs of mma B frag), fp16
#define TBL_PER_LAYER (2 * 8 * 8 * 32)
__device__ uint2 g_bfrag_hi[3 * TBL_PER_LAYER];
__device__ uint2 g_bfrag_lo[3 * TBL_PER_LAYER];

// ================= helpers =================
__device__ __forceinline__ uint32_t smem_u32(const void* p) {
    uint32_t a;
    asm("{ .reg .u64 t; cvta.to.shared.u64 t, %1; cvt.u32.u64 %0, t; }" : "=r"(a) : "l"(p));
    return a;
}
__device__ __forceinline__ void ldm_x4(uint32_t* r, uint32_t addr) {
    asm volatile("ldmatrix.sync.aligned.m8n8.x4.shared.b16 {%0,%1,%2,%3}, [%4];"
                 : "=r"(r[0]), "=r"(r[1]), "=r"(r[2]), "=r"(r[3]) : "r"(addr));
}
__device__ __forceinline__ void mma_f16(float* c, const uint32_t* a, const uint32_t* b) {
    asm volatile(
        "mma.sync.aligned.m16n8k16.row.col.f32.f16.f16.f32 "
        "{%0,%1,%2,%3}, {%4,%5,%6,%7}, {%8,%9}, {%0,%1,%2,%3};"
        : "+f"(c[0]), "+f"(c[1]), "+f"(c[2]), "+f"(c[3])
        : "r"(a[0]), "r"(a[1]), "r"(a[2]), "r"(a[3]), "r"(b[0]), "r"(b[1]));
}
__device__ __forceinline__ void cp_async16(uint32_t saddr, const void* gptr) {
    asm volatile("cp.async.cg.shared.global [%0], [%1], 16;"
                 :: "r"(saddr), "l"(gptr) : "memory");
}
__device__ __forceinline__ void cp_async_wait_all() {
    asm volatile("cp.async.commit_group;" ::: "memory");
    asm volatile("cp.async.wait_group 0;" ::: "memory");
}

// ================= prep: zero deg/cnt + W frag tables (fp16 hi/lo) + x -> fp16 plane =================
__global__ void prep_kernel(const float* __restrict__ W1, const float* __restrict__ W2,
                            const float* __restrict__ W3,
                            uint2* __restrict__ thi, uint2* __restrict__ tlo,
                            const float* __restrict__ x, __half* __restrict__ xa,
                            int* __restrict__ deg, int* __restrict__ cnt, int n) {
    int i = blockIdx.x * blockDim.x + threadIdx.x;
    if (i < n) { deg[i] = 0; cnt[i] = 0; }
    if (i < 3 * TBL_PER_LAYER) {
        int lane = i & 31;
        int j    = (i >> 5) & 7;
        int ks   = (i >> 8) & 7;
        int half = (i >> 11) & 1;
        int l    = i >> 12;
        const float* W = (l == 0) ? W1 : (l == 1) ? W2 : W3;
        int nn = half * 64 + j * 8 + (lane >> 2);
        int k  = ks * 16 + (lane & 3) * 2;
        float w00 = W[(size_t)k * DIM + nn];
        float w01 = W[(size_t)(k + 1) * DIM + nn];
        float w10 = W[(size_t)(k + 8) * DIM + nn];
        float w11 = W[(size_t)(k + 9) * DIM + nn];
        __half h00 = __float2half_rn(w00), h01 = __float2half_rn(w01);
        __half h10 = __float2half_rn(w10), h11 = __float2half_rn(w11);
        __half2 b0h = __halves2half2(h00, h01);
        __half2 b1h = __halves2half2(h10, h11);
        __half2 b0l = __halves2half2(__float2half_rn(w00 - __half2float(h00)),
                                     __float2half_rn(w01 - __half2float(h01)));
        __half2 b1l = __halves2half2(__float2half_rn(w10 - __half2float(h10)),
                                     __float2half_rn(w11 - __half2float(h11)));
        thi[i] = make_uint2(*(uint32_t*)&b0h, *(uint32_t*)&b1h);
        tlo[i] = make_uint2(*(uint32_t*)&b0l, *(uint32_t*)&b1l);
    }
    // x -> fp16 plane, float2 granules
    long tot = (long)n * 64;
    for (long j = i; j < tot; j += (long)gridDim.x * blockDim.x) {
        float2 v = *(const float2*)(x + j * 2);
        __half2 p = __float22half2_rn(v);
        *(uint32_t*)(xa + j * 2) = *(uint32_t*)&p;
    }
}

// ================= CSR build =================
__global__ void deg_acc_kernel(const int* __restrict__ dst, int* __restrict__ deg, int E) {
    int e = blockIdx.x * blockDim.x + threadIdx.x;
    if (e < E) atomicAdd(&deg[dst[e]], 1);
}
__global__ void dinv_kernel(const int* __restrict__ deg, float* __restrict__ dinv, int n) {
    int i = blockIdx.x * blockDim.x + threadIdx.x;
    if (i < n) dinv[i] = rsqrtf((float)(deg[i] + 1));
}
__global__ void scan1_kernel(const int* __restrict__ in, int* __restrict__ out,
                             int* __restrict__ bsum, int n) {
    __shared__ int sh[256];
    int t = threadIdx.x;
    int i0 = blockIdx.x * 1024 + t * 4;
    int v[4];
#pragma unroll
    for (int k = 0; k < 4; k++) v[k] = (i0 + k < n) ? in[i0 + k] : 0;
    int s = v[0] + v[1] + v[2] + v[3];
    sh[t] = s;
    __syncthreads();
#pragma unroll
    for (int off = 1; off < 256; off <<= 1) {
        int x = (t >= off) ? sh[t - off] : 0;
        __syncthreads();
        sh[t] += x;
        __syncthreads();
    }
    int run = sh[t] - s;
#pragma unroll
    for (int k = 0; k < 4; k++) {
        if (i0 + k < n) out[i0 + k] = run;
        run += v[k];
    }
    if (t == 255) bsum[blockIdx.x] = sh[255];
}
__global__ void scan2_kernel(int* __restrict__ bsum, int nch, int* __restrict__ rowptr,
                             int n, int E) {
    if (threadIdx.x == 0) {
        int run = 0;
        for (int i = 0; i < nch; i++) { int t = bsum[i]; bsum[i] = run; run += t; }
        rowptr[n] = E;
    }
}
__global__ void scan3_kernel(int* __restrict__ rowptr, const int* __restrict__ bsum, int n) {
    int i = blockIdx.x * blockDim.x + threadIdx.x;
    if (i < n) rowptr[i] += bsum[i >> 10];
}
__global__ void fill_kernel(const int* __restrict__ src, const int* __restrict__ dst,
                            const int* __restrict__ rowptr, int* __restrict__ cnt,
                            int* __restrict__ csr_src, int E) {
    int e = blockIdx.x * blockDim.x + threadIdx.x;
    if (e >= E) return;
    int s = src[e], d = dst[e];
    int pos = rowptr[d] + atomicAdd(&cnt[d], 1);
    csr_src[pos] = s;
}

// ================= HMMA GEMM: C[M,128] = A[M,128] @ W, fp16 in/out, 2-term W split =================
#define TILE_M 128
#define NTHR   256
#define LDA 136           // fp16 elems per smem row (pad 8: conflict-free ldmatrix)
#define LDAB (LDA * 2)    // 272 bytes per smem row
#define SM_TOT (TILE_M * LDAB)   // 34816 (A plane; reused as fp16 staging in epilogue)

__global__ __launch_bounds__(NTHR, 2)
void mma_gemm(const __half* __restrict__ A,
              const uint2* __restrict__ Thi,
              const uint2* __restrict__ Tlo,
              __half* __restrict__ C, int M) {
    extern __shared__ char smem[];
    const uint32_t sb = smem_u32(smem);
    const int tid  = threadIdx.x;
    const int wid  = tid >> 5;
    const int lane = tid & 31;
    const int row0 = blockIdx.x * TILE_M;

    // ---- async copy A plane into padded smem (16B chunks) ----
    {
        const char* ga = (const char*)(A + (size_t)row0 * DIM);
        for (int i = tid; i < TILE_M * 16; i += NTHR) {
            int row = i >> 4, c = (i & 15) * 16;
            if (row0 + row < M)
                cp_async16(sb + (uint32_t)(row * LDAB + c), ga + row * 256 + c);
        }
        cp_async_wait_all();
    }
    __syncthreads();

    const int wr   = (wid >> 1) * 32;
    const int half = wid & 1;
    const int wc   = half * 64;

    float acc[2][8][4];
#pragma unroll
    for (int rt = 0; rt < 2; rt++)
#pragma unroll
        for (int j = 0; j < 8; j++)
#pragma unroll
            for (int q = 0; q < 4; q++) acc[rt][j][q] = 0.f;

    const int m  = lane >> 3;
    const int rr = lane & 7;

#pragma unroll
    for (int ks = 0; ks < 8; ks++) {
        const int k0 = ks * 16;

        // A fragments: 2 row-tiles of 16
        uint32_t ah[2][4];
#pragma unroll
        for (int rt = 0; rt < 2; rt++) {
            int arow = wr + rt * 16 + ((m & 1) ? 8 : 0) + rr;
            int acol = k0 + ((m >> 1) ? 8 : 0);
            ldm_x4(ah[rt], sb + (uint32_t)(arow * LDA + acol) * 2);
        }

        // B fragments from global tables (L1/L2-hot), coalesced LDG.64 per j
        const uint2* ph = Thi + ((size_t)(half * 8 + ks) * 8) * 32 + lane;
        const uint2* pl = Tlo + ((size_t)(half * 8 + ks) * 8) * 32 + lane;
#pragma unroll
        for (int jh = 0; jh < 2; jh++) {
            uint32_t bh[4][2], bl[4][2];
#pragma unroll
            for (int j4 = 0; j4 < 4; j4++) {
                uint2 vh = __ldg(ph + (jh * 4 + j4) * 32);
                uint2 vl = __ldg(pl + (jh * 4 + j4) * 32);
                bh[j4][0] = vh.x; bh[j4][1] = vh.y;
                bl[j4][0] = vl.x; bl[j4][1] = vl.y;
            }
            // term-major: 8 independent accs per term
#pragma unroll
            for (int rt = 0; rt < 2; rt++)
#pragma unroll
                for (int j4 = 0; j4 < 4; j4++)
                    mma_f16(acc[rt][jh * 4 + j4], ah[rt], bh[j4]);
#pragma unroll
            for (int rt = 0; rt < 2; rt++)
#pragma unroll
                for (int j4 = 0; j4 < 4; j4++)
                    mma_f16(acc[rt][jh * 4 + j4], ah[rt], bl[j4]);
        }
    }

    // ---- epilogue: fragments -> fp16 staging smem (reuses A region) -> coalesced global ----
    __syncthreads();
    __half* stage = (__half*)smem;
    const int g  = lane >> 2;
    const int cq = (lane & 3) * 2;
#pragma unroll
    for (int rt = 0; rt < 2; rt++)
#pragma unroll
        for (int j = 0; j < 8; j++) {
            int row = wr + rt * 16 + g;
            int col = wc + j * 8 + cq;
            *(__half2*)(stage + row * LDA + col) =
                __float22half2_rn(make_float2(acc[rt][j][0], acc[rt][j][1]));
            *(__half2*)(stage + (row + 8) * LDA + col) =
                __float22half2_rn(make_float2(acc[rt][j][2], acc[rt][j][3]));
        }
    __syncthreads();

    for (int i = tid; i < TILE_M * 16; i += NTHR) {
        int r = i >> 4, cp = i & 15;   // 16 chunks of 8 halves per row
        if (row0 + r < M) {
            uint4 v = *(uint4*)(stage + r * LDA + cp * 8);
            *(uint4*)(C + (size_t)(row0 + r) * DIM + cp * 8) = v;
        }
    }
}

// ================= fused gather (fp16 h, fp32 accumulate) =================
__device__ __forceinline__ float4 h4_to_f4(uint2 u) {
    float2 f0 = __half22float2(*(__half2*)&u.x);
    float2 f1 = __half22float2(*(__half2*)&u.y);
    return make_float4(f0.x, f0.y, f1.x, f1.y);
}

template <bool RELU, bool F16OUT>
__global__ __launch_bounds__(256)
void gather_kernel(const __half* __restrict__ h, const float* __restrict__ bias,
                   const int* __restrict__ rowptr, const int* __restrict__ csr_src,
                   const float* __restrict__ dinv,
                   float* __restrict__ outf, __half* __restrict__ oa, int n) {
    int warp = (blockIdx.x * blockDim.x + threadIdx.x) >> 5;
    int lane = threadIdx.x & 31;
    if (warp >= n) return;
    const int d = warp;
    const int c4 = lane * 4;

    float di = __ldg(&dinv[d]);
    float s  = di * di;
    float4 self = h4_to_f4(*(const uint2*)(h + (size_t)d * DIM + c4));
    float4 bb   = *(const float4*)(bias + c4);
    float4 acc;
    acc.x = fmaf(self.x, s, bb.x);
    acc.y = fmaf(self.y, s, bb.y);
    acc.z = fmaf(self.z, s, bb.z);
    acc.w = fmaf(self.w, s, bb.w);

    int j   = __ldg(&rowptr[d]);
    int end = __ldg(&rowptr[d + 1]);

    for (; j + 3 < end; j += 4) {
        int   s0 = __ldg(&csr_src[j]);
        int   s1 = __ldg(&csr_src[j + 1]);
        int   s2 = __ldg(&csr_src[j + 2]);
        int   s3 = __ldg(&csr_src[j + 3]);
        float c0 = __ldg(&dinv[s0]) * di;
        float c1 = __ldg(&dinv[s1]) * di;
        float c2 = __ldg(&dinv[s2]) * di;
        float c3 = __ldg(&dinv[s3]) * di;
        uint2 u0 = *(const uint2*)(h + (size_t)s0 * DIM + c4);
        uint2 u1 = *(const uint2*)(h + (size_t)s1 * DIM + c4);
        uint2 u2 = *(const uint2*)(h + (size_t)s2 * DIM + c4);
        uint2 u3 = *(const uint2*)(h + (size_t)s3 * DIM + c4);
        float4 v0 = h4_to_f4(u0);
        float4 v1 = h4_to_f4(u1);
        float4 v2 = h4_to_f4(u2);
        float4 v3 = h4_to_f4(u3);
        acc.x = fmaf(v0.x, c0, acc.x);
        acc.y = fmaf(v0.y, c0, acc.y);
        acc.z = fmaf(v0.z, c0, acc.z);
        acc.w = fmaf(v0.w, c0, acc.w);
        acc.x = fmaf(v1.x, c1, acc.x);
        acc.y = fmaf(v1.y, c1, acc.y);
        acc.z = fmaf(v1.z, c1, acc.z);
        acc.w = fmaf(v1.w, c1, acc.w);
        acc.x = fmaf(v2.x, c2, acc.x);
        acc.y = fmaf(v2.y, c2, acc.y);
        acc.z = fmaf(v2.z, c2, acc.z);
        acc.w = fmaf(v2.w, c2, acc.w);
        acc.x = fmaf(v3.x, c3, acc.x);
        acc.y = fmaf(v3.y, c3, acc.y);
        acc.z = fmaf(v3.z, c3, acc.z);
        acc.w = fmaf(v3.w, c3, acc.w);
    }
    for (; j < end; j++) {
        int   s0 = __ldg(&csr_src[j]);
        float c0 = __ldg(&dinv[s0]) * di;
        float4 v0 = h4_to_f4(*(const uint2*)(h + (size_t)s0 * DIM + c4));
        acc.x = fmaf(v0.x, c0, acc.x);
        acc.y = fmaf(v0.y, c0, acc.y);
        acc.z = fmaf(v0.z, c0, acc.z);
        acc.w = fmaf(v0.w, c0, acc.w);
    }

    if (RELU) {
        acc.x = fmaxf(acc.x, 0.f);
        acc.y = fmaxf(acc.y, 0.f);
        acc.z = fmaxf(acc.z, 0.f);
        acc.w = fmaxf(acc.w, 0.f);
    }

    if (F16OUT) {
        __half2 p0 = __float22half2_rn(make_float2(acc.x, acc.y));
        __half2 p1 = __float22half2_rn(make_float2(acc.z, acc.w));
        *(uint2*)(oa + (size_t)d * DIM + c4) = make_uint2(*(uint32_t*)&p0, *(uint32_t*)&p1);
    } else {
        *(float4*)(outf + (size_t)d * DIM + c4) = acc;
    }
}

extern "C" void kernel_launch(void* const* d_in, const int* in_sizes, int n_in,
                              void* d_out, int out_size) {
    const float* x  = (const float*)d_in[0];
    const int*   ei = (const int*)d_in[1];
    const float* W1 = (const float*)d_in[2];
    const float* b1 = (const float*)d_in[3];
    const float* W2 = (const float*)d_in[4];
    const float* b2 = (const float*)d_in[5];
    const float* W3 = (const float*)d_in[6];
    const float* b3 = (const float*)d_in[7];
    float*       out = (float*)d_out;

    const int N = in_sizes[0] / DIM;
    const int E = in_sizes[1] / 2;
    const int* src = ei;
    const int* dst = ei + E;

    __half *h, *a;
    float* dinv;
    int *deg, *cnt, *rowptr, *bsum, *csr_src;
    uint2 *thi, *tlo;
    cudaGetSymbolAddress((void**)&h,       g_h);
    cudaGetSymbolAddress((void**)&a,       g_a);
    cudaGetSymbolAddress((void**)&dinv,    g_dinv);
    cudaGetSymbolAddress((void**)&deg,     g_deg);
    cudaGetSymbolAddress((void**)&cnt,     g_cnt);
    cudaGetSymbolAddress((void**)&rowptr,  g_rowptr);
    cudaGetSymbolAddress((void**)&bsum,    g_bsum);
    cudaGetSymbolAddress((void**)&csr_src, g_csr_src);
    cudaGetSymbolAddress((void**)&thi,     g_bfrag_hi);
    cudaGetSymbolAddress((void**)&tlo,     g_bfrag_lo);

    cudaFuncSetAttribute(mma_gemm, cudaFuncAttributeMaxDynamicSharedMemorySize, SM_TOT);

    const int TB = 256;
    const int n_blk  = (N + TB - 1) / TB;
    const int e_blk  = (E + TB - 1) / TB;
    const int gemm_g = (N + TILE_M - 1) / TILE_M;
    const int nch    = (N + 1023) / 1024;
    const int gat_blk = (int)(((long)N * 32 + TB - 1) / TB);

    // 1: prep (zero deg/cnt + W frag tables + x -> fp16 plane)
    prep_kernel<<<8192, TB>>>(W1, W2, W3, thi, tlo, x, a, deg, cnt, N);
    // 2-3: degrees
    deg_acc_kernel<<<e_blk, TB>>>(dst, deg, E);
    dinv_kernel<<<n_blk, TB>>>(deg, dinv, N);
    // 4 (profiled): layer-1 GEMM
    mma_gemm<<<gemm_g, NTHR, SM_TOT>>>(a, thi, tlo, h, N);
    // 5-8: CSR
    scan1_kernel<<<nch, 256>>>(deg, rowptr, bsum, N);
    scan2_kernel<<<1, 32>>>(bsum, nch, rowptr, N, E);
    scan3_kernel<<<n_blk, TB>>>(rowptr, bsum, N);
    fill_kernel<<<e_blk, TB>>>(src, dst, rowptr, cnt, csr_src, E);

    // layer 1 aggregation -> fp16 plane
    gather_kernel<true, true><<<gat_blk, TB>>>(h, b1, rowptr, csr_src, dinv,
                                               nullptr, a, N);
    // layer 2
    mma_gemm<<<gemm_g, NTHR, SM_TOT>>>(a, thi + TBL_PER_LAYER, tlo + TBL_PER_LAYER, h, N);
    gather_kernel<true, true><<<gat_blk, TB>>>(h, b2, rowptr, csr_src, dinv,
                                               nullptr, a, N);
    // layer 3 -> d_out (fp32)
    mma_gemm<<<gemm_g, NTHR, SM_TOT>>>(a, thi + 2 * TBL_PER_LAYER, tlo + 2 * TBL_PER_LAYER, h, N);
    gather_kernel<false, false><<<gat_blk, TB>>>(h, b3, rowptr, csr_src, dinv,
                                                 out, nullptr, N);
}

// round 13
// speedup vs baseline: 2.2502x; 1.0659x over previous
#include <cuda_runtime.h>
#include <cuda_bf16.h>
#include <cuda_fp16.h>
#include <cstdint>

#define NNODES 100000
#define EMAX   1600000
#define DIM    128

// Scratch (__device__ globals: allocation-free rule)
__device__ __half g_h[(size_t)NNODES * DIM];   // GEMM output (fp16, gather input)
__device__ __half g_a[(size_t)NNODES * DIM];   // activation plane (fp16, GEMM input)
__device__ float g_dinv[NNODES];
__device__ int   g_deg[NNODES];
__device__ int   g_cnt[NNODES];
__device__ int   g_rowptr[NNODES + 1];
__device__ int   g_bsum[256];
__device__ int   g_csr_src[EMAX];
// B-fragment table: [layer][half][ks][j][lane] -> uint2 (b0,b1 regs of mma B frag), fp16
#define TBL_PER_LAYER (2 * 8 * 8 * 32)
__device__ uint2 g_bfrag[3 * TBL_PER_LAYER];

// ================= helpers =================
__device__ __forceinline__ uint32_t smem_u32(const void* p) {
    uint32_t a;
    asm("{ .reg .u64 t; cvta.to.shared.u64 t, %1; cvt.u32.u64 %0, t; }" : "=r"(a) : "l"(p));
    return a;
}
__device__ __forceinline__ void ldm_x4(uint32_t* r, uint32_t addr) {
    asm volatile("ldmatrix.sync.aligned.m8n8.x4.shared.b16 {%0,%1,%2,%3}, [%4];"
                 : "=r"(r[0]), "=r"(r[1]), "=r"(r[2]), "=r"(r[3]) : "r"(addr));
}
__device__ __forceinline__ void mma_f16(float* c, const uint32_t* a, const uint32_t* b) {
    asm volatile(
        "mma.sync.aligned.m16n8k16.row.col.f32.f16.f16.f32 "
        "{%0,%1,%2,%3}, {%4,%5,%6,%7}, {%8,%9}, {%0,%1,%2,%3};"
        : "+f"(c[0]), "+f"(c[1]), "+f"(c[2]), "+f"(c[3])
        : "r"(a[0]), "r"(a[1]), "r"(a[2]), "r"(a[3]), "r"(b[0]), "r"(b[1]));
}
__device__ __forceinline__ void cp_async16(uint32_t saddr, const void* gptr) {
    asm volatile("cp.async.cg.shared.global [%0], [%1], 16;"
                 :: "r"(saddr), "l"(gptr) : "memory");
}
__device__ __forceinline__ void cp_async_wait_all() {
    asm volatile("cp.async.commit_group;" ::: "memory");
    asm volatile("cp.async.wait_group 0;" ::: "memory");
}

// ================= prep: zero deg/cnt + W frag table (fp16) + x -> fp16 plane =================
__global__ void prep_kernel(const float* __restrict__ W1, const float* __restrict__ W2,
                            const float* __restrict__ W3,
                            uint2* __restrict__ tbl,
                            const float* __restrict__ x, __half* __restrict__ xa,
                            int* __restrict__ deg, int* __restrict__ cnt, int n) {
    int i = blockIdx.x * blockDim.x + threadIdx.x;
    if (i < n) { deg[i] = 0; cnt[i] = 0; }
    if (i < 3 * TBL_PER_LAYER) {
        int lane = i & 31;
        int j    = (i >> 5) & 7;
        int ks   = (i >> 8) & 7;
        int half = (i >> 11) & 1;
        int l    = i >> 12;
        const float* W = (l == 0) ? W1 : (l == 1) ? W2 : W3;
        int nn = half * 64 + j * 8 + (lane >> 2);
        int k  = ks * 16 + (lane & 3) * 2;
        __half2 b0 = __halves2half2(__float2half_rn(W[(size_t)k * DIM + nn]),
                                    __float2half_rn(W[(size_t)(k + 1) * DIM + nn]));
        __half2 b1 = __halves2half2(__float2half_rn(W[(size_t)(k + 8) * DIM + nn]),
                                    __float2half_rn(W[(size_t)(k + 9) * DIM + nn]));
        tbl[i] = make_uint2(*(uint32_t*)&b0, *(uint32_t*)&b1);
    }
    // x -> fp16 plane, float2 granules
    long tot = (long)n * 64;
    for (long j = i; j < tot; j += (long)gridDim.x * blockDim.x) {
        float2 v = *(const float2*)(x + j * 2);
        __half2 p = __float22half2_rn(v);
        *(uint32_t*)(xa + j * 2) = *(uint32_t*)&p;
    }
}

// ================= CSR build =================
__global__ void deg_acc_kernel(const int* __restrict__ dst, int* __restrict__ deg, int E) {
    int e = blockIdx.x * blockDim.x + threadIdx.x;
    if (e < E) atomicAdd(&deg[dst[e]], 1);
}
__global__ void dinv_kernel(const int* __restrict__ deg, float* __restrict__ dinv, int n) {
    int i = blockIdx.x * blockDim.x + threadIdx.x;
    if (i < n) dinv[i] = rsqrtf((float)(deg[i] + 1));
}
__global__ void scan1_kernel(const int* __restrict__ in, int* __restrict__ out,
                             int* __restrict__ bsum, int n) {
    __shared__ int sh[256];
    int t = threadIdx.x;
    int i0 = blockIdx.x * 1024 + t * 4;
    int v[4];
#pragma unroll
    for (int k = 0; k < 4; k++) v[k] = (i0 + k < n) ? in[i0 + k] : 0;
    int s = v[0] + v[1] + v[2] + v[3];
    sh[t] = s;
    __syncthreads();
#pragma unroll
    for (int off = 1; off < 256; off <<= 1) {
        int x = (t >= off) ? sh[t - off] : 0;
        __syncthreads();
        sh[t] += x;
        __syncthreads();
    }
    int run = sh[t] - s;
#pragma unroll
    for (int k = 0; k < 4; k++) {
        if (i0 + k < n) out[i0 + k] = run;
        run += v[k];
    }
    if (t == 255) bsum[blockIdx.x] = sh[255];
}
__global__ void scan2_kernel(int* __restrict__ bsum, int nch, int* __restrict__ rowptr,
                             int n, int E) {
    if (threadIdx.x == 0) {
        int run = 0;
        for (int i = 0; i < nch; i++) { int t = bsum[i]; bsum[i] = run; run += t; }
        rowptr[n] = E;
    }
}
__global__ void scan3_kernel(int* __restrict__ rowptr, const int* __restrict__ bsum, int n) {
    int i = blockIdx.x * blockDim.x + threadIdx.x;
    if (i < n) rowptr[i] += bsum[i >> 10];
}
__global__ void fill_kernel(const int* __restrict__ src, const int* __restrict__ dst,
                            const int* __restrict__ rowptr, int* __restrict__ cnt,
                            int* __restrict__ csr_src, int E) {
    int e = blockIdx.x * blockDim.x + threadIdx.x;
    if (e >= E) return;
    int s = src[e], d = dst[e];
    int pos = rowptr[d] + atomicAdd(&cnt[d], 1);
    csr_src[pos] = s;
}

// ================= HMMA GEMM: C[M,128] = A[M,128] @ W, fp16 in/out, 1-term fp16 W =================
#define TILE_M 128
#define NTHR   256
#define LDA 136           // fp16 elems per smem row (pad 8: conflict-free ldmatrix)
#define LDAB (LDA * 2)    // 272 bytes per smem row
#define SM_TOT (TILE_M * LDAB)   // 34816 (A plane; reused as fp16 staging in epilogue)

__global__ __launch_bounds__(NTHR, 2)
void mma_gemm(const __half* __restrict__ A,
              const uint2* __restrict__ Tbl,
              __half* __restrict__ C, int M) {
    extern __shared__ char smem[];
    const uint32_t sb = smem_u32(smem);
    const int tid  = threadIdx.x;
    const int wid  = tid >> 5;
    const int lane = tid & 31;
    const int row0 = blockIdx.x * TILE_M;

    // ---- async copy A plane into padded smem (16B chunks) ----
    {
        const char* ga = (const char*)(A + (size_t)row0 * DIM);
        for (int i = tid; i < TILE_M * 16; i += NTHR) {
            int row = i >> 4, c = (i & 15) * 16;
            if (row0 + row < M)
                cp_async16(sb + (uint32_t)(row * LDAB + c), ga + row * 256 + c);
        }
        cp_async_wait_all();
    }
    __syncthreads();

    const int wr   = (wid >> 1) * 32;
    const int half = wid & 1;
    const int wc   = half * 64;

    float acc[2][8][4];
#pragma unroll
    for (int rt = 0; rt < 2; rt++)
#pragma unroll
        for (int j = 0; j < 8; j++)
#pragma unroll
            for (int q = 0; q < 4; q++) acc[rt][j][q] = 0.f;

    const int m  = lane >> 3;
    const int rr = lane & 7;

#pragma unroll
    for (int ks = 0; ks < 8; ks++) {
        const int k0 = ks * 16;

        // A fragments: 2 row-tiles of 16
        uint32_t ah[2][4];
#pragma unroll
        for (int rt = 0; rt < 2; rt++) {
            int arow = wr + rt * 16 + ((m & 1) ? 8 : 0) + rr;
            int acol = k0 + ((m >> 1) ? 8 : 0);
            ldm_x4(ah[rt], sb + (uint32_t)(arow * LDA + acol) * 2);
        }

        // B fragments from global table (L1/L2-hot), coalesced LDG.64 per j
        const uint2* pb = Tbl + ((size_t)(half * 8 + ks) * 8) * 32 + lane;
        uint32_t bf[8][2];
#pragma unroll
        for (int j = 0; j < 8; j++) {
            uint2 v = __ldg(pb + j * 32);
            bf[j][0] = v.x; bf[j][1] = v.y;
        }
#pragma unroll
        for (int rt = 0; rt < 2; rt++)
#pragma unroll
            for (int j = 0; j < 8; j++)
                mma_f16(acc[rt][j], ah[rt], bf[j]);
    }

    // ---- epilogue: fragments -> fp16 staging smem (reuses A region) -> coalesced global ----
    __syncthreads();
    __half* stage = (__half*)smem;
    const int g  = lane >> 2;
    const int cq = (lane & 3) * 2;
#pragma unroll
    for (int rt = 0; rt < 2; rt++)
#pragma unroll
        for (int j = 0; j < 8; j++) {
            int row = wr + rt * 16 + g;
            int col = wc + j * 8 + cq;
            *(__half2*)(stage + row * LDA + col) =
                __float22half2_rn(make_float2(acc[rt][j][0], acc[rt][j][1]));
            *(__half2*)(stage + (row + 8) * LDA + col) =
                __float22half2_rn(make_float2(acc[rt][j][2], acc[rt][j][3]));
        }
    __syncthreads();

    for (int i = tid; i < TILE_M * 16; i += NTHR) {
        int r = i >> 4, cp = i & 15;   // 16 chunks of 8 halves per row
        if (row0 + r < M) {
            uint4 v = *(uint4*)(stage + r * LDA + cp * 8);
            *(uint4*)(C + (size_t)(row0 + r) * DIM + cp * 8) = v;
        }
    }
}

// ================= fused gather (fp16 h, fp32 accumulate) =================
__device__ __forceinline__ float4 h4_to_f4(uint2 u) {
    float2 f0 = __half22float2(*(__half2*)&u.x);
    float2 f1 = __half22float2(*(__half2*)&u.y);
    return make_float4(f0.x, f0.y, f1.x, f1.y);
}

template <bool RELU, bool F16OUT>
__global__ __launch_bounds__(256)
void gather_kernel(const __half* __restrict__ h, const float* __restrict__ bias,
                   const int* __restrict__ rowptr, const int* __restrict__ csr_src,
                   const float* __restrict__ dinv,
                   float* __restrict__ outf, __half* __restrict__ oa, int n) {
    int warp = (blockIdx.x * blockDim.x + threadIdx.x) >> 5;
    int lane = threadIdx.x & 31;
    if (warp >= n) return;
    const int d = warp;
    const int c4 = lane * 4;

    float di = __ldg(&dinv[d]);
    float s  = di * di;
    float4 self = h4_to_f4(*(const uint2*)(h + (size_t)d * DIM + c4));
    float4 bb   = *(const float4*)(bias + c4);
    float4 acc;
    acc.x = fmaf(self.x, s, bb.x);
    acc.y = fmaf(self.y, s, bb.y);
    acc.z = fmaf(self.z, s, bb.z);
    acc.w = fmaf(self.w, s, bb.w);

    int j   = __ldg(&rowptr[d]);
    int end = __ldg(&rowptr[d + 1]);

    for (; j + 3 < end; j += 4) {
        int   s0 = __ldg(&csr_src[j]);
        int   s1 = __ldg(&csr_src[j + 1]);
        int   s2 = __ldg(&csr_src[j + 2]);
        int   s3 = __ldg(&csr_src[j + 3]);
        float c0 = __ldg(&dinv[s0]) * di;
        float c1 = __ldg(&dinv[s1]) * di;
        float c2 = __ldg(&dinv[s2]) * di;
        float c3 = __ldg(&dinv[s3]) * di;
        uint2 u0 = *(const uint2*)(h + (size_t)s0 * DIM + c4);
        uint2 u1 = *(const uint2*)(h + (size_t)s1 * DIM + c4);
        uint2 u2 = *(const uint2*)(h + (size_t)s2 * DIM + c4);
        uint2 u3 = *(const uint2*)(h + (size_t)s3 * DIM + c4);
        float4 v0 = h4_to_f4(u0);
        float4 v1 = h4_to_f4(u1);
        float4 v2 = h4_to_f4(u2);
        float4 v3 = h4_to_f4(u3);
        acc.x = fmaf(v0.x, c0, acc.x);
        acc.y = fmaf(v0.y, c0, acc.y);
        acc.z = fmaf(v0.z, c0, acc.z);
        acc.w = fmaf(v0.w, c0, acc.w);
        acc.x = fmaf(v1.x, c1, acc.x);
        acc.y = fmaf(v1.y, c1, acc.y);
        acc.z = fmaf(v1.z, c1, acc.z);
        acc.w = fmaf(v1.w, c1, acc.w);
        acc.x = fmaf(v2.x, c2, acc.x);
        acc.y = fmaf(v2.y, c2, acc.y);
        acc.z = fmaf(v2.z, c2, acc.z);
        acc.w = fmaf(v2.w, c2, acc.w);
        acc.x = fmaf(v3.x, c3, acc.x);
        acc.y = fmaf(v3.y, c3, acc.y);
        acc.z = fmaf(v3.z, c3, acc.z);
        acc.w = fmaf(v3.w, c3, acc.w);
    }
    for (; j < end; j++) {
        int   s0 = __ldg(&csr_src[j]);
        float c0 = __ldg(&dinv[s0]) * di;
        float4 v0 = h4_to_f4(*(const uint2*)(h + (size_t)s0 * DIM + c4));
        acc.x = fmaf(v0.x, c0, acc.x);
        acc.y = fmaf(v0.y, c0, acc.y);
        acc.z = fmaf(v0.z, c0, acc.z);
        acc.w = fmaf(v0.w, c0, acc.w);
    }

    if (RELU) {
        acc.x = fmaxf(acc.x, 0.f);
        acc.y = fmaxf(acc.y, 0.f);
        acc.z = fmaxf(acc.z, 0.f);
        acc.w = fmaxf(acc.w, 0.f);
    }

    if (F16OUT) {
        __half2 p0 = __float22half2_rn(make_float2(acc.x, acc.y));
        __half2 p1 = __float22half2_rn(make_float2(acc.z, acc.w));
        *(uint2*)(oa + (size_t)d * DIM + c4) = make_uint2(*(uint32_t*)&p0, *(uint32_t*)&p1);
    } else {
        *(float4*)(outf + (size_t)d * DIM + c4) = acc;
    }
}

extern "C" void kernel_launch(void* const* d_in, const int* in_sizes, int n_in,
                              void* d_out, int out_size) {
    const float* x  = (const float*)d_in[0];
    const int*   ei = (const int*)d_in[1];
    const float* W1 = (const float*)d_in[2];
    const float* b1 = (const float*)d_in[3];
    const float* W2 = (const float*)d_in[4];
    const float* b2 = (const float*)d_in[5];
    const float* W3 = (const float*)d_in[6];
    const float* b3 = (const float*)d_in[7];
    float*       out = (float*)d_out;

    const int N = in_sizes[0] / DIM;
    const int E = in_sizes[1] / 2;
    const int* src = ei;
    const int* dst = ei + E;

    __half *h, *a;
    float* dinv;
    int *deg, *cnt, *rowptr, *bsum, *csr_src;
    uint2* tbl;
    cudaGetSymbolAddress((void**)&h,       g_h);
    cudaGetSymbolAddress((void**)&a,       g_a);
    cudaGetSymbolAddress((void**)&dinv,    g_dinv);
    cudaGetSymbolAddress((void**)&deg,     g_deg);
    cudaGetSymbolAddress((void**)&cnt,     g_cnt);
    cudaGetSymbolAddress((void**)&rowptr,  g_rowptr);
    cudaGetSymbolAddress((void**)&bsum,    g_bsum);
    cudaGetSymbolAddress((void**)&csr_src, g_csr_src);
    cudaGetSymbolAddress((void**)&tbl,     g_bfrag);

    cudaFuncSetAttribute(mma_gemm, cudaFuncAttributeMaxDynamicSharedMemorySize, SM_TOT);

    const int TB = 256;
    const int n_blk  = (N + TB - 1) / TB;
    const int e_blk  = (E + TB - 1) / TB;
    const int gemm_g = (N + TILE_M - 1) / TILE_M;
    const int nch    = (N + 1023) / 1024;
    const int gat_blk = (int)(((long)N * 32 + TB - 1) / TB);

    // 1: prep (zero deg/cnt + W frag table + x -> fp16 plane)
    prep_kernel<<<8192, TB>>>(W1, W2, W3, tbl, x, a, deg, cnt, N);
    // 2-3: degrees
    deg_acc_kernel<<<e_blk, TB>>>(dst, deg, E);
    dinv_kernel<<<n_blk, TB>>>(deg, dinv, N);
    // 4 (profiled): layer-1 GEMM
    mma_gemm<<<gemm_g, NTHR, SM_TOT>>>(a, tbl, h, N);
    // 5-8: CSR
    scan1_kernel<<<nch, 256>>>(deg, rowptr, bsum, N);
    scan2_kernel<<<1, 32>>>(bsum, nch, rowptr, N, E);
    scan3_kernel<<<n_blk, TB>>>(rowptr, bsum, N);
    fill_kernel<<<e_blk, TB>>>(src, dst, rowptr, cnt, csr_src, E);

    // layer 1 aggregation -> fp16 plane
    gather_kernel<true, true><<<gat_blk, TB>>>(h, b1, rowptr, csr_src, dinv,
                                               nullptr, a, N);
    // layer 2
    mma_gemm<<<gemm_g, NTHR, SM_TOT>>>(a, tbl + TBL_PER_LAYER, h, N);
    gather_kernel<true, true><<<gat_blk, TB>>>(h, b2, rowptr, csr_src, dinv,
                                               nullptr, a, N);
    // layer 3 -> d_out (fp32)
    mma_gemm<<<gemm_g, NTHR, SM_TOT>>>(a, tbl + 2 * TBL_PER_LAYER, h, N);
    gather_kernel<false, false><<<gat_blk, TB>>>(h, b3, rowptr, csr_src, dinv,
                                                 out, nullptr, N);
}

// round 14
// speedup vs baseline: 2.3521x; 1.0453x over previous
#include <cuda_runtime.h>
#include <cuda_bf16.h>
#include <cuda_fp16.h>
#include <cstdint>

#define NNODES 100000
#define EMAX   1600000
#define DIM    128

// Scratch (__device__ globals: allocation-free rule)
__device__ __half g_h[(size_t)NNODES * DIM];   // GEMM output (fp16, gather input)
__device__ __half g_a[(size_t)NNODES * DIM];   // activation plane (fp16, GEMM input)
__device__ float g_dinv[NNODES];
__device__ int   g_deg[NNODES];
__device__ int   g_cnt[NNODES];
__device__ int   g_rowptr[NNODES + 1];
__device__ int   g_bsum[256];
__device__ int   g_csr_src[EMAX];
// B-fragment table: [layer][half][ks][j][lane] -> uint2 (b0,b1 regs of mma B frag), fp16
#define TBL_PER_LAYER (2 * 8 * 8 * 32)
__device__ uint2 g_bfrag[3 * TBL_PER_LAYER];

// ================= helpers =================
__device__ __forceinline__ uint32_t smem_u32(const void* p) {
    uint32_t a;
    asm("{ .reg .u64 t; cvta.to.shared.u64 t, %1; cvt.u32.u64 %0, t; }" : "=r"(a) : "l"(p));
    return a;
}
__device__ __forceinline__ void ldm_x4(uint32_t* r, uint32_t addr) {
    asm volatile("ldmatrix.sync.aligned.m8n8.x4.shared.b16 {%0,%1,%2,%3}, [%4];"
                 : "=r"(r[0]), "=r"(r[1]), "=r"(r[2]), "=r"(r[3]) : "r"(addr));
}
__device__ __forceinline__ void mma_f16(float* c, const uint32_t* a, const uint32_t* b) {
    asm volatile(
        "mma.sync.aligned.m16n8k16.row.col.f32.f16.f16.f32 "
        "{%0,%1,%2,%3}, {%4,%5,%6,%7}, {%8,%9}, {%0,%1,%2,%3};"
        : "+f"(c[0]), "+f"(c[1]), "+f"(c[2]), "+f"(c[3])
        : "r"(a[0]), "r"(a[1]), "r"(a[2]), "r"(a[3]), "r"(b[0]), "r"(b[1]));
}
__device__ __forceinline__ void cp_async16(uint32_t saddr, const void* gptr) {
    asm volatile("cp.async.cg.shared.global [%0], [%1], 16;"
                 :: "r"(saddr), "l"(gptr) : "memory");
}
__device__ __forceinline__ void cp_async_wait_all() {
    asm volatile("cp.async.commit_group;" ::: "memory");
    asm volatile("cp.async.wait_group 0;" ::: "memory");
}

// ================= prep: zero deg/cnt + W frag table (fp16) + x -> fp16 plane =================
__global__ void prep_kernel(const float* __restrict__ W1, const float* __restrict__ W2,
                            const float* __restrict__ W3,
                            uint2* __restrict__ tbl,
                            const float* __restrict__ x, __half* __restrict__ xa,
                            int* __restrict__ deg, int* __restrict__ cnt, int n) {
    int i = blockIdx.x * blockDim.x + threadIdx.x;
    if (i < n) { deg[i] = 0; cnt[i] = 0; }
    if (i < 3 * TBL_PER_LAYER) {
        int lane = i & 31;
        int j    = (i >> 5) & 7;
        int ks   = (i >> 8) & 7;
        int half = (i >> 11) & 1;
        int l    = i >> 12;
        const float* W = (l == 0) ? W1 : (l == 1) ? W2 : W3;
        int nn = half * 64 + j * 8 + (lane >> 2);
        int k  = ks * 16 + (lane & 3) * 2;
        __half2 b0 = __halves2half2(__float2half_rn(W[(size_t)k * DIM + nn]),
                                    __float2half_rn(W[(size_t)(k + 1) * DIM + nn]));
        __half2 b1 = __halves2half2(__float2half_rn(W[(size_t)(k + 8) * DIM + nn]),
                                    __float2half_rn(W[(size_t)(k + 9) * DIM + nn]));
        tbl[i] = make_uint2(*(uint32_t*)&b0, *(uint32_t*)&b1);
    }
    // x -> fp16 plane, float2 granules
    long tot = (long)n * 64;
    for (long j = i; j < tot; j += (long)gridDim.x * blockDim.x) {
        float2 v = *(const float2*)(x + j * 2);
        __half2 p = __float22half2_rn(v);
        *(uint32_t*)(xa + j * 2) = *(uint32_t*)&p;
    }
}

// ================= CSR build =================
__global__ void deg_acc_kernel(const int* __restrict__ dst, int* __restrict__ deg, int E) {
    int e = blockIdx.x * blockDim.x + threadIdx.x;
    if (e < E) atomicAdd(&deg[dst[e]], 1);
}
// scan1 also emits dinv = rsqrt(deg+1)
__global__ void scan1_kernel(const int* __restrict__ in, int* __restrict__ out,
                             int* __restrict__ bsum, float* __restrict__ dinv, int n) {
    __shared__ int sh[256];
    int t = threadIdx.x;
    int i0 = blockIdx.x * 1024 + t * 4;
    int v[4];
#pragma unroll
    for (int k = 0; k < 4; k++) {
        v[k] = (i0 + k < n) ? in[i0 + k] : 0;
        if (i0 + k < n) dinv[i0 + k] = rsqrtf((float)(v[k] + 1));
    }
    int s = v[0] + v[1] + v[2] + v[3];
    sh[t] = s;
    __syncthreads();
#pragma unroll
    for (int off = 1; off < 256; off <<= 1) {
        int x = (t >= off) ? sh[t - off] : 0;
        __syncthreads();
        sh[t] += x;
        __syncthreads();
    }
    int run = sh[t] - s;
#pragma unroll
    for (int k = 0; k < 4; k++) {
        if (i0 + k < n) out[i0 + k] = run;
        run += v[k];
    }
    if (t == 255) bsum[blockIdx.x] = sh[255];
}
__global__ void scan2_kernel(int* __restrict__ bsum, int nch, int* __restrict__ rowptr,
                             int n, int E) {
    if (threadIdx.x == 0) {
        int run = 0;
        for (int i = 0; i < nch; i++) { int t = bsum[i]; bsum[i] = run; run += t; }
        rowptr[n] = E;
    }
}
__global__ void scan3_kernel(int* __restrict__ rowptr, const int* __restrict__ bsum, int n) {
    int i = blockIdx.x * blockDim.x + threadIdx.x;
    if (i < n) rowptr[i] += bsum[i >> 10];
}
__global__ void fill_kernel(const int* __restrict__ src, const int* __restrict__ dst,
                            const int* __restrict__ rowptr, int* __restrict__ cnt,
                            int* __restrict__ csr_src, int E) {
    int e = blockIdx.x * blockDim.x + threadIdx.x;
    if (e >= E) return;
    int s = src[e], d = dst[e];
    int pos = rowptr[d] + atomicAdd(&cnt[d], 1);
    csr_src[pos] = s;
}

// ================= HMMA GEMM: C[M,128] = A[M,128] @ W, fp16 in/out =================
// TILE_M=64, 128 threads (4 warps, warp tile 32x64), 4 CTAs/SM for phase overlap.
#define TILE_M 64
#define NTHR   128
#define LDA 136           // fp16 elems per smem row (pad 8: conflict-free ldmatrix)
#define LDAB (LDA * 2)    // 272 bytes per smem row
#define SM_TOT (TILE_M * LDAB)   // 17408 (A plane; reused as fp16 staging in epilogue)

__global__ __launch_bounds__(NTHR, 4)
void mma_gemm(const __half* __restrict__ A,
              const uint2* __restrict__ Tbl,
              __half* __restrict__ C, int M) {
    extern __shared__ char smem[];
    const uint32_t sb = smem_u32(smem);
    const int tid  = threadIdx.x;
    const int wid  = tid >> 5;
    const int lane = tid & 31;
    const int row0 = blockIdx.x * TILE_M;

    // ---- async copy A plane into padded smem (16B chunks) ----
    {
        const char* ga = (const char*)(A + (size_t)row0 * DIM);
        for (int i = tid; i < TILE_M * 16; i += NTHR) {
            int row = i >> 4, c = (i & 15) * 16;
            if (row0 + row < M)
                cp_async16(sb + (uint32_t)(row * LDAB + c), ga + row * 256 + c);
        }
        cp_async_wait_all();
    }
    __syncthreads();

    const int wr   = (wid >> 1) * 32;   // warp row base: 0/32
    const int half = wid & 1;           // warp col half: 0 -> cols 0-63, 1 -> 64-127
    const int wc   = half * 64;

    float acc[2][8][4];
#pragma unroll
    for (int rt = 0; rt < 2; rt++)
#pragma unroll
        for (int j = 0; j < 8; j++)
#pragma unroll
            for (int q = 0; q < 4; q++) acc[rt][j][q] = 0.f;

    const int m  = lane >> 3;
    const int rr = lane & 7;

#pragma unroll
    for (int ks = 0; ks < 8; ks++) {
        const int k0 = ks * 16;

        // A fragments: 2 row-tiles of 16
        uint32_t ah[2][4];
#pragma unroll
        for (int rt = 0; rt < 2; rt++) {
            int arow = wr + rt * 16 + ((m & 1) ? 8 : 0) + rr;
            int acol = k0 + ((m >> 1) ? 8 : 0);
            ldm_x4(ah[rt], sb + (uint32_t)(arow * LDA + acol) * 2);
        }

        // B fragments from global table (L1/L2-hot), coalesced LDG.64 per j
        const uint2* pb = Tbl + ((size_t)(half * 8 + ks) * 8) * 32 + lane;
        uint32_t bf[8][2];
#pragma unroll
        for (int j = 0; j < 8; j++) {
            uint2 v = __ldg(pb + j * 32);
            bf[j][0] = v.x; bf[j][1] = v.y;
        }
#pragma unroll
        for (int rt = 0; rt < 2; rt++)
#pragma unroll
            for (int j = 0; j < 8; j++)
                mma_f16(acc[rt][j], ah[rt], bf[j]);
    }

    // ---- epilogue: fragments -> fp16 staging smem (reuses A region) -> coalesced global ----
    __syncthreads();
    __half* stage = (__half*)smem;
    const int g  = lane >> 2;
    const int cq = (lane & 3) * 2;
#pragma unroll
    for (int rt = 0; rt < 2; rt++)
#pragma unroll
        for (int j = 0; j < 8; j++) {
            int row = wr + rt * 16 + g;
            int col = wc + j * 8 + cq;
            *(__half2*)(stage + row * LDA + col) =
                __float22half2_rn(make_float2(acc[rt][j][0], acc[rt][j][1]));
            *(__half2*)(stage + (row + 8) * LDA + col) =
                __float22half2_rn(make_float2(acc[rt][j][2], acc[rt][j][3]));
        }
    __syncthreads();

    for (int i = tid; i < TILE_M * 16; i += NTHR) {
        int r = i >> 4, cp = i & 15;   // 16 chunks of 8 halves per row
        if (row0 + r < M) {
            uint4 v = *(uint4*)(stage + r * LDA + cp * 8);
            *(uint4*)(C + (size_t)(row0 + r) * DIM + cp * 8) = v;
        }
    }
}

// ================= fused gather (fp16 h, fp32 accumulate) =================
__device__ __forceinline__ float4 h4_to_f4(uint2 u) {
    float2 f0 = __half22float2(*(__half2*)&u.x);
    float2 f1 = __half22float2(*(__half2*)&u.y);
    return make_float4(f0.x, f0.y, f1.x, f1.y);
}

template <bool RELU, bool F16OUT>
__global__ __launch_bounds__(256)
void gather_kernel(const __half* __restrict__ h, const float* __restrict__ bias,
                   const int* __restrict__ rowptr, const int* __restrict__ csr_src,
                   const float* __restrict__ dinv,
                   float* __restrict__ outf, __half* __restrict__ oa, int n) {
    int warp = (blockIdx.x * blockDim.x + threadIdx.x) >> 5;
    int lane = threadIdx.x & 31;
    if (warp >= n) return;
    const int d = warp;
    const int c4 = lane * 4;

    float di = __ldg(&dinv[d]);
    float s  = di * di;
    float4 self = h4_to_f4(*(const uint2*)(h + (size_t)d * DIM + c4));
    float4 bb   = *(const float4*)(bias + c4);
    float4 acc;
    acc.x = fmaf(self.x, s, bb.x);
    acc.y = fmaf(self.y, s, bb.y);
    acc.z = fmaf(self.z, s, bb.z);
    acc.w = fmaf(self.w, s, bb.w);

    int j   = __ldg(&rowptr[d]);
    int end = __ldg(&rowptr[d + 1]);

    for (; j + 3 < end; j += 4) {
        int   s0 = __ldg(&csr_src[j]);
        int   s1 = __ldg(&csr_src[j + 1]);
        int   s2 = __ldg(&csr_src[j + 2]);
        int   s3 = __ldg(&csr_src[j + 3]);
        float c0 = __ldg(&dinv[s0]) * di;
        float c1 = __ldg(&dinv[s1]) * di;
        float c2 = __ldg(&dinv[s2]) * di;
        float c3 = __ldg(&dinv[s3]) * di;
        uint2 u0 = *(const uint2*)(h + (size_t)s0 * DIM + c4);
        uint2 u1 = *(const uint2*)(h + (size_t)s1 * DIM + c4);
        uint2 u2 = *(const uint2*)(h + (size_t)s2 * DIM + c4);
        uint2 u3 = *(const uint2*)(h + (size_t)s3 * DIM + c4);
        float4 v0 = h4_to_f4(u0);
        float4 v1 = h4_to_f4(u1);
        float4 v2 = h4_to_f4(u2);
        float4 v3 = h4_to_f4(u3);
        acc.x = fmaf(v0.x, c0, acc.x);
        acc.y = fmaf(v0.y, c0, acc.y);
        acc.z = fmaf(v0.z, c0, acc.z);
        acc.w = fmaf(v0.w, c0, acc.w);
        acc.x = fmaf(v1.x, c1, acc.x);
        acc.y = fmaf(v1.y, c1, acc.y);
        acc.z = fmaf(v1.z, c1, acc.z);
        acc.w = fmaf(v1.w, c1, acc.w);
        acc.x = fmaf(v2.x, c2, acc.x);
        acc.y = fmaf(v2.y, c2, acc.y);
        acc.z = fmaf(v2.z, c2, acc.z);
        acc.w = fmaf(v2.w, c2, acc.w);
        acc.x = fmaf(v3.x, c3, acc.x);
        acc.y = fmaf(v3.y, c3, acc.y);
        acc.z = fmaf(v3.z, c3, acc.z);
        acc.w = fmaf(v3.w, c3, acc.w);
    }
    for (; j < end; j++) {
        int   s0 = __ldg(&csr_src[j]);
        float c0 = __ldg(&dinv[s0]) * di;
        float4 v0 = h4_to_f4(*(const uint2*)(h + (size_t)s0 * DIM + c4));
        acc.x = fmaf(v0.x, c0, acc.x);
        acc.y = fmaf(v0.y, c0, acc.y);
        acc.z = fmaf(v0.z, c0, acc.z);
        acc.w = fmaf(v0.w, c0, acc.w);
    }

    if (RELU) {
        acc.x = fmaxf(acc.x, 0.f);
        acc.y = fmaxf(acc.y, 0.f);
        acc.z = fmaxf(acc.z, 0.f);
        acc.w = fmaxf(acc.w, 0.f);
    }

    if (F16OUT) {
        __half2 p0 = __float22half2_rn(make_float2(acc.x, acc.y));
        __half2 p1 = __float22half2_rn(make_float2(acc.z, acc.w));
        *(uint2*)(oa + (size_t)d * DIM + c4) = make_uint2(*(uint32_t*)&p0, *(uint32_t*)&p1);
    } else {
        *(float4*)(outf + (size_t)d * DIM + c4) = acc;
    }
}

extern "C" void kernel_launch(void* const* d_in, const int* in_sizes, int n_in,
                              void* d_out, int out_size) {
    const float* x  = (const float*)d_in[0];
    const int*   ei = (const int*)d_in[1];
    const float* W1 = (const float*)d_in[2];
    const float* b1 = (const float*)d_in[3];
    const float* W2 = (const float*)d_in[4];
    const float* b2 = (const float*)d_in[5];
    const float* W3 = (const float*)d_in[6];
    const float* b3 = (const float*)d_in[7];
    float*       out = (float*)d_out;

    const int N = in_sizes[0] / DIM;
    const int E = in_sizes[1] / 2;
    const int* src = ei;
    const int* dst = ei + E;

    __half *h, *a;
    float* dinv;
    int *deg, *cnt, *rowptr, *bsum, *csr_src;
    uint2* tbl;
    cudaGetSymbolAddress((void**)&h,       g_h);
    cudaGetSymbolAddress((void**)&a,       g_a);
    cudaGetSymbolAddress((void**)&dinv,    g_dinv);
    cudaGetSymbolAddress((void**)&deg,     g_deg);
    cudaGetSymbolAddress((void**)&cnt,     g_cnt);
    cudaGetSymbolAddress((void**)&rowptr,  g_rowptr);
    cudaGetSymbolAddress((void**)&bsum,    g_bsum);
    cudaGetSymbolAddress((void**)&csr_src, g_csr_src);
    cudaGetSymbolAddress((void**)&tbl,     g_bfrag);

    cudaFuncSetAttribute(mma_gemm, cudaFuncAttributeMaxDynamicSharedMemorySize, SM_TOT);

    const int TB = 256;
    const int n_blk  = (N + TB - 1) / TB;
    const int e_blk  = (E + TB - 1) / TB;
    const int gemm_g = (N + TILE_M - 1) / TILE_M;
    const int nch    = (N + 1023) / 1024;
    const int gat_blk = (int)(((long)N * 32 + TB - 1) / TB);

    // 1: prep (zero deg/cnt + W frag table + x -> fp16 plane)
    prep_kernel<<<8192, TB>>>(W1, W2, W3, tbl, x, a, deg, cnt, N);
    // 2: degrees
    deg_acc_kernel<<<e_blk, TB>>>(dst, deg, E);
    // 3: scan chunk pass (also emits dinv)
    scan1_kernel<<<nch, 256>>>(deg, rowptr, bsum, dinv, N);
    // 4 (profiled): layer-1 GEMM
    mma_gemm<<<gemm_g, NTHR, SM_TOT>>>(a, tbl, h, N);
    // 5-7: rest of CSR
    scan2_kernel<<<1, 32>>>(bsum, nch, rowptr, N, E);
    scan3_kernel<<<n_blk, TB>>>(rowptr, bsum, N);
    fill_kernel<<<e_blk, TB>>>(src, dst, rowptr, cnt, csr_src, E);

    // layer 1 aggregation -> fp16 plane
    gather_kernel<true, true><<<gat_blk, TB>>>(h, b1, rowptr, csr_src, dinv,
                                               nullptr, a, N);
    // layer 2
    mma_gemm<<<gemm_g, NTHR, SM_TOT>>>(a, tbl + TBL_PER_LAYER, h, N);
    gather_kernel<true, true><<<gat_blk, TB>>>(h, b2, rowptr, csr_src, dinv,
                                               nullptr, a, N);
    // layer 3 -> d_out (fp32)
    mma_gemm<<<gemm_g, NTHR, SM_TOT>>>(a, tbl + 2 * TBL_PER_LAYER, h, N);
    gather_kernel<false, false><<<gat_blk, TB>>>(h, b3, rowptr, csr_src, dinv,
                                                 out, nullptr, N);
}

// round 15
// speedup vs baseline: 2.4128x; 1.0258x over previous
#include <cuda_runtime.h>
#include <cuda_bf16.h>
#include <cuda_fp16.h>
#include <cstdint>

#define NNODES 100000
#define EMAX   1600000
#define DIM    128

// Scratch (__device__ globals: allocation-free rule)
__device__ __half g_h[(size_t)NNODES * DIM];   // GEMM output (fp16, gather input)
__device__ __half g_a[(size_t)NNODES * DIM];   // activation plane (fp16, GEMM input)
__device__ float g_dinv[NNODES];
__device__ int   g_deg[NNODES];
__device__ int   g_cnt[NNODES];
__device__ int   g_rowptr[NNODES + 1];
__device__ int   g_bsum[256];
__device__ int   g_csr_src[EMAX];
// B-fragment table: [layer][half][ks][j][lane] -> uint2 (b0,b1 regs of mma B frag), fp16
#define TBL_PER_LAYER (2 * 8 * 8 * 32)
__device__ uint2 g_bfrag[3 * TBL_PER_LAYER];

// ================= helpers =================
__device__ __forceinline__ uint32_t smem_u32(const void* p) {
    uint32_t a;
    asm("{ .reg .u64 t; cvta.to.shared.u64 t, %1; cvt.u32.u64 %0, t; }" : "=r"(a) : "l"(p));
    return a;
}
__device__ __forceinline__ void ldm_x4(uint32_t* r, uint32_t addr) {
    asm volatile("ldmatrix.sync.aligned.m8n8.x4.shared.b16 {%0,%1,%2,%3}, [%4];"
                 : "=r"(r[0]), "=r"(r[1]), "=r"(r[2]), "=r"(r[3]) : "r"(addr));
}
__device__ __forceinline__ void mma_f16(float* c, const uint32_t* a, const uint32_t* b) {
    asm volatile(
        "mma.sync.aligned.m16n8k16.row.col.f32.f16.f16.f32 "
        "{%0,%1,%2,%3}, {%4,%5,%6,%7}, {%8,%9}, {%0,%1,%2,%3};"
        : "+f"(c[0]), "+f"(c[1]), "+f"(c[2]), "+f"(c[3])
        : "r"(a[0]), "r"(a[1]), "r"(a[2]), "r"(a[3]), "r"(b[0]), "r"(b[1]));
}
__device__ __forceinline__ void cp_async16(uint32_t saddr, const void* gptr) {
    asm volatile("cp.async.cg.shared.global [%0], [%1], 16;"
                 :: "r"(saddr), "l"(gptr) : "memory");
}
__device__ __forceinline__ void cp_async_wait_all() {
    asm volatile("cp.async.commit_group;" ::: "memory");
    asm volatile("cp.async.wait_group 0;" ::: "memory");
}

// ================= prep: W frag table (fp16) + x -> fp16 plane =================
__global__ void prep_kernel(const float* __restrict__ W1, const float* __restrict__ W2,
                            const float* __restrict__ W3,
                            uint2* __restrict__ tbl,
                            const float* __restrict__ x, __half* __restrict__ xa, int n) {
    int i = blockIdx.x * blockDim.x + threadIdx.x;
    if (i < 3 * TBL_PER_LAYER) {
        int lane = i & 31;
        int j    = (i >> 5) & 7;
        int ks   = (i >> 8) & 7;
        int half = (i >> 11) & 1;
        int l    = i >> 12;
        const float* W = (l == 0) ? W1 : (l == 1) ? W2 : W3;
        int nn = half * 64 + j * 8 + (lane >> 2);
        int k  = ks * 16 + (lane & 3) * 2;
        __half2 b0 = __halves2half2(__float2half_rn(W[(size_t)k * DIM + nn]),
                                    __float2half_rn(W[(size_t)(k + 1) * DIM + nn]));
        __half2 b1 = __halves2half2(__float2half_rn(W[(size_t)(k + 8) * DIM + nn]),
                                    __float2half_rn(W[(size_t)(k + 9) * DIM + nn]));
        tbl[i] = make_uint2(*(uint32_t*)&b0, *(uint32_t*)&b1);
    }
    // x -> fp16 plane, float2 granules
    long tot = (long)n * 64;
    for (long j = i; j < tot; j += (long)gridDim.x * blockDim.x) {
        float2 v = *(const float2*)(x + j * 2);
        __half2 p = __float22half2_rn(v);
        *(uint32_t*)(xa + j * 2) = *(uint32_t*)&p;
    }
}

// ================= CSR build =================
__global__ void zero2_kernel(int* __restrict__ a, int* __restrict__ b, int n) {
    int i = blockIdx.x * blockDim.x + threadIdx.x;
    if (i < n) { a[i] = 0; b[i] = 0; }
}
__global__ void deg_acc_kernel(const int* __restrict__ dst, int* __restrict__ deg, int E) {
    int e = blockIdx.x * blockDim.x + threadIdx.x;
    if (e < E) atomicAdd(&deg[dst[e]], 1);
}
// scan1 also emits dinv = rsqrt(deg+1)
__global__ void scan1_kernel(const int* __restrict__ in, int* __restrict__ out,
                             int* __restrict__ bsum, float* __restrict__ dinv, int n) {
    __shared__ int sh[256];
    int t = threadIdx.x;
    int i0 = blockIdx.x * 1024 + t * 4;
    int v[4];
#pragma unroll
    for (int k = 0; k < 4; k++) {
        v[k] = (i0 + k < n) ? in[i0 + k] : 0;
        if (i0 + k < n) dinv[i0 + k] = rsqrtf((float)(v[k] + 1));
    }
    int s = v[0] + v[1] + v[2] + v[3];
    sh[t] = s;
    __syncthreads();
#pragma unroll
    for (int off = 1; off < 256; off <<= 1) {
        int x = (t >= off) ? sh[t - off] : 0;
        __syncthreads();
        sh[t] += x;
        __syncthreads();
    }
    int run = sh[t] - s;
#pragma unroll
    for (int k = 0; k < 4; k++) {
        if (i0 + k < n) out[i0 + k] = run;
        run += v[k];
    }
    if (t == 255) bsum[blockIdx.x] = sh[255];
}
__global__ void scan2_kernel(int* __restrict__ bsum, int nch, int* __restrict__ rowptr,
                             int n, int E) {
    if (threadIdx.x == 0) {
        int run = 0;
        for (int i = 0; i < nch; i++) { int t = bsum[i]; bsum[i] = run; run += t; }
        rowptr[n] = E;
    }
}
__global__ void scan3_kernel(int* __restrict__ rowptr, const int* __restrict__ bsum, int n) {
    int i = blockIdx.x * blockDim.x + threadIdx.x;
    if (i < n) rowptr[i] += bsum[i >> 10];
}
__global__ void fill_kernel(const int* __restrict__ src, const int* __restrict__ dst,
                            const int* __restrict__ rowptr, int* __restrict__ cnt,
                            int* __restrict__ csr_src, int E) {
    int e = blockIdx.x * blockDim.x + threadIdx.x;
    if (e >= E) return;
    int s = src[e], d = dst[e];
    int pos = rowptr[d] + atomicAdd(&cnt[d], 1);
    csr_src[pos] = s;
}

// ================= HMMA GEMM: C[M,128] = A[M,128] @ W, fp16 in/out =================
// TILE_M=64, 128 threads (4 warps, warp tile 32x64), 4 CTAs/SM for phase overlap.
#define TILE_M 64
#define NTHR   128
#define LDA 136           // fp16 elems per smem row (pad 8: conflict-free ldmatrix)
#define LDAB (LDA * 2)    // 272 bytes per smem row
#define SM_TOT (TILE_M * LDAB)   // 17408 (A plane; reused as fp16 staging in epilogue)

__global__ __launch_bounds__(NTHR, 4)
void mma_gemm(const __half* __restrict__ A,
              const uint2* __restrict__ Tbl,
              __half* __restrict__ C, int M) {
    extern __shared__ char smem[];
    const uint32_t sb = smem_u32(smem);
    const int tid  = threadIdx.x;
    const int wid  = tid >> 5;
    const int lane = tid & 31;
    const int row0 = blockIdx.x * TILE_M;

    // ---- async copy A plane into padded smem (16B chunks) ----
    {
        const char* ga = (const char*)(A + (size_t)row0 * DIM);
        for (int i = tid; i < TILE_M * 16; i += NTHR) {
            int row = i >> 4, c = (i & 15) * 16;
            if (row0 + row < M)
                cp_async16(sb + (uint32_t)(row * LDAB + c), ga + row * 256 + c);
        }
        cp_async_wait_all();
    }
    __syncthreads();

    const int wr   = (wid >> 1) * 32;   // warp row base: 0/32
    const int half = wid & 1;           // warp col half: 0 -> cols 0-63, 1 -> 64-127
    const int wc   = half * 64;

    float acc[2][8][4];
#pragma unroll
    for (int rt = 0; rt < 2; rt++)
#pragma unroll
        for (int j = 0; j < 8; j++)
#pragma unroll
            for (int q = 0; q < 4; q++) acc[rt][j][q] = 0.f;

    const int m  = lane >> 3;
    const int rr = lane & 7;

#pragma unroll
    for (int ks = 0; ks < 8; ks++) {
        const int k0 = ks * 16;

        // A fragments: 2 row-tiles of 16
        uint32_t ah[2][4];
#pragma unroll
        for (int rt = 0; rt < 2; rt++) {
            int arow = wr + rt * 16 + ((m & 1) ? 8 : 0) + rr;
            int acol = k0 + ((m >> 1) ? 8 : 0);
            ldm_x4(ah[rt], sb + (uint32_t)(arow * LDA + acol) * 2);
        }

        // B fragments from global table (L1/L2-hot), coalesced LDG.64 per j
        const uint2* pb = Tbl + ((size_t)(half * 8 + ks) * 8) * 32 + lane;
        uint32_t bf[8][2];
#pragma unroll
        for (int j = 0; j < 8; j++) {
            uint2 v = __ldg(pb + j * 32);
            bf[j][0] = v.x; bf[j][1] = v.y;
        }
#pragma unroll
        for (int rt = 0; rt < 2; rt++)
#pragma unroll
            for (int j = 0; j < 8; j++)
                mma_f16(acc[rt][j], ah[rt], bf[j]);
    }

    // ---- epilogue: fragments -> fp16 staging smem (reuses A region) -> coalesced global ----
    __syncthreads();
    __half* stage = (__half*)smem;
    const int g  = lane >> 2;
    const int cq = (lane & 3) * 2;
#pragma unroll
    for (int rt = 0; rt < 2; rt++)
#pragma unroll
        for (int j = 0; j < 8; j++) {
            int row = wr + rt * 16 + g;
            int col = wc + j * 8 + cq;
            *(__half2*)(stage + row * LDA + col) =
                __float22half2_rn(make_float2(acc[rt][j][0], acc[rt][j][1]));
            *(__half2*)(stage + (row + 8) * LDA + col) =
                __float22half2_rn(make_float2(acc[rt][j][2], acc[rt][j][3]));
        }
    __syncthreads();

    for (int i = tid; i < TILE_M * 16; i += NTHR) {
        int r = i >> 4, cp = i & 15;   // 16 chunks of 8 halves per row
        if (row0 + r < M) {
            uint4 v = *(uint4*)(stage + r * LDA + cp * 8);
            *(uint4*)(C + (size_t)(row0 + r) * DIM + cp * 8) = v;
        }
    }
}

// ================= fused gather (fp16 h, fp32 accumulate) =================
__device__ __forceinline__ float4 h4_to_f4(uint2 u) {
    float2 f0 = __half22float2(*(__half2*)&u.x);
    float2 f1 = __half22float2(*(__half2*)&u.y);
    return make_float4(f0.x, f0.y, f1.x, f1.y);
}

template <bool RELU, bool F16OUT>
__global__ __launch_bounds__(256)
void gather_kernel(const __half* __restrict__ h, const float* __restrict__ bias,
                   const int* __restrict__ rowptr, const int* __restrict__ csr_src,
                   const float* __restrict__ dinv,
                   float* __restrict__ outf, __half* __restrict__ oa, int n) {
    int warp = (blockIdx.x * blockDim.x + threadIdx.x) >> 5;
    int lane = threadIdx.x & 31;
    if (warp >= n) return;
    const int d = warp;
    const int c4 = lane * 4;

    float di = __ldg(&dinv[d]);
    float s  = di * di;
    float4 self = h4_to_f4(*(const uint2*)(h + (size_t)d * DIM + c4));
    float4 bb   = *(const float4*)(bias + c4);
    float4 acc;
    acc.x = fmaf(self.x, s, bb.x);
    acc.y = fmaf(self.y, s, bb.y);
    acc.z = fmaf(self.z, s, bb.z);
    acc.w = fmaf(self.w, s, bb.w);

    int j   = __ldg(&rowptr[d]);
    int end = __ldg(&rowptr[d + 1]);

    for (; j + 3 < end; j += 4) {
        int   s0 = __ldg(&csr_src[j]);
        int   s1 = __ldg(&csr_src[j + 1]);
        int   s2 = __ldg(&csr_src[j + 2]);
        int   s3 = __ldg(&csr_src[j + 3]);
        float c0 = __ldg(&dinv[s0]) * di;
        float c1 = __ldg(&dinv[s1]) * di;
        float c2 = __ldg(&dinv[s2]) * di;
        float c3 = __ldg(&dinv[s3]) * di;
        uint2 u0 = *(const uint2*)(h + (size_t)s0 * DIM + c4);
        uint2 u1 = *(const uint2*)(h + (size_t)s1 * DIM + c4);
        uint2 u2 = *(const uint2*)(h + (size_t)s2 * DIM + c4);
        uint2 u3 = *(const uint2*)(h + (size_t)s3 * DIM + c4);
        float4 v0 = h4_to_f4(u0);
        float4 v1 = h4_to_f4(u1);
        float4 v2 = h4_to_f4(u2);
        float4 v3 = h4_to_f4(u3);
        acc.x = fmaf(v0.x, c0, acc.x);
        acc.y = fmaf(v0.y, c0, acc.y);
        acc.z = fmaf(v0.z, c0, acc.z);
        acc.w = fmaf(v0.w, c0, acc.w);
        acc.x = fmaf(v1.x, c1, acc.x);
        acc.y = fmaf(v1.y, c1, acc.y);
        acc.z = fmaf(v1.z, c1, acc.z);
        acc.w = fmaf(v1.w, c1, acc.w);
        acc.x = fmaf(v2.x, c2, acc.x);
        acc.y = fmaf(v2.y, c2, acc.y);
        acc.z = fmaf(v2.z, c2, acc.z);
        acc.w = fmaf(v2.w, c2, acc.w);
        acc.x = fmaf(v3.x, c3, acc.x);
        acc.y = fmaf(v3.y, c3, acc.y);
        acc.z = fmaf(v3.z, c3, acc.z);
        acc.w = fmaf(v3.w, c3, acc.w);
    }
    for (; j < end; j++) {
        int   s0 = __ldg(&csr_src[j]);
        float c0 = __ldg(&dinv[s0]) * di;
        float4 v0 = h4_to_f4(*(const uint2*)(h + (size_t)s0 * DIM + c4));
        acc.x = fmaf(v0.x, c0, acc.x);
        acc.y = fmaf(v0.y, c0, acc.y);
        acc.z = fmaf(v0.z, c0, acc.z);
        acc.w = fmaf(v0.w, c0, acc.w);
    }

    if (RELU) {
        acc.x = fmaxf(acc.x, 0.f);
        acc.y = fmaxf(acc.y, 0.f);
        acc.z = fmaxf(acc.z, 0.f);
        acc.w = fmaxf(acc.w, 0.f);
    }

    if (F16OUT) {
        __half2 p0 = __float22half2_rn(make_float2(acc.x, acc.y));
        __half2 p1 = __float22half2_rn(make_float2(acc.z, acc.w));
        *(uint2*)(oa + (size_t)d * DIM + c4) = make_uint2(*(uint32_t*)&p0, *(uint32_t*)&p1);
    } else {
        *(float4*)(outf + (size_t)d * DIM + c4) = acc;
    }
}

extern "C" void kernel_launch(void* const* d_in, const int* in_sizes, int n_in,
                              void* d_out, int out_size) {
    const float* x  = (const float*)d_in[0];
    const int*   ei = (const int*)d_in[1];
    const float* W1 = (const float*)d_in[2];
    const float* b1 = (const float*)d_in[3];
    const float* W2 = (const float*)d_in[4];
    const float* b2 = (const float*)d_in[5];
    const float* W3 = (const float*)d_in[6];
    const float* b3 = (const float*)d_in[7];
    float*       out = (float*)d_out;

    const int N = in_sizes[0] / DIM;
    const int E = in_sizes[1] / 2;
    const int* src = ei;
    const int* dst = ei + E;

    __half *h, *a;
    float* dinv;
    int *deg, *cnt, *rowptr, *bsum, *csr_src;
    uint2* tbl;
    cudaGetSymbolAddress((void**)&h,       g_h);
    cudaGetSymbolAddress((void**)&a,       g_a);
    cudaGetSymbolAddress((void**)&dinv,    g_dinv);
    cudaGetSymbolAddress((void**)&deg,     g_deg);
    cudaGetSymbolAddress((void**)&cnt,     g_cnt);
    cudaGetSymbolAddress((void**)&rowptr,  g_rowptr);
    cudaGetSymbolAddress((void**)&bsum,    g_bsum);
    cudaGetSymbolAddress((void**)&csr_src, g_csr_src);
    cudaGetSymbolAddress((void**)&tbl,     g_bfrag);

    // One-time: side stream + events (no device memory involved)
    static cudaStream_t sB = nullptr;
    static cudaEvent_t evFork = nullptr, evJoin = nullptr;
    if (!sB) {
        cudaStreamCreateWithFlags(&sB, cudaStreamNonBlocking);
        cudaEventCreateWithFlags(&evFork, cudaEventDisableTiming);
        cudaEventCreateWithFlags(&evJoin, cudaEventDisableTiming);
        cudaFuncSetAttribute(mma_gemm, cudaFuncAttributeMaxDynamicSharedMemorySize, SM_TOT);
    }

    const int TB = 256;
    const int n_blk  = (N + TB - 1) / TB;
    const int e_blk  = (E + TB - 1) / TB;
    const int gemm_g = (N + TILE_M - 1) / TILE_M;
    const int nch    = (N + 1023) / 1024;
    const int gat_blk = (int)(((long)N * 32 + TB - 1) / TB);

    // ---- fork: CSR build on side stream, prep+GEMM1 on main stream ----
    cudaEventRecord(evFork, 0);
    cudaStreamWaitEvent(sB, evFork, 0);

    // side stream: CSR chain
    zero2_kernel<<<n_blk, TB, 0, sB>>>(deg, cnt, N);
    deg_acc_kernel<<<e_blk, TB, 0, sB>>>(dst, deg, E);
    scan1_kernel<<<nch, 256, 0, sB>>>(deg, rowptr, bsum, dinv, N);
    scan2_kernel<<<1, 32, 0, sB>>>(bsum, nch, rowptr, N, E);
    scan3_kernel<<<n_blk, TB, 0, sB>>>(rowptr, bsum, N);
    fill_kernel<<<e_blk, TB, 0, sB>>>(src, dst, rowptr, cnt, csr_src, E);
    cudaEventRecord(evJoin, sB);

    // main stream: prep + layer-1 GEMM
    prep_kernel<<<8192, TB>>>(W1, W2, W3, tbl, x, a, N);
    mma_gemm<<<gemm_g, NTHR, SM_TOT>>>(a, tbl, h, N);

    // join before aggregation
    cudaStreamWaitEvent(0, evJoin, 0);

    // layer 1 aggregation -> fp16 plane
    gather_kernel<true, true><<<gat_blk, TB>>>(h, b1, rowptr, csr_src, dinv,
                                               nullptr, a, N);
    // layer 2
    mma_gemm<<<gemm_g, NTHR, SM_TOT>>>(a, tbl + TBL_PER_LAYER, h, N);
    gather_kernel<true, true><<<gat_blk, TB>>>(h, b2, rowptr, csr_src, dinv,
                                               nullptr, a, N);
    // layer 3 -> d_out (fp32)
    mma_gemm<<<gemm_g, NTHR, SM_TOT>>>(a, tbl + 2 * TBL_PER_LAYER, h, N);
    gather_kernel<false, false><<<gat_blk, TB>>>(h, b3, rowptr, csr_src, dinv,
                                                 out, nullptr, N);
}